// round 6
// baseline (speedup 1.0000x reference)
#include <cuda_runtime.h>
#include <cuda_bf16.h>
#include <math.h>
#include <stdint.h>

#define B_   2
#define T_   2048
#define C_   2048
#define NH   16
#define NKV  4
#define HD   128
#define SCALE 0.08838834764831845f           // 1/sqrt(128)
#define QSCL  0.1275495818259719f            // SCALE * log2(e)

// ---------------------------------------------------------------------------
// Scratch (device globals; no allocation allowed)
// ---------------------------------------------------------------------------
__device__ float g_q[(size_t)B_ * NH  * T_ * HD];   // [B, NH, T, D] fp32
__device__ float g_k[(size_t)B_ * NKV * T_ * HD];
__device__ float g_v[(size_t)B_ * NKV * T_ * HD];

__device__ __nv_bfloat16 g_xhi[(size_t)B_ * T_ * C_];
__device__ __nv_bfloat16 g_xlo[(size_t)B_ * T_ * C_];
__device__ __nv_bfloat16 g_yhi[(size_t)B_ * T_ * C_];
__device__ __nv_bfloat16 g_ylo[(size_t)B_ * T_ * C_];
__device__ __nv_bfloat16 g_qhi[(size_t)B_ * NH  * T_ * HD];
__device__ __nv_bfloat16 g_qlo[(size_t)B_ * NH  * T_ * HD];
__device__ __nv_bfloat16 g_khi[(size_t)B_ * NKV * T_ * HD];
__device__ __nv_bfloat16 g_klo[(size_t)B_ * NKV * T_ * HD];
__device__ __nv_bfloat16 g_vhi[(size_t)B_ * NKV * T_ * HD];
__device__ __nv_bfloat16 g_vlo[(size_t)B_ * NKV * T_ * HD];
__device__ __nv_bfloat16 g_wqhi[(size_t)C_ * C_];
__device__ __nv_bfloat16 g_wqlo[(size_t)C_ * C_];
__device__ __nv_bfloat16 g_wkhi[(size_t)NKV * HD * C_];
__device__ __nv_bfloat16 g_wklo[(size_t)NKV * HD * C_];
__device__ __nv_bfloat16 g_wvhi[(size_t)NKV * HD * C_];
__device__ __nv_bfloat16 g_wvlo[(size_t)NKV * HD * C_];
__device__ __nv_bfloat16 g_wohi[(size_t)C_ * C_];
__device__ __nv_bfloat16 g_wolo[(size_t)C_ * C_];

// ---------------------------------------------------------------------------
// PTX helpers — arch-agnostic (sm_80+)
// ---------------------------------------------------------------------------
__device__ __forceinline__ uint32_t smem_u32(const void* p) {
    uint32_t a;
    asm("{ .reg .u64 t; cvta.to.shared.u64 t, %1; cvt.u32.u64 %0, t; }"
        : "=r"(a) : "l"(p));
    return a;
}
__device__ __forceinline__ void cp_async16(uint32_t saddr, const void* gaddr) {
    asm volatile("cp.async.cg.shared.global [%0], [%1], 16;"
                 :: "r"(saddr), "l"(gaddr));
}
__device__ __forceinline__ void cp_commit() { asm volatile("cp.async.commit_group;"); }
template <int N> __device__ __forceinline__ void cp_wait() {
    asm volatile("cp.async.wait_group %0;" :: "n"(N));
}
__device__ __forceinline__ void ldsm4(uint32_t* r, uint32_t addr) {
    asm volatile("ldmatrix.sync.aligned.m8n8.x4.shared.b16 {%0,%1,%2,%3}, [%4];"
                 : "=r"(r[0]), "=r"(r[1]), "=r"(r[2]), "=r"(r[3]) : "r"(addr));
}
__device__ __forceinline__ void ldsm4t(uint32_t* r, uint32_t addr) {
    asm volatile("ldmatrix.sync.aligned.m8n8.x4.trans.shared.b16 {%0,%1,%2,%3}, [%4];"
                 : "=r"(r[0]), "=r"(r[1]), "=r"(r[2]), "=r"(r[3]) : "r"(addr));
}
__device__ __forceinline__ void mma_bf16(float* c, const uint32_t* a,
                                         uint32_t b0, uint32_t b1) {
    asm volatile(
        "mma.sync.aligned.m16n8k16.row.col.f32.bf16.bf16.f32 "
        "{%0,%1,%2,%3}, {%4,%5,%6,%7}, {%8,%9}, {%0,%1,%2,%3};"
        : "+f"(c[0]), "+f"(c[1]), "+f"(c[2]), "+f"(c[3])
        : "r"(a[0]), "r"(a[1]), "r"(a[2]), "r"(a[3]), "r"(b0), "r"(b1));
}
__device__ __forceinline__ float ex2f(float x) {
    float y; asm("ex2.approx.f32 %0, %1;" : "=f"(y) : "f"(x)); return y;
}
__device__ __forceinline__ void pack_hilo(float x, float y, uint32_t& hi, uint32_t& lo) {
    __nv_bfloat16 hx = __float2bfloat16(x), hy = __float2bfloat16(y);
    __nv_bfloat16 lx = __float2bfloat16(x - __bfloat162float(hx));
    __nv_bfloat16 ly = __float2bfloat16(y - __bfloat162float(hy));
    __nv_bfloat162 h2(hx, hy), l2(lx, ly);
    hi = *reinterpret_cast<uint32_t*>(&h2);
    lo = *reinterpret_cast<uint32_t*>(&l2);
}

// ---------------------------------------------------------------------------
// fp32 -> bf16 hi/lo split
// ---------------------------------------------------------------------------
__global__ void cvt_hilo(const float4* __restrict__ in,
                         __nv_bfloat162* __restrict__ hi2,
                         __nv_bfloat162* __restrict__ lo2, int n4)
{
    int i = blockIdx.x * blockDim.x + threadIdx.x;
    if (i >= n4) return;
    float4 v = in[i];
    uint32_t h0, l0, h1, l1;
    pack_hilo(v.x, v.y, h0, l0);
    pack_hilo(v.z, v.w, h1, l1);
    hi2[2 * i + 0] = *reinterpret_cast<__nv_bfloat162*>(&h0);
    hi2[2 * i + 1] = *reinterpret_cast<__nv_bfloat162*>(&h1);
    lo2[2 * i + 0] = *reinterpret_cast<__nv_bfloat162*>(&l0);
    lo2[2 * i + 1] = *reinterpret_cast<__nv_bfloat162*>(&l1);
}

// ---------------------------------------------------------------------------
// RoPE on fp32 [B,Hx,T,D] input -> bf16 hi/lo outputs (optionally scaled).
// ---------------------------------------------------------------------------
__global__ void rope_hilo(const float* __restrict__ buf,
                          const float* __restrict__ fcos,
                          const float* __restrict__ fsin,
                          __nv_bfloat162* __restrict__ hi2,
                          __nv_bfloat162* __restrict__ lo2, float scl)
{
    int idx = blockIdx.x * blockDim.x + threadIdx.x;
    int d2 = idx & 63;
    int t  = (idx >> 6) & (T_ - 1);
    float c = fcos[t * 64 + d2];
    float s = fsin[t * 64 + d2];
    const float* p = buf + (size_t)idx * 2;
    float x0 = p[0], x1 = p[1];
    float r0 = (x0 * c - x1 * s) * scl;
    float r1 = (x0 * s + x1 * c) * scl;
    uint32_t h, l;
    pack_hilo(r0, r1, h, l);
    hi2[idx] = *reinterpret_cast<__nv_bfloat162*>(&h);
    lo2[idx] = *reinterpret_cast<__nv_bfloat162*>(&l);
}

// ---------------------------------------------------------------------------
// mma.sync bf16-split GEMM (NT): C[M,N] = A[M,K] * W[N,K]^T, fp32 out.
// CTA tile 256x128, BK=32, 3-stage cp.async pipeline, 256 threads.
// Warp grid 4(m) x 2(n); warp tile 64x64.
// Smem/stage: Ahi/Alo 256x80B + Whi/Wlo 128x80B = 61440B; 3 stages = 184320B.
// mode 0: C row-major [M,N].  mode 1: scatter to [B, Hn, T_, HD].
// ---------------------------------------------------------------------------
#define G_AOFF  20480                // 256*80
#define G_WOFF  10240                // 128*80
#define G_WBASE 40960                // 2*G_AOFF
#define G_STG   61440                // G_WBASE + 2*G_WOFF
#define GSM_TOTAL (3 * G_STG)        // 184320

__global__ __launch_bounds__(256, 1) void gemm_mma(
    const __nv_bfloat16* __restrict__ Ahi, const __nv_bfloat16* __restrict__ Alo,
    const __nv_bfloat16* __restrict__ Whi, const __nv_bfloat16* __restrict__ Wlo,
    float* __restrict__ Cout, int K, int N, int mode, int Hn)
{
    extern __shared__ char smem[];
    const int tid = threadIdx.x;
    const int lid = tid & 31, wid = tid >> 5;
    const int wm = wid & 3, wn = wid >> 2;     // 4(m) x 2(n)
    const int bm = blockIdx.y, bn = blockIdx.x;

    const __nv_bfloat16* Asrc[2];
    const __nv_bfloat16* Wsrc[2];
    Asrc[0] = Ahi + (size_t)bm * 256 * K;
    Asrc[1] = Alo + (size_t)bm * 256 * K;
    Wsrc[0] = Whi + (size_t)bn * 128 * K;
    Wsrc[1] = Wlo + (size_t)bn * 128 * K;

    float acc[4][8][4];
    #pragma unroll
    for (int mi = 0; mi < 4; mi++)
        #pragma unroll
        for (int ni = 0; ni < 8; ni++)
            #pragma unroll
            for (int e = 0; e < 4; e++) acc[mi][ni][e] = 0.f;

    const int nst = K >> 5;

    auto load_stage = [&](int s) {
        const uint32_t base = smem_u32(smem) + (s % 3) * G_STG;
        const int k0 = s << 5;
        // A: 2 mats x 1024 chunks; W: 2 mats x 512 chunks. 3072 total, 12/thread.
        #pragma unroll
        for (int j = 0; j < 8; j++) {          // A chunks
            int idx = j * 256 + tid;
            int mat = idx >> 10;
            int rem = idx & 1023;
            int row = rem >> 2, c = rem & 3;
            cp_async16(base + mat * G_AOFF + row * 80 + c * 16,
                       Asrc[mat] + (size_t)row * K + k0 + c * 8);
        }
        #pragma unroll
        for (int j = 0; j < 4; j++) {          // W chunks
            int idx = j * 256 + tid;
            int mat = idx >> 9;
            int rem = idx & 511;
            int row = rem >> 2, c = rem & 3;
            cp_async16(base + G_WBASE + mat * G_WOFF + row * 80 + c * 16,
                       Wsrc[mat] + (size_t)row * K + k0 + c * 8);
        }
        cp_commit();
    };

    load_stage(0);
    if (nst > 1) load_stage(1);

    for (int s = 0; s < nst; s++) {
        cp_wait<1>();
        __syncthreads();
        if (s + 2 < nst) load_stage(s + 2);

        const uint32_t sb = smem_u32(smem) + (s % 3) * G_STG;
        #pragma unroll
        for (int kk = 0; kk < 2; kk++) {
            uint32_t ah[4][4], al[4][4], bh[4][4], bl[4][4];
            const int arow  = wm * 64 + (lid & 15);
            const int akcol = kk * 16 + ((lid & 16) ? 8 : 0);
            #pragma unroll
            for (int mi = 0; mi < 4; mi++) {
                uint32_t addr = sb + (arow + mi * 16) * 80 + akcol * 2;
                ldsm4(ah[mi], addr);
                ldsm4(al[mi], addr + G_AOFF);
            }
            const int brow  = wn * 64 + (lid & 7) + ((lid & 16) ? 8 : 0);
            const int bkcol = kk * 16 + ((lid & 8) ? 8 : 0);
            #pragma unroll
            for (int p = 0; p < 4; p++) {
                uint32_t addr = sb + G_WBASE + (brow + p * 16) * 80 + bkcol * 2;
                ldsm4(bh[p], addr);
                ldsm4(bl[p], addr + G_WOFF);
            }
            #pragma unroll
            for (int mi = 0; mi < 4; mi++)
                #pragma unroll
                for (int ni = 0; ni < 8; ni++) {
                    const int p = ni >> 1, q = (ni & 1) * 2;
                    mma_bf16(acc[mi][ni], ah[mi], bh[p][q], bh[p][q + 1]);
                    mma_bf16(acc[mi][ni], ah[mi], bl[p][q], bl[p][q + 1]);
                    mma_bf16(acc[mi][ni], al[mi], bh[p][q], bh[p][q + 1]);
                }
        }
        __syncthreads();
    }

    const int r0c = lid >> 2, cc = (lid & 3) * 2;
    #pragma unroll
    for (int mi = 0; mi < 4; mi++) {
        #pragma unroll
        for (int ni = 0; ni < 8; ni++) {
            int row = bm * 256 + wm * 64 + mi * 16 + r0c;
            int col = bn * 128 + wn * 64 + ni * 8 + cc;
            #pragma unroll
            for (int half = 0; half < 2; half++) {
                int rr = row + half * 8;
                float2 v = make_float2(acc[mi][ni][half * 2], acc[mi][ni][half * 2 + 1]);
                if (mode == 0) {
                    *(float2*)(Cout + (size_t)rr * N + col) = v;
                } else {
                    int b = rr >> 11, t = rr & (T_ - 1);
                    int h = col >> 7, d = col & (HD - 1);
                    *(float2*)(Cout + ((((size_t)b * Hn + h) * T_ + t) * HD + d)) = v;
                }
            }
        }
    }
}

// ---------------------------------------------------------------------------
// Tensor-core causal flash attention (unchanged from R5, passing).
// ---------------------------------------------------------------------------
#define AROWB  272
#define AQMAT  34816
#define AKVMAT 17408
#define AKVST  (4 * AKVMAT)
#define ASM_TOTAL (2 * AQMAT + 2 * AKVST)

__global__ __launch_bounds__(256, 1) void attn_mma(
    const __nv_bfloat16* __restrict__ Qhi, const __nv_bfloat16* __restrict__ Qlo,
    const __nv_bfloat16* __restrict__ Khi, const __nv_bfloat16* __restrict__ Klo,
    const __nv_bfloat16* __restrict__ Vhi, const __nv_bfloat16* __restrict__ Vlo,
    __nv_bfloat16* __restrict__ Yhi, __nv_bfloat16* __restrict__ Ylo)
{
    extern __shared__ char smem[];
    const int tid = threadIdx.x;
    const int lid = tid & 31, wid = tid >> 5;
    const int qt = (T_ / 128 - 1) - blockIdx.x;
    const int bh = blockIdx.y;
    const int b  = bh >> 4, h = bh & 15;
    const int kvh = h >> 2;

    const size_t qg = ((size_t)(b * NH + h) * T_ + qt * 128) * HD;
    const size_t kg = (size_t)(b * NKV + kvh) * T_ * HD;

    const uint32_t sQhi = smem_u32(smem);
    const uint32_t sQlo = sQhi + AQMAT;
    const uint32_t sKV0 = sQlo + AQMAT;

    {
        #pragma unroll
        for (int i = 0; i < 16; i++) {
            int idx = i * 256 + tid;
            int mat = idx >> 11;
            int rem = idx & 2047;
            int row = rem >> 4, c = rem & 15;
            const __nv_bfloat16* src = (mat ? Qlo : Qhi) + qg + (size_t)row * HD + c * 8;
            cp_async16((mat ? sQlo : sQhi) + row * AROWB + c * 16, src);
        }
    }
    const __nv_bfloat16* kvsrc[4] = {Khi, Klo, Vhi, Vlo};
    auto load_kv = [&](int kt, int st) {
        uint32_t sb = sKV0 + st * AKVST;
        const size_t base = kg + (size_t)kt * 64 * HD;
        #pragma unroll
        for (int i = 0; i < 16; i++) {
            int idx = i * 256 + tid;
            int mat = idx >> 10;
            int rem = idx & 1023;
            int row = rem >> 4, c = rem & 15;
            cp_async16(sb + mat * AKVMAT + row * AROWB + c * 16,
                       kvsrc[mat] + base + (size_t)row * HD + c * 8);
        }
        cp_commit();
    };
    load_kv(0, 0);

    float oacc[16][4];
    #pragma unroll
    for (int jn = 0; jn < 16; jn++)
        #pragma unroll
        for (int e = 0; e < 4; e++) oacc[jn][e] = 0.f;
    float mrow[2] = {-1e30f, -1e30f};
    float lrow[2] = {0.f, 0.f};

    const int nkt = 2 * qt + 2;

    for (int kt = 0; kt < nkt; kt++) {
        if (kt + 1 < nkt) { load_kv(kt + 1, (kt + 1) & 1); cp_wait<1>(); }
        else              { cp_wait<0>(); }
        __syncthreads();

        const uint32_t sb  = sKV0 + (kt & 1) * AKVST;
        const uint32_t sKh = sb, sKl = sb + AKVMAT;
        const uint32_t sVh = sb + 2 * AKVMAT, sVl = sb + 3 * AKVMAT;

        float sacc[8][4];
        #pragma unroll
        for (int j = 0; j < 8; j++)
            #pragma unroll
            for (int e = 0; e < 4; e++) sacc[j][e] = 0.f;

        #pragma unroll
        for (int kk = 0; kk < 8; kk++) {
            uint32_t ah[4], al[4];
            const int arow  = wid * 16 + (lid & 15);
            const int akcol = kk * 16 + ((lid & 16) ? 8 : 0);
            uint32_t qaddr = sQhi + arow * AROWB + akcol * 2;
            ldsm4(ah, qaddr);
            ldsm4(al, qaddr + AQMAT);
            #pragma unroll
            for (int np = 0; np < 4; np++) {
                uint32_t bh4[4], bl4[4];
                const int brow  = np * 16 + (lid & 7) + ((lid & 16) ? 8 : 0);
                const int bkcol = kk * 16 + ((lid & 8) ? 8 : 0);
                uint32_t kaddr = brow * AROWB + bkcol * 2;
                ldsm4(bh4, sKh + kaddr);
                ldsm4(bl4, sKl + kaddr);
                #pragma unroll
                for (int jj = 0; jj < 2; jj++) {
                    const int j = 2 * np + jj, q = jj * 2;
                    mma_bf16(sacc[j], ah, bh4[q], bh4[q + 1]);
                    mma_bf16(sacc[j], ah, bl4[q], bl4[q + 1]);
                    mma_bf16(sacc[j], al, bh4[q], bh4[q + 1]);
                }
            }
        }

        const int kv0 = kt * 64;
        if (kv0 + 63 > qt * 128) {
            const int rbase = qt * 128 + wid * 16 + (lid >> 2);
            #pragma unroll
            for (int j = 0; j < 8; j++)
                #pragma unroll
                for (int e = 0; e < 4; e++) {
                    int col = kv0 + j * 8 + 2 * (lid & 3) + (e & 1);
                    int row = rbase + (e >> 1) * 8;
                    if (col > row) sacc[j][e] = -1e30f;
                }
        }

        #pragma unroll
        for (int h2 = 0; h2 < 2; h2++) {
            float tm = -1e30f;
            #pragma unroll
            for (int j = 0; j < 8; j++)
                tm = fmaxf(tm, fmaxf(sacc[j][h2 * 2], sacc[j][h2 * 2 + 1]));
            tm = fmaxf(tm, __shfl_xor_sync(0xffffffffu, tm, 1));
            tm = fmaxf(tm, __shfl_xor_sync(0xffffffffu, tm, 2));
            float mnew = fmaxf(mrow[h2], tm);
            float corr = ex2f(mrow[h2] - mnew);
            float sum = 0.f;
            #pragma unroll
            for (int j = 0; j < 8; j++) {
                float p0 = ex2f(sacc[j][h2 * 2] - mnew);
                float p1 = ex2f(sacc[j][h2 * 2 + 1] - mnew);
                sacc[j][h2 * 2] = p0; sacc[j][h2 * 2 + 1] = p1;
                sum += p0 + p1;
            }
            sum += __shfl_xor_sync(0xffffffffu, sum, 1);
            sum += __shfl_xor_sync(0xffffffffu, sum, 2);
            lrow[h2] = lrow[h2] * corr + sum;
            mrow[h2] = mnew;
            #pragma unroll
            for (int jn = 0; jn < 16; jn++) {
                oacc[jn][h2 * 2]     *= corr;
                oacc[jn][h2 * 2 + 1] *= corr;
            }
        }

        #pragma unroll
        for (int ks = 0; ks < 4; ks++) {
            uint32_t phi[4], plo[4];
            const int j0 = 2 * ks, j1 = 2 * ks + 1;
            pack_hilo(sacc[j0][0], sacc[j0][1], phi[0], plo[0]);
            pack_hilo(sacc[j0][2], sacc[j0][3], phi[1], plo[1]);
            pack_hilo(sacc[j1][0], sacc[j1][1], phi[2], plo[2]);
            pack_hilo(sacc[j1][2], sacc[j1][3], phi[3], plo[3]);
            #pragma unroll
            for (int np = 0; np < 8; np++) {
                uint32_t vh4[4], vl4[4];
                const int vrow = ks * 16 + (lid & 7) + 8 * ((lid >> 3) & 1);
                const int vcol = np * 16 + 8 * (lid >> 4);
                uint32_t vaddr = vrow * AROWB + vcol * 2;
                ldsm4t(vh4, sVh + vaddr);
                ldsm4t(vl4, sVl + vaddr);
                #pragma unroll
                for (int jj = 0; jj < 2; jj++) {
                    const int jn = 2 * np + jj, q = jj * 2;
                    mma_bf16(oacc[jn], phi, vh4[q], vh4[q + 1]);
                    mma_bf16(oacc[jn], phi, vl4[q], vl4[q + 1]);
                    mma_bf16(oacc[jn], plo, vh4[q], vh4[q + 1]);
                }
            }
        }
        __syncthreads();
    }

    #pragma unroll
    for (int h2 = 0; h2 < 2; h2++) {
        float inv = 1.f / lrow[h2];
        int row_t = qt * 128 + wid * 16 + (lid >> 2) + 8 * h2;
        size_t base = ((size_t)b * T_ + row_t) * C_ + h * HD;
        #pragma unroll
        for (int jn = 0; jn < 16; jn++) {
            int col = jn * 8 + 2 * (lid & 3);
            float v0 = oacc[jn][h2 * 2] * inv;
            float v1 = oacc[jn][h2 * 2 + 1] * inv;
            uint32_t hi, lo;
            pack_hilo(v0, v1, hi, lo);
            *(uint32_t*)(Yhi + base + col) = hi;
            *(uint32_t*)(Ylo + base + col) = lo;
        }
    }
}

// ---------------------------------------------------------------------------
extern "C" void kernel_launch(void* const* d_in, const int* in_sizes, int n_in,
                              void* d_out, int out_size)
{
    const float* x    = (const float*)d_in[0];
    const float* fcos = (const float*)d_in[1];
    const float* fsin = (const float*)d_in[2];
    const float* wq   = (const float*)d_in[3];
    const float* wk   = (const float*)d_in[4];
    const float* wv   = (const float*)d_in[5];
    const float* wo   = (const float*)d_in[6];
    float* out = (float*)d_out;

    float *qp, *kp, *vp;
    cudaGetSymbolAddress((void**)&qp, g_q);
    cudaGetSymbolAddress((void**)&kp, g_k);
    cudaGetSymbolAddress((void**)&vp, g_v);

    __nv_bfloat16 *xhi, *xlo, *yhi, *ylo;
    __nv_bfloat16 *qhi, *qlo, *khi, *klo, *vhi, *vlo;
    __nv_bfloat16 *wqhi, *wqlo, *wkhi, *wklo, *wvhi, *wvlo, *wohi, *wolo;
    cudaGetSymbolAddress((void**)&xhi, g_xhi);   cudaGetSymbolAddress((void**)&xlo, g_xlo);
    cudaGetSymbolAddress((void**)&yhi, g_yhi);   cudaGetSymbolAddress((void**)&ylo, g_ylo);
    cudaGetSymbolAddress((void**)&qhi, g_qhi);   cudaGetSymbolAddress((void**)&qlo, g_qlo);
    cudaGetSymbolAddress((void**)&khi, g_khi);   cudaGetSymbolAddress((void**)&klo, g_klo);
    cudaGetSymbolAddress((void**)&vhi, g_vhi);   cudaGetSymbolAddress((void**)&vlo, g_vlo);
    cudaGetSymbolAddress((void**)&wqhi, g_wqhi); cudaGetSymbolAddress((void**)&wqlo, g_wqlo);
    cudaGetSymbolAddress((void**)&wkhi, g_wkhi); cudaGetSymbolAddress((void**)&wklo, g_wklo);
    cudaGetSymbolAddress((void**)&wvhi, g_wvhi); cudaGetSymbolAddress((void**)&wvlo, g_wvlo);
    cudaGetSymbolAddress((void**)&wohi, g_wohi); cudaGetSymbolAddress((void**)&wolo, g_wolo);

    const int M = B_ * T_;  // 4096

    // fp32 -> bf16 hi/lo splits of inputs/weights
    {
        int n4;
        n4 = (M * C_) / 4;
        cvt_hilo<<<(n4 + 255) / 256, 256>>>((const float4*)x, (__nv_bfloat162*)xhi, (__nv_bfloat162*)xlo, n4);
        n4 = (C_ * C_) / 4;
        cvt_hilo<<<(n4 + 255) / 256, 256>>>((const float4*)wq, (__nv_bfloat162*)wqhi, (__nv_bfloat162*)wqlo, n4);
        cvt_hilo<<<(n4 + 255) / 256, 256>>>((const float4*)wo, (__nv_bfloat162*)wohi, (__nv_bfloat162*)wolo, n4);
        n4 = (NKV * HD * C_) / 4;
        cvt_hilo<<<(n4 + 255) / 256, 256>>>((const float4*)wk, (__nv_bfloat162*)wkhi, (__nv_bfloat162*)wklo, n4);
        cvt_hilo<<<(n4 + 255) / 256, 256>>>((const float4*)wv, (__nv_bfloat162*)wvhi, (__nv_bfloat162*)wvlo, n4);
    }

    cudaFuncSetAttribute(gemm_mma, cudaFuncAttributeMaxDynamicSharedMemorySize, GSM_TOTAL);

    // QKV projections (fp32 scatter into [B, H, T, D]); CTA tile 256x128
    gemm_mma<<<dim3(C_ / 128, M / 256), 256, GSM_TOTAL>>>(xhi, xlo, wqhi, wqlo, qp, C_, C_, 1, NH);
    gemm_mma<<<dim3((NKV * HD) / 128, M / 256), 256, GSM_TOTAL>>>(xhi, xlo, wkhi, wklo, kp, C_, NKV * HD, 1, NKV);
    gemm_mma<<<dim3((NKV * HD) / 128, M / 256), 256, GSM_TOTAL>>>(xhi, xlo, wvhi, wvlo, vp, C_, NKV * HD, 1, NKV);

    // RoPE -> bf16 hi/lo (Q pre-scaled by SCALE*log2e for base-2 softmax)
    rope_hilo<<<(B_ * NH  * T_ * 64) / 256, 256>>>(qp, fcos, fsin,
        (__nv_bfloat162*)qhi, (__nv_bfloat162*)qlo, QSCL);
    rope_hilo<<<(B_ * NKV * T_ * 64) / 256, 256>>>(kp, fcos, fsin,
        (__nv_bfloat162*)khi, (__nv_bfloat162*)klo, 1.0f);
    // V -> bf16 hi/lo
    {
        int n4 = (B_ * NKV * T_ * HD) / 4;
        cvt_hilo<<<(n4 + 255) / 256, 256>>>((const float4*)vp, (__nv_bfloat162*)vhi, (__nv_bfloat162*)vlo, n4);
    }

    // Tensor-core flash attention -> yhi/ylo
    cudaFuncSetAttribute(attn_mma, cudaFuncAttributeMaxDynamicSharedMemorySize, ASM_TOTAL);
    attn_mma<<<dim3(T_ / 128, B_ * NH), 256, ASM_TOTAL>>>(qhi, qlo, khi, klo, vhi, vlo, yhi, ylo);

    // Output projection
    gemm_mma<<<dim3(C_ / 128, M / 256), 256, GSM_TOTAL>>>(yhi, ylo, wohi, wolo, out, C_, C_, 0, 0);
}

// round 7
// speedup vs baseline: 1.0789x; 1.0789x over previous
#include <cuda_runtime.h>
#include <cuda_bf16.h>
#include <cuda_fp16.h>
#include <math.h>
#include <stdint.h>

#define B_   2
#define T_   2048
#define C_   2048
#define NH   16
#define NKV  4
#define HD   128
#define SCALE 0.08838834764831845f           // 1/sqrt(128)
#define QSCL  0.1275495818259719f            // SCALE * log2(e)

// ---------------------------------------------------------------------------
// Scratch (device globals; no allocation allowed)
// ---------------------------------------------------------------------------
__device__ float g_q[(size_t)B_ * NH  * T_ * HD];   // [B, NH, T, D] fp32
__device__ float g_k[(size_t)B_ * NKV * T_ * HD];
__device__ float g_v[(size_t)B_ * NKV * T_ * HD];

__device__ __nv_bfloat16 g_xhi[(size_t)B_ * T_ * C_];
__device__ __nv_bfloat16 g_xlo[(size_t)B_ * T_ * C_];
__device__ __nv_bfloat16 g_yhi[(size_t)B_ * T_ * C_];
__device__ __nv_bfloat16 g_ylo[(size_t)B_ * T_ * C_];
__device__ __nv_bfloat16 g_qhi[(size_t)B_ * NH  * T_ * HD];
__device__ __nv_bfloat16 g_qlo[(size_t)B_ * NH  * T_ * HD];
__device__ __nv_bfloat16 g_khi[(size_t)B_ * NKV * T_ * HD];
__device__ __nv_bfloat16 g_klo[(size_t)B_ * NKV * T_ * HD];
__device__ __half        g_vhi[(size_t)B_ * NKV * T_ * HD];   // f16 for PV path
__device__ __half        g_vlo[(size_t)B_ * NKV * T_ * HD];
__device__ __nv_bfloat16 g_wqhi[(size_t)C_ * C_];
__device__ __nv_bfloat16 g_wqlo[(size_t)C_ * C_];
__device__ __nv_bfloat16 g_wkhi[(size_t)NKV * HD * C_];
__device__ __nv_bfloat16 g_wklo[(size_t)NKV * HD * C_];
__device__ __nv_bfloat16 g_wvhi[(size_t)NKV * HD * C_];
__device__ __nv_bfloat16 g_wvlo[(size_t)NKV * HD * C_];
__device__ __nv_bfloat16 g_wohi[(size_t)C_ * C_];
__device__ __nv_bfloat16 g_wolo[(size_t)C_ * C_];

// ---------------------------------------------------------------------------
// PTX helpers — arch-agnostic (sm_80+)
// ---------------------------------------------------------------------------
__device__ __forceinline__ uint32_t smem_u32(const void* p) {
    uint32_t a;
    asm("{ .reg .u64 t; cvta.to.shared.u64 t, %1; cvt.u32.u64 %0, t; }"
        : "=r"(a) : "l"(p));
    return a;
}
__device__ __forceinline__ void cp_async16(uint32_t saddr, const void* gaddr) {
    asm volatile("cp.async.cg.shared.global [%0], [%1], 16;"
                 :: "r"(saddr), "l"(gaddr));
}
__device__ __forceinline__ void cp_commit() { asm volatile("cp.async.commit_group;"); }
template <int N> __device__ __forceinline__ void cp_wait() {
    asm volatile("cp.async.wait_group %0;" :: "n"(N));
}
__device__ __forceinline__ void ldsm4(uint32_t* r, uint32_t addr) {
    asm volatile("ldmatrix.sync.aligned.m8n8.x4.shared.b16 {%0,%1,%2,%3}, [%4];"
                 : "=r"(r[0]), "=r"(r[1]), "=r"(r[2]), "=r"(r[3]) : "r"(addr));
}
__device__ __forceinline__ void ldsm4t(uint32_t* r, uint32_t addr) {
    asm volatile("ldmatrix.sync.aligned.m8n8.x4.trans.shared.b16 {%0,%1,%2,%3}, [%4];"
                 : "=r"(r[0]), "=r"(r[1]), "=r"(r[2]), "=r"(r[3]) : "r"(addr));
}
__device__ __forceinline__ void mma_bf16(float* c, const uint32_t* a,
                                         uint32_t b0, uint32_t b1) {
    asm volatile(
        "mma.sync.aligned.m16n8k16.row.col.f32.bf16.bf16.f32 "
        "{%0,%1,%2,%3}, {%4,%5,%6,%7}, {%8,%9}, {%0,%1,%2,%3};"
        : "+f"(c[0]), "+f"(c[1]), "+f"(c[2]), "+f"(c[3])
        : "r"(a[0]), "r"(a[1]), "r"(a[2]), "r"(a[3]), "r"(b0), "r"(b1));
}
__device__ __forceinline__ void mma_f16(float* c, const uint32_t* a,
                                        uint32_t b0, uint32_t b1) {
    asm volatile(
        "mma.sync.aligned.m16n8k16.row.col.f32.f16.f16.f32 "
        "{%0,%1,%2,%3}, {%4,%5,%6,%7}, {%8,%9}, {%0,%1,%2,%3};"
        : "+f"(c[0]), "+f"(c[1]), "+f"(c[2]), "+f"(c[3])
        : "r"(a[0]), "r"(a[1]), "r"(a[2]), "r"(a[3]), "r"(b0), "r"(b1));
}
__device__ __forceinline__ float ex2f(float x) {
    float y; asm("ex2.approx.f32 %0, %1;" : "=f"(y) : "f"(x)); return y;
}
// Paired exp2: pack (s0,s1) -> f16x2 (lo=s0), MUFU once, return packed P frag
// plus f32 copies for the row sum. (cvt d, a, b => d.hi = a, d.lo = b)
__device__ __forceinline__ uint32_t ex2_pack(float s0, float s1,
                                             float& e0, float& e1) {
    uint32_t t;
    asm("{\n\t.reg .b16 l, h;\n\t"
        "cvt.rn.f16x2.f32 %0, %4, %3;\n\t"
        "ex2.approx.f16x2 %0, %0;\n\t"
        "mov.b32 {l, h}, %0;\n\t"
        "cvt.f32.f16 %1, l;\n\t"
        "cvt.f32.f16 %2, h;\n\t}"
        : "=r"(t), "=f"(e0), "=f"(e1) : "f"(s0), "f"(s1));
    return t;
}
__device__ __forceinline__ void pack_hilo(float x, float y, uint32_t& hi, uint32_t& lo) {
    __nv_bfloat16 hx = __float2bfloat16(x), hy = __float2bfloat16(y);
    __nv_bfloat16 lx = __float2bfloat16(x - __bfloat162float(hx));
    __nv_bfloat16 ly = __float2bfloat16(y - __bfloat162float(hy));
    __nv_bfloat162 h2(hx, hy), l2(lx, ly);
    hi = *reinterpret_cast<uint32_t*>(&h2);
    lo = *reinterpret_cast<uint32_t*>(&l2);
}

// ---------------------------------------------------------------------------
// fp32 -> bf16 hi/lo split
// ---------------------------------------------------------------------------
__global__ void cvt_hilo(const float4* __restrict__ in,
                         __nv_bfloat162* __restrict__ hi2,
                         __nv_bfloat162* __restrict__ lo2, int n4)
{
    int i = blockIdx.x * blockDim.x + threadIdx.x;
    if (i >= n4) return;
    float4 v = in[i];
    uint32_t h0, l0, h1, l1;
    pack_hilo(v.x, v.y, h0, l0);
    pack_hilo(v.z, v.w, h1, l1);
    hi2[2 * i + 0] = *reinterpret_cast<__nv_bfloat162*>(&h0);
    hi2[2 * i + 1] = *reinterpret_cast<__nv_bfloat162*>(&h1);
    lo2[2 * i + 0] = *reinterpret_cast<__nv_bfloat162*>(&l0);
    lo2[2 * i + 1] = *reinterpret_cast<__nv_bfloat162*>(&l1);
}

// fp32 -> f16 hi/lo split (for V)
__global__ void cvt_hilo_h(const float4* __restrict__ in,
                           __half2* __restrict__ hi2,
                           __half2* __restrict__ lo2, int n4)
{
    int i = blockIdx.x * blockDim.x + threadIdx.x;
    if (i >= n4) return;
    float4 v = in[i];
    __half h0 = __float2half(v.x), h1 = __float2half(v.y);
    __half h2 = __float2half(v.z), h3 = __float2half(v.w);
    __half l0 = __float2half(v.x - __half2float(h0));
    __half l1 = __float2half(v.y - __half2float(h1));
    __half l2 = __float2half(v.z - __half2float(h2));
    __half l3 = __float2half(v.w - __half2float(h3));
    hi2[2 * i + 0] = __half2(h0, h1);
    hi2[2 * i + 1] = __half2(h2, h3);
    lo2[2 * i + 0] = __half2(l0, l1);
    lo2[2 * i + 1] = __half2(l2, l3);
}

// ---------------------------------------------------------------------------
// RoPE on fp32 [B,Hx,T,D] input -> bf16 hi/lo outputs (optionally scaled).
// ---------------------------------------------------------------------------
__global__ void rope_hilo(const float* __restrict__ buf,
                          const float* __restrict__ fcos,
                          const float* __restrict__ fsin,
                          __nv_bfloat162* __restrict__ hi2,
                          __nv_bfloat162* __restrict__ lo2, float scl)
{
    int idx = blockIdx.x * blockDim.x + threadIdx.x;
    int d2 = idx & 63;
    int t  = (idx >> 6) & (T_ - 1);
    float c = fcos[t * 64 + d2];
    float s = fsin[t * 64 + d2];
    const float* p = buf + (size_t)idx * 2;
    float x0 = p[0], x1 = p[1];
    float r0 = (x0 * c - x1 * s) * scl;
    float r1 = (x0 * s + x1 * c) * scl;
    uint32_t h, l;
    pack_hilo(r0, r1, h, l);
    hi2[idx] = *reinterpret_cast<__nv_bfloat162*>(&h);
    lo2[idx] = *reinterpret_cast<__nv_bfloat162*>(&l);
}

// ---------------------------------------------------------------------------
// mma.sync bf16-split GEMM (NT) — exact R5 config (128x128, BK=32, 2-stage).
// ---------------------------------------------------------------------------
#define GMAT_BYTES 10240
#define GSTAGE     40960
#define GSM_TOTAL  (2 * GSTAGE)

__global__ __launch_bounds__(256) void gemm_mma(
    const __nv_bfloat16* __restrict__ Ahi, const __nv_bfloat16* __restrict__ Alo,
    const __nv_bfloat16* __restrict__ Whi, const __nv_bfloat16* __restrict__ Wlo,
    float* __restrict__ Cout, int K, int N, int mode, int Hn)
{
    extern __shared__ char smem[];
    const int tid = threadIdx.x;
    const int lid = tid & 31, wid = tid >> 5;
    const int wm = wid & 1, wn = wid >> 1;
    const int bm = blockIdx.y, bn = blockIdx.x;

    const __nv_bfloat16* srcs[4];
    srcs[0] = Ahi + (size_t)bm * 128 * K;
    srcs[1] = Alo + (size_t)bm * 128 * K;
    srcs[2] = Whi + (size_t)bn * 128 * K;
    srcs[3] = Wlo + (size_t)bn * 128 * K;

    float acc[4][4][4];
    #pragma unroll
    for (int mi = 0; mi < 4; mi++)
        #pragma unroll
        for (int ni = 0; ni < 4; ni++)
            #pragma unroll
            for (int e = 0; e < 4; e++) acc[mi][ni][e] = 0.f;

    const int nst = K >> 5;

    auto load_stage = [&](int s) {
        char* base = smem + (s & 1) * GSTAGE;
        const int k0 = s << 5;
        #pragma unroll
        for (int m = 0; m < 4; m++) {
            const __nv_bfloat16* src = srcs[m] + k0;
            char* dst = base + m * GMAT_BYTES;
            #pragma unroll
            for (int j = 0; j < 2; j++) {
                int idx = j * 256 + tid;
                int row = idx >> 2;
                int c   = idx & 3;
                cp_async16(smem_u32(dst + row * 80 + c * 16),
                           src + (size_t)row * K + c * 8);
            }
        }
        cp_commit();
    };

    load_stage(0);

    for (int s = 0; s < nst; s++) {
        if (s + 1 < nst) { load_stage(s + 1); cp_wait<1>(); }
        else             { cp_wait<0>(); }
        __syncthreads();

        const uint32_t sb = smem_u32(smem + (s & 1) * GSTAGE);
        #pragma unroll
        for (int kk = 0; kk < 2; kk++) {
            uint32_t ah[4][4], al[4][4], bh[2][4], bl[2][4];
            const int arow  = wm * 64 + (lid & 15);
            const int akcol = kk * 16 + ((lid & 16) ? 8 : 0);
            #pragma unroll
            for (int mi = 0; mi < 4; mi++) {
                uint32_t addr = sb + (arow + mi * 16) * 80 + akcol * 2;
                ldsm4(ah[mi], addr);
                ldsm4(al[mi], addr + GMAT_BYTES);
            }
            const int brow  = wn * 32 + (lid & 7) + ((lid & 16) ? 8 : 0);
            const int bkcol = kk * 16 + ((lid & 8) ? 8 : 0);
            #pragma unroll
            for (int p = 0; p < 2; p++) {
                uint32_t addr = sb + 2 * GMAT_BYTES + (brow + p * 16) * 80 + bkcol * 2;
                ldsm4(bh[p], addr);
                ldsm4(bl[p], addr + GMAT_BYTES);
            }
            #pragma unroll
            for (int mi = 0; mi < 4; mi++)
                #pragma unroll
                for (int ni = 0; ni < 4; ni++) {
                    const int p = ni >> 1, q = (ni & 1) * 2;
                    mma_bf16(acc[mi][ni], ah[mi], bh[p][q], bh[p][q + 1]);
                    mma_bf16(acc[mi][ni], ah[mi], bl[p][q], bl[p][q + 1]);
                    mma_bf16(acc[mi][ni], al[mi], bh[p][q], bh[p][q + 1]);
                }
        }
        __syncthreads();
    }

    const int r0c = lid >> 2, cc = (lid & 3) * 2;
    #pragma unroll
    for (int mi = 0; mi < 4; mi++) {
        #pragma unroll
        for (int ni = 0; ni < 4; ni++) {
            int row = bm * 128 + wm * 64 + mi * 16 + r0c;
            int col = bn * 128 + wn * 32 + ni * 8 + cc;
            #pragma unroll
            for (int half = 0; half < 2; half++) {
                int rr = row + half * 8;
                float2 v = make_float2(acc[mi][ni][half * 2], acc[mi][ni][half * 2 + 1]);
                if (mode == 0) {
                    *(float2*)(Cout + (size_t)rr * N + col) = v;
                } else {
                    int b = rr >> 11, t = rr & (T_ - 1);
                    int h = col >> 7, d = col & (HD - 1);
                    *(float2*)(Cout + ((((size_t)b * Hn + h) * T_ + t) * HD + d)) = v;
                }
            }
        }
    }
}

// ---------------------------------------------------------------------------
// Tensor-core causal flash attention.
// S = QK^T: bf16 hi/lo 3-term.  Softmax: paired ex2.approx.f16x2 (packed
// output IS the f16 P fragment).  PV: f16, 2-term (P * Vhi + P * Vlo).
// ---------------------------------------------------------------------------
#define AROWB  272
#define AQMAT  34816
#define AKVMAT 17408
#define AKVST  (4 * AKVMAT)
#define ASM_TOTAL (2 * AQMAT + 2 * AKVST)

__global__ __launch_bounds__(256, 1) void attn_mma(
    const __nv_bfloat16* __restrict__ Qhi, const __nv_bfloat16* __restrict__ Qlo,
    const __nv_bfloat16* __restrict__ Khi, const __nv_bfloat16* __restrict__ Klo,
    const __half* __restrict__ Vhi, const __half* __restrict__ Vlo,
    __nv_bfloat16* __restrict__ Yhi, __nv_bfloat16* __restrict__ Ylo)
{
    extern __shared__ char smem[];
    const int tid = threadIdx.x;
    const int lid = tid & 31, wid = tid >> 5;
    const int qt = (T_ / 128 - 1) - blockIdx.x;
    const int bh = blockIdx.y;
    const int b  = bh >> 4, h = bh & 15;
    const int kvh = h >> 2;

    const size_t qg = ((size_t)(b * NH + h) * T_ + qt * 128) * HD;
    const size_t kg = (size_t)(b * NKV + kvh) * T_ * HD;

    const uint32_t sQhi = smem_u32(smem);
    const uint32_t sQlo = sQhi + AQMAT;
    const uint32_t sKV0 = sQlo + AQMAT;

    {
        #pragma unroll
        for (int i = 0; i < 16; i++) {
            int idx = i * 256 + tid;
            int mat = idx >> 11;
            int rem = idx & 2047;
            int row = rem >> 4, c = rem & 15;
            const __nv_bfloat16* src = (mat ? Qlo : Qhi) + qg + (size_t)row * HD + c * 8;
            cp_async16((mat ? sQlo : sQhi) + row * AROWB + c * 16, src);
        }
    }
    const void* kvsrc[4] = {Khi, Klo, Vhi, Vlo};
    auto load_kv = [&](int kt, int st) {
        uint32_t sb = sKV0 + st * AKVST;
        const size_t base = kg + (size_t)kt * 64 * HD;
        #pragma unroll
        for (int i = 0; i < 16; i++) {
            int idx = i * 256 + tid;
            int mat = idx >> 10;
            int rem = idx & 1023;
            int row = rem >> 4, c = rem & 15;
            cp_async16(sb + mat * AKVMAT + row * AROWB + c * 16,
                       (const char*)kvsrc[mat] + 2 * (base + (size_t)row * HD + c * 8));
        }
        cp_commit();
    };
    load_kv(0, 0);

    float oacc[16][4];
    #pragma unroll
    for (int jn = 0; jn < 16; jn++)
        #pragma unroll
        for (int e = 0; e < 4; e++) oacc[jn][e] = 0.f;
    float mrow[2] = {-1e30f, -1e30f};
    float lrow[2] = {0.f, 0.f};

    const int nkt = 2 * qt + 2;

    for (int kt = 0; kt < nkt; kt++) {
        if (kt + 1 < nkt) { load_kv(kt + 1, (kt + 1) & 1); cp_wait<1>(); }
        else              { cp_wait<0>(); }
        __syncthreads();

        const uint32_t sb  = sKV0 + (kt & 1) * AKVST;
        const uint32_t sKh = sb, sKl = sb + AKVMAT;
        const uint32_t sVh = sb + 2 * AKVMAT, sVl = sb + 3 * AKVMAT;

        // ---- S = Q K^T (bf16 3-term)
        float sacc[8][4];
        #pragma unroll
        for (int j = 0; j < 8; j++)
            #pragma unroll
            for (int e = 0; e < 4; e++) sacc[j][e] = 0.f;

        #pragma unroll
        for (int kk = 0; kk < 8; kk++) {
            uint32_t ah[4], al[4];
            const int arow  = wid * 16 + (lid & 15);
            const int akcol = kk * 16 + ((lid & 16) ? 8 : 0);
            uint32_t qaddr = sQhi + arow * AROWB + akcol * 2;
            ldsm4(ah, qaddr);
            ldsm4(al, qaddr + AQMAT);
            #pragma unroll
            for (int np = 0; np < 4; np++) {
                uint32_t bh4[4], bl4[4];
                const int brow  = np * 16 + (lid & 7) + ((lid & 16) ? 8 : 0);
                const int bkcol = kk * 16 + ((lid & 8) ? 8 : 0);
                uint32_t kaddr = brow * AROWB + bkcol * 2;
                ldsm4(bh4, sKh + kaddr);
                ldsm4(bl4, sKl + kaddr);
                #pragma unroll
                for (int jj = 0; jj < 2; jj++) {
                    const int j = 2 * np + jj, q = jj * 2;
                    mma_bf16(sacc[j], ah, bh4[q], bh4[q + 1]);
                    mma_bf16(sacc[j], ah, bl4[q], bl4[q + 1]);
                    mma_bf16(sacc[j], al, bh4[q], bh4[q + 1]);
                }
            }
        }

        // ---- causal mask (diagonal tiles only)
        const int kv0 = kt * 64;
        if (kv0 + 63 > qt * 128) {
            const int rbase = qt * 128 + wid * 16 + (lid >> 2);
            #pragma unroll
            for (int j = 0; j < 8; j++)
                #pragma unroll
                for (int e = 0; e < 4; e++) {
                    int col = kv0 + j * 8 + 2 * (lid & 3) + (e & 1);
                    int row = rbase + (e >> 1) * 8;
                    if (col > row) sacc[j][e] = -1e30f;
                }
        }

        // ---- online softmax: row max, then paired f16x2 exp -> P fragments
        float mnew[2];
        #pragma unroll
        for (int h2 = 0; h2 < 2; h2++) {
            float tm = -1e30f;
            #pragma unroll
            for (int j = 0; j < 8; j++)
                tm = fmaxf(tm, fmaxf(sacc[j][h2 * 2], sacc[j][h2 * 2 + 1]));
            tm = fmaxf(tm, __shfl_xor_sync(0xffffffffu, tm, 1));
            tm = fmaxf(tm, __shfl_xor_sync(0xffffffffu, tm, 2));
            mnew[h2] = fmaxf(mrow[h2], tm);
        }

        uint32_t pfrag[8][2];
        float sum0 = 0.f, sum1 = 0.f;
        #pragma unroll
        for (int j = 0; j < 8; j++) {
            float e0, e1;
            pfrag[j][0] = ex2_pack(sacc[j][0] - mnew[0], sacc[j][1] - mnew[0], e0, e1);
            sum0 += e0 + e1;
            pfrag[j][1] = ex2_pack(sacc[j][2] - mnew[1], sacc[j][3] - mnew[1], e0, e1);
            sum1 += e0 + e1;
        }
        sum0 += __shfl_xor_sync(0xffffffffu, sum0, 1);
        sum0 += __shfl_xor_sync(0xffffffffu, sum0, 2);
        sum1 += __shfl_xor_sync(0xffffffffu, sum1, 1);
        sum1 += __shfl_xor_sync(0xffffffffu, sum1, 2);

        #pragma unroll
        for (int h2 = 0; h2 < 2; h2++) {
            float corr = ex2f(mrow[h2] - mnew[h2]);
            lrow[h2] = lrow[h2] * corr + (h2 ? sum1 : sum0);
            mrow[h2] = mnew[h2];
            #pragma unroll
            for (int jn = 0; jn < 16; jn++) {
                oacc[jn][h2 * 2]     *= corr;
                oacc[jn][h2 * 2 + 1] *= corr;
            }
        }

        // ---- O += P V (f16, 2-term)
        #pragma unroll
        for (int ks = 0; ks < 4; ks++) {
            uint32_t pf[4];
            pf[0] = pfrag[2 * ks][0];
            pf[1] = pfrag[2 * ks][1];
            pf[2] = pfrag[2 * ks + 1][0];
            pf[3] = pfrag[2 * ks + 1][1];
            #pragma unroll
            for (int np = 0; np < 8; np++) {
                uint32_t vh4[4], vl4[4];
                const int vrow = ks * 16 + (lid & 7) + 8 * ((lid >> 3) & 1);
                const int vcol = np * 16 + 8 * (lid >> 4);
                uint32_t vaddr = vrow * AROWB + vcol * 2;
                ldsm4t(vh4, sVh + vaddr);
                ldsm4t(vl4, sVl + vaddr);
                #pragma unroll
                for (int jj = 0; jj < 2; jj++) {
                    const int jn = 2 * np + jj, q = jj * 2;
                    mma_f16(oacc[jn], pf, vh4[q], vh4[q + 1]);
                    mma_f16(oacc[jn], pf, vl4[q], vl4[q + 1]);
                }
            }
        }
        __syncthreads();
    }

    // ---- epilogue: normalize, split hi/lo, store y[b, t, h*128 + d]
    #pragma unroll
    for (int h2 = 0; h2 < 2; h2++) {
        float inv = 1.f / lrow[h2];
        int row_t = qt * 128 + wid * 16 + (lid >> 2) + 8 * h2;
        size_t base = ((size_t)b * T_ + row_t) * C_ + h * HD;
        #pragma unroll
        for (int jn = 0; jn < 16; jn++) {
            int col = jn * 8 + 2 * (lid & 3);
            float v0 = oacc[jn][h2 * 2] * inv;
            float v1 = oacc[jn][h2 * 2 + 1] * inv;
            uint32_t hi, lo;
            pack_hilo(v0, v1, hi, lo);
            *(uint32_t*)(Yhi + base + col) = hi;
            *(uint32_t*)(Ylo + base + col) = lo;
        }
    }
}

// ---------------------------------------------------------------------------
extern "C" void kernel_launch(void* const* d_in, const int* in_sizes, int n_in,
                              void* d_out, int out_size)
{
    const float* x    = (const float*)d_in[0];
    const float* fcos = (const float*)d_in[1];
    const float* fsin = (const float*)d_in[2];
    const float* wq   = (const float*)d_in[3];
    const float* wk   = (const float*)d_in[4];
    const float* wv   = (const float*)d_in[5];
    const float* wo   = (const float*)d_in[6];
    float* out = (float*)d_out;

    float *qp, *kp, *vp;
    cudaGetSymbolAddress((void**)&qp, g_q);
    cudaGetSymbolAddress((void**)&kp, g_k);
    cudaGetSymbolAddress((void**)&vp, g_v);

    __nv_bfloat16 *xhi, *xlo, *yhi, *ylo;
    __nv_bfloat16 *qhi, *qlo, *khi, *klo;
    __half *vhi, *vlo;
    __nv_bfloat16 *wqhi, *wqlo, *wkhi, *wklo, *wvhi, *wvlo, *wohi, *wolo;
    cudaGetSymbolAddress((void**)&xhi, g_xhi);   cudaGetSymbolAddress((void**)&xlo, g_xlo);
    cudaGetSymbolAddress((void**)&yhi, g_yhi);   cudaGetSymbolAddress((void**)&ylo, g_ylo);
    cudaGetSymbolAddress((void**)&qhi, g_qhi);   cudaGetSymbolAddress((void**)&qlo, g_qlo);
    cudaGetSymbolAddress((void**)&khi, g_khi);   cudaGetSymbolAddress((void**)&klo, g_klo);
    cudaGetSymbolAddress((void**)&vhi, g_vhi);   cudaGetSymbolAddress((void**)&vlo, g_vlo);
    cudaGetSymbolAddress((void**)&wqhi, g_wqhi); cudaGetSymbolAddress((void**)&wqlo, g_wqlo);
    cudaGetSymbolAddress((void**)&wkhi, g_wkhi); cudaGetSymbolAddress((void**)&wklo, g_wklo);
    cudaGetSymbolAddress((void**)&wvhi, g_wvhi); cudaGetSymbolAddress((void**)&wvlo, g_wvlo);
    cudaGetSymbolAddress((void**)&wohi, g_wohi); cudaGetSymbolAddress((void**)&wolo, g_wolo);

    const int M = B_ * T_;  // 4096

    // fp32 -> bf16 hi/lo splits of inputs/weights
    {
        int n4;
        n4 = (M * C_) / 4;
        cvt_hilo<<<(n4 + 255) / 256, 256>>>((const float4*)x, (__nv_bfloat162*)xhi, (__nv_bfloat162*)xlo, n4);
        n4 = (C_ * C_) / 4;
        cvt_hilo<<<(n4 + 255) / 256, 256>>>((const float4*)wq, (__nv_bfloat162*)wqhi, (__nv_bfloat162*)wqlo, n4);
        cvt_hilo<<<(n4 + 255) / 256, 256>>>((const float4*)wo, (__nv_bfloat162*)wohi, (__nv_bfloat162*)wolo, n4);
        n4 = (NKV * HD * C_) / 4;
        cvt_hilo<<<(n4 + 255) / 256, 256>>>((const float4*)wk, (__nv_bfloat162*)wkhi, (__nv_bfloat162*)wklo, n4);
        cvt_hilo<<<(n4 + 255) / 256, 256>>>((const float4*)wv, (__nv_bfloat162*)wvhi, (__nv_bfloat162*)wvlo, n4);
    }

    cudaFuncSetAttribute(gemm_mma, cudaFuncAttributeMaxDynamicSharedMemorySize, GSM_TOTAL);

    // QKV projections (fp32 scatter into [B, H, T, D])
    gemm_mma<<<dim3(C_ / 128, M / 128), 256, GSM_TOTAL>>>(xhi, xlo, wqhi, wqlo, qp, C_, C_, 1, NH);
    gemm_mma<<<dim3((NKV * HD) / 128, M / 128), 256, GSM_TOTAL>>>(xhi, xlo, wkhi, wklo, kp, C_, NKV * HD, 1, NKV);
    gemm_mma<<<dim3((NKV * HD) / 128, M / 128), 256, GSM_TOTAL>>>(xhi, xlo, wvhi, wvlo, vp, C_, NKV * HD, 1, NKV);

    // RoPE -> bf16 hi/lo (Q pre-scaled by SCALE*log2e for base-2 softmax)
    rope_hilo<<<(B_ * NH  * T_ * 64) / 256, 256>>>(qp, fcos, fsin,
        (__nv_bfloat162*)qhi, (__nv_bfloat162*)qlo, QSCL);
    rope_hilo<<<(B_ * NKV * T_ * 64) / 256, 256>>>(kp, fcos, fsin,
        (__nv_bfloat162*)khi, (__nv_bfloat162*)klo, 1.0f);
    // V -> f16 hi/lo
    {
        int n4 = (B_ * NKV * T_ * HD) / 4;
        cvt_hilo_h<<<(n4 + 255) / 256, 256>>>((const float4*)vp, (__half2*)vhi, (__half2*)vlo, n4);
    }

    // Tensor-core flash attention -> yhi/ylo
    cudaFuncSetAttribute(attn_mma, cudaFuncAttributeMaxDynamicSharedMemorySize, ASM_TOTAL);
    attn_mma<<<dim3(T_ / 128, B_ * NH), 256, ASM_TOTAL>>>(qhi, qlo, khi, klo, vhi, vlo, yhi, ylo);

    // Output projection
    gemm_mma<<<dim3(C_ / 128, M / 128), 256, GSM_TOTAL>>>(yhi, ylo, wohi, wolo, out, C_, C_, 0, 0);
}

// round 8
// speedup vs baseline: 1.2289x; 1.1390x over previous
#include <cuda_runtime.h>
#include <cuda_bf16.h>
#include <cuda_fp16.h>
#include <math.h>
#include <stdint.h>

#define B_   2
#define T_   2048
#define C_   2048
#define NH   16
#define NKV  4
#define HD   128
#define SCALE 0.08838834764831845f           // 1/sqrt(128)
#define QSCL  0.1275495818259719f            // SCALE * log2(e)

// ---------------------------------------------------------------------------
// Scratch (device globals; no allocation allowed)
// ---------------------------------------------------------------------------
__device__ float g_q[(size_t)B_ * NH  * T_ * HD];   // [B, NH, T, D] fp32
__device__ float g_k[(size_t)B_ * NKV * T_ * HD];
__device__ float g_v[(size_t)B_ * NKV * T_ * HD];

__device__ __nv_bfloat16 g_xhi[(size_t)B_ * T_ * C_];
__device__ __nv_bfloat16 g_xlo[(size_t)B_ * T_ * C_];
__device__ __half        g_yh [(size_t)B_ * T_ * C_];         // f16 attn output
__device__ __nv_bfloat16 g_qhi[(size_t)B_ * NH  * T_ * HD];
__device__ __nv_bfloat16 g_qlo[(size_t)B_ * NH  * T_ * HD];
__device__ __nv_bfloat16 g_khi[(size_t)B_ * NKV * T_ * HD];
__device__ __nv_bfloat16 g_klo[(size_t)B_ * NKV * T_ * HD];
__device__ __half        g_vhi[(size_t)B_ * NKV * T_ * HD];   // f16 for PV path
__device__ __half        g_vlo[(size_t)B_ * NKV * T_ * HD];
__device__ __nv_bfloat16 g_wqhi[(size_t)C_ * C_];
__device__ __nv_bfloat16 g_wqlo[(size_t)C_ * C_];
__device__ __nv_bfloat16 g_wkvhi[(size_t)2 * NKV * HD * C_]; // [wk; wv] rows 0-1023
__device__ __nv_bfloat16 g_wkvlo[(size_t)2 * NKV * HD * C_];
__device__ __half        g_wohi_h[(size_t)C_ * C_];           // f16 hi/lo for wo
__device__ __half        g_wolo_h[(size_t)C_ * C_];

// ---------------------------------------------------------------------------
// PTX helpers — arch-agnostic (sm_80+)
// ---------------------------------------------------------------------------
__device__ __forceinline__ uint32_t smem_u32(const void* p) {
    uint32_t a;
    asm("{ .reg .u64 t; cvta.to.shared.u64 t, %1; cvt.u32.u64 %0, t; }"
        : "=r"(a) : "l"(p));
    return a;
}
__device__ __forceinline__ void cp_async16(uint32_t saddr, const void* gaddr) {
    asm volatile("cp.async.cg.shared.global [%0], [%1], 16;"
                 :: "r"(saddr), "l"(gaddr));
}
__device__ __forceinline__ void cp_commit() { asm volatile("cp.async.commit_group;"); }
template <int N> __device__ __forceinline__ void cp_wait() {
    asm volatile("cp.async.wait_group %0;" :: "n"(N));
}
__device__ __forceinline__ void ldsm4(uint32_t* r, uint32_t addr) {
    asm volatile("ldmatrix.sync.aligned.m8n8.x4.shared.b16 {%0,%1,%2,%3}, [%4];"
                 : "=r"(r[0]), "=r"(r[1]), "=r"(r[2]), "=r"(r[3]) : "r"(addr));
}
__device__ __forceinline__ void ldsm4t(uint32_t* r, uint32_t addr) {
    asm volatile("ldmatrix.sync.aligned.m8n8.x4.trans.shared.b16 {%0,%1,%2,%3}, [%4];"
                 : "=r"(r[0]), "=r"(r[1]), "=r"(r[2]), "=r"(r[3]) : "r"(addr));
}
__device__ __forceinline__ void mma_bf16(float* c, const uint32_t* a,
                                         uint32_t b0, uint32_t b1) {
    asm volatile(
        "mma.sync.aligned.m16n8k16.row.col.f32.bf16.bf16.f32 "
        "{%0,%1,%2,%3}, {%4,%5,%6,%7}, {%8,%9}, {%0,%1,%2,%3};"
        : "+f"(c[0]), "+f"(c[1]), "+f"(c[2]), "+f"(c[3])
        : "r"(a[0]), "r"(a[1]), "r"(a[2]), "r"(a[3]), "r"(b0), "r"(b1));
}
__device__ __forceinline__ void mma_f16(float* c, const uint32_t* a,
                                        uint32_t b0, uint32_t b1) {
    asm volatile(
        "mma.sync.aligned.m16n8k16.row.col.f32.f16.f16.f32 "
        "{%0,%1,%2,%3}, {%4,%5,%6,%7}, {%8,%9}, {%0,%1,%2,%3};"
        : "+f"(c[0]), "+f"(c[1]), "+f"(c[2]), "+f"(c[3])
        : "r"(a[0]), "r"(a[1]), "r"(a[2]), "r"(a[3]), "r"(b0), "r"(b1));
}
__device__ __forceinline__ float ex2f(float x) {
    float y; asm("ex2.approx.f32 %0, %1;" : "=f"(y) : "f"(x)); return y;
}
__device__ __forceinline__ uint32_t ex2_pack(float s0, float s1,
                                             float& e0, float& e1) {
    uint32_t t;
    asm("{\n\t.reg .b16 l, h;\n\t"
        "cvt.rn.f16x2.f32 %0, %4, %3;\n\t"
        "ex2.approx.f16x2 %0, %0;\n\t"
        "mov.b32 {l, h}, %0;\n\t"
        "cvt.f32.f16 %1, l;\n\t"
        "cvt.f32.f16 %2, h;\n\t}"
        : "=r"(t), "=f"(e0), "=f"(e1) : "f"(s0), "f"(s1));
    return t;
}
__device__ __forceinline__ void pack_hilo(float x, float y, uint32_t& hi, uint32_t& lo) {
    __nv_bfloat16 hx = __float2bfloat16(x), hy = __float2bfloat16(y);
    __nv_bfloat16 lx = __float2bfloat16(x - __bfloat162float(hx));
    __nv_bfloat16 ly = __float2bfloat16(y - __bfloat162float(hy));
    __nv_bfloat162 h2(hx, hy), l2(lx, ly);
    hi = *reinterpret_cast<uint32_t*>(&h2);
    lo = *reinterpret_cast<uint32_t*>(&l2);
}

// ---------------------------------------------------------------------------
// fp32 -> bf16 hi/lo split
// ---------------------------------------------------------------------------
__global__ void cvt_hilo(const float4* __restrict__ in,
                         __nv_bfloat162* __restrict__ hi2,
                         __nv_bfloat162* __restrict__ lo2, int n4)
{
    int i = blockIdx.x * blockDim.x + threadIdx.x;
    if (i >= n4) return;
    float4 v = in[i];
    uint32_t h0, l0, h1, l1;
    pack_hilo(v.x, v.y, h0, l0);
    pack_hilo(v.z, v.w, h1, l1);
    hi2[2 * i + 0] = *reinterpret_cast<__nv_bfloat162*>(&h0);
    hi2[2 * i + 1] = *reinterpret_cast<__nv_bfloat162*>(&h1);
    lo2[2 * i + 0] = *reinterpret_cast<__nv_bfloat162*>(&l0);
    lo2[2 * i + 1] = *reinterpret_cast<__nv_bfloat162*>(&l1);
}

// fp32 -> f16 hi/lo split (for V and wo)
__global__ void cvt_hilo_h(const float4* __restrict__ in,
                           __half2* __restrict__ hi2,
                           __half2* __restrict__ lo2, int n4)
{
    int i = blockIdx.x * blockDim.x + threadIdx.x;
    if (i >= n4) return;
    float4 v = in[i];
    __half h0 = __float2half(v.x), h1 = __float2half(v.y);
    __half h2 = __float2half(v.z), h3 = __float2half(v.w);
    __half l0 = __float2half(v.x - __half2float(h0));
    __half l1 = __float2half(v.y - __half2float(h1));
    __half l2 = __float2half(v.z - __half2float(h2));
    __half l3 = __float2half(v.w - __half2float(h3));
    hi2[2 * i + 0] = __half2(h0, h1);
    hi2[2 * i + 1] = __half2(h2, h3);
    lo2[2 * i + 0] = __half2(l0, l1);
    lo2[2 * i + 1] = __half2(l2, l3);
}

// ---------------------------------------------------------------------------
// RoPE on fp32 [B,Hx,T,D] input -> bf16 hi/lo outputs (optionally scaled).
// ---------------------------------------------------------------------------
__global__ void rope_hilo(const float* __restrict__ buf,
                          const float* __restrict__ fcos,
                          const float* __restrict__ fsin,
                          __nv_bfloat162* __restrict__ hi2,
                          __nv_bfloat162* __restrict__ lo2, float scl)
{
    int idx = blockIdx.x * blockDim.x + threadIdx.x;
    int d2 = idx & 63;
    int t  = (idx >> 6) & (T_ - 1);
    float c = fcos[t * 64 + d2];
    float s = fsin[t * 64 + d2];
    const float* p = buf + (size_t)idx * 2;
    float x0 = p[0], x1 = p[1];
    float r0 = (x0 * c - x1 * s) * scl;
    float r1 = (x0 * s + x1 * c) * scl;
    uint32_t h, l;
    pack_hilo(r0, r1, h, l);
    hi2[idx] = *reinterpret_cast<__nv_bfloat162*>(&h);
    lo2[idx] = *reinterpret_cast<__nv_bfloat162*>(&l);
}

// ---------------------------------------------------------------------------
// mma.sync bf16-split GEMM (NT) — R5 config (128x128, BK=32, 2-stage).
// mode 0: row-major.  mode 1: scatter [B,Hn,T,HD] to Cout.
// mode 2: merged KV — col<512 scatter to Cout (k), col>=512 to Cout2 (v).
// ---------------------------------------------------------------------------
#define GMAT_BYTES 10240
#define GSTAGE     40960
#define GSM_TOTAL  (2 * GSTAGE)

__global__ __launch_bounds__(256) void gemm_mma(
    const __nv_bfloat16* __restrict__ Ahi, const __nv_bfloat16* __restrict__ Alo,
    const __nv_bfloat16* __restrict__ Whi, const __nv_bfloat16* __restrict__ Wlo,
    float* __restrict__ Cout, float* __restrict__ Cout2,
    int K, int N, int mode, int Hn)
{
    extern __shared__ char smem[];
    const int tid = threadIdx.x;
    const int lid = tid & 31, wid = tid >> 5;
    const int wm = wid & 1, wn = wid >> 1;
    const int bm = blockIdx.y, bn = blockIdx.x;

    const __nv_bfloat16* srcs[4];
    srcs[0] = Ahi + (size_t)bm * 128 * K;
    srcs[1] = Alo + (size_t)bm * 128 * K;
    srcs[2] = Whi + (size_t)bn * 128 * K;
    srcs[3] = Wlo + (size_t)bn * 128 * K;

    float acc[4][4][4];
    #pragma unroll
    for (int mi = 0; mi < 4; mi++)
        #pragma unroll
        for (int ni = 0; ni < 4; ni++)
            #pragma unroll
            for (int e = 0; e < 4; e++) acc[mi][ni][e] = 0.f;

    const int nst = K >> 5;

    auto load_stage = [&](int s) {
        char* base = smem + (s & 1) * GSTAGE;
        const int k0 = s << 5;
        #pragma unroll
        for (int m = 0; m < 4; m++) {
            const __nv_bfloat16* src = srcs[m] + k0;
            char* dst = base + m * GMAT_BYTES;
            #pragma unroll
            for (int j = 0; j < 2; j++) {
                int idx = j * 256 + tid;
                int row = idx >> 2;
                int c   = idx & 3;
                cp_async16(smem_u32(dst + row * 80 + c * 16),
                           src + (size_t)row * K + c * 8);
            }
        }
        cp_commit();
    };

    load_stage(0);

    for (int s = 0; s < nst; s++) {
        if (s + 1 < nst) { load_stage(s + 1); cp_wait<1>(); }
        else             { cp_wait<0>(); }
        __syncthreads();

        const uint32_t sb = smem_u32(smem + (s & 1) * GSTAGE);
        #pragma unroll
        for (int kk = 0; kk < 2; kk++) {
            uint32_t ah[4][4], al[4][4], bh[2][4], bl[2][4];
            const int arow  = wm * 64 + (lid & 15);
            const int akcol = kk * 16 + ((lid & 16) ? 8 : 0);
            #pragma unroll
            for (int mi = 0; mi < 4; mi++) {
                uint32_t addr = sb + (arow + mi * 16) * 80 + akcol * 2;
                ldsm4(ah[mi], addr);
                ldsm4(al[mi], addr + GMAT_BYTES);
            }
            const int brow  = wn * 32 + (lid & 7) + ((lid & 16) ? 8 : 0);
            const int bkcol = kk * 16 + ((lid & 8) ? 8 : 0);
            #pragma unroll
            for (int p = 0; p < 2; p++) {
                uint32_t addr = sb + 2 * GMAT_BYTES + (brow + p * 16) * 80 + bkcol * 2;
                ldsm4(bh[p], addr);
                ldsm4(bl[p], addr + GMAT_BYTES);
            }
            #pragma unroll
            for (int mi = 0; mi < 4; mi++)
                #pragma unroll
                for (int ni = 0; ni < 4; ni++) {
                    const int p = ni >> 1, q = (ni & 1) * 2;
                    mma_bf16(acc[mi][ni], ah[mi], bh[p][q], bh[p][q + 1]);
                    mma_bf16(acc[mi][ni], ah[mi], bl[p][q], bl[p][q + 1]);
                    mma_bf16(acc[mi][ni], al[mi], bh[p][q], bh[p][q + 1]);
                }
        }
        __syncthreads();
    }

    const int r0c = lid >> 2, cc = (lid & 3) * 2;
    #pragma unroll
    for (int mi = 0; mi < 4; mi++) {
        #pragma unroll
        for (int ni = 0; ni < 4; ni++) {
            int row = bm * 128 + wm * 64 + mi * 16 + r0c;
            int col = bn * 128 + wn * 32 + ni * 8 + cc;
            #pragma unroll
            for (int half = 0; half < 2; half++) {
                int rr = row + half * 8;
                float2 v = make_float2(acc[mi][ni][half * 2], acc[mi][ni][half * 2 + 1]);
                if (mode == 0) {
                    *(float2*)(Cout + (size_t)rr * N + col) = v;
                } else if (mode == 1) {
                    int b = rr >> 11, t = rr & (T_ - 1);
                    int h = col >> 7, d = col & (HD - 1);
                    *(float2*)(Cout + ((((size_t)b * Hn + h) * T_ + t) * HD + d)) = v;
                } else {
                    int b = rr >> 11, t = rr & (T_ - 1);
                    int ht = col >> 7, d = col & (HD - 1);
                    float* dst = (ht < NKV) ? Cout : Cout2;
                    int h = ht & (NKV - 1);
                    *(float2*)(dst + ((((size_t)b * NKV + h) * T_ + t) * HD + d)) = v;
                }
            }
        }
    }
}

// ---------------------------------------------------------------------------
// f16 2-term GEMM (NT): C = A * (Whi + Wlo)^T, A single f16 matrix.
// Same tiling as gemm_mma; 3 smem matrices per stage.
// ---------------------------------------------------------------------------
#define G2MAT  10240
#define G2STG  30720
#define G2SM_TOTAL (2 * G2STG)

__global__ __launch_bounds__(256) void gemm_f16_2t(
    const __half* __restrict__ A,
    const __half* __restrict__ Whi, const __half* __restrict__ Wlo,
    float* __restrict__ Cout, int K, int N)
{
    extern __shared__ char smem[];
    const int tid = threadIdx.x;
    const int lid = tid & 31, wid = tid >> 5;
    const int wm = wid & 1, wn = wid >> 1;
    const int bm = blockIdx.y, bn = blockIdx.x;

    const __half* srcs[3];
    srcs[0] = A   + (size_t)bm * 128 * K;
    srcs[1] = Whi + (size_t)bn * 128 * K;
    srcs[2] = Wlo + (size_t)bn * 128 * K;

    float acc[4][4][4];
    #pragma unroll
    for (int mi = 0; mi < 4; mi++)
        #pragma unroll
        for (int ni = 0; ni < 4; ni++)
            #pragma unroll
            for (int e = 0; e < 4; e++) acc[mi][ni][e] = 0.f;

    const int nst = K >> 5;

    auto load_stage = [&](int s) {
        char* base = smem + (s & 1) * G2STG;
        const int k0 = s << 5;
        #pragma unroll
        for (int m = 0; m < 3; m++) {
            const __half* src = srcs[m] + k0;
            char* dst = base + m * G2MAT;
            #pragma unroll
            for (int j = 0; j < 2; j++) {
                int idx = j * 256 + tid;
                int row = idx >> 2;
                int c   = idx & 3;
                cp_async16(smem_u32(dst + row * 80 + c * 16),
                           src + (size_t)row * K + c * 8);
            }
        }
        cp_commit();
    };

    load_stage(0);

    for (int s = 0; s < nst; s++) {
        if (s + 1 < nst) { load_stage(s + 1); cp_wait<1>(); }
        else             { cp_wait<0>(); }
        __syncthreads();

        const uint32_t sb = smem_u32(smem + (s & 1) * G2STG);
        #pragma unroll
        for (int kk = 0; kk < 2; kk++) {
            uint32_t ah[4][4], bh[2][4], bl[2][4];
            const int arow  = wm * 64 + (lid & 15);
            const int akcol = kk * 16 + ((lid & 16) ? 8 : 0);
            #pragma unroll
            for (int mi = 0; mi < 4; mi++)
                ldsm4(ah[mi], sb + (arow + mi * 16) * 80 + akcol * 2);
            const int brow  = wn * 32 + (lid & 7) + ((lid & 16) ? 8 : 0);
            const int bkcol = kk * 16 + ((lid & 8) ? 8 : 0);
            #pragma unroll
            for (int p = 0; p < 2; p++) {
                uint32_t addr = sb + G2MAT + (brow + p * 16) * 80 + bkcol * 2;
                ldsm4(bh[p], addr);
                ldsm4(bl[p], addr + G2MAT);
            }
            #pragma unroll
            for (int mi = 0; mi < 4; mi++)
                #pragma unroll
                for (int ni = 0; ni < 4; ni++) {
                    const int p = ni >> 1, q = (ni & 1) * 2;
                    mma_f16(acc[mi][ni], ah[mi], bh[p][q], bh[p][q + 1]);
                    mma_f16(acc[mi][ni], ah[mi], bl[p][q], bl[p][q + 1]);
                }
        }
        __syncthreads();
    }

    const int r0c = lid >> 2, cc = (lid & 3) * 2;
    #pragma unroll
    for (int mi = 0; mi < 4; mi++) {
        #pragma unroll
        for (int ni = 0; ni < 4; ni++) {
            int row = bm * 128 + wm * 64 + mi * 16 + r0c;
            int col = bn * 128 + wn * 32 + ni * 8 + cc;
            #pragma unroll
            for (int half = 0; half < 2; half++) {
                int rr = row + half * 8;
                *(float2*)(Cout + (size_t)rr * N + col) =
                    make_float2(acc[mi][ni][half * 2], acc[mi][ni][half * 2 + 1]);
            }
        }
    }
}

// ---------------------------------------------------------------------------
// Tensor-core causal flash attention (R7 core; epilogue writes single f16 y).
// ---------------------------------------------------------------------------
#define AROWB  272
#define AQMAT  34816
#define AKVMAT 17408
#define AKVST  (4 * AKVMAT)
#define ASM_TOTAL (2 * AQMAT + 2 * AKVST)

__global__ __launch_bounds__(256, 1) void attn_mma(
    const __nv_bfloat16* __restrict__ Qhi, const __nv_bfloat16* __restrict__ Qlo,
    const __nv_bfloat16* __restrict__ Khi, const __nv_bfloat16* __restrict__ Klo,
    const __half* __restrict__ Vhi, const __half* __restrict__ Vlo,
    __half* __restrict__ Yh)
{
    extern __shared__ char smem[];
    const int tid = threadIdx.x;
    const int lid = tid & 31, wid = tid >> 5;
    const int qt = (T_ / 128 - 1) - blockIdx.x;
    const int bh = blockIdx.y;
    const int b  = bh >> 4, h = bh & 15;
    const int kvh = h >> 2;

    const size_t qg = ((size_t)(b * NH + h) * T_ + qt * 128) * HD;
    const size_t kg = (size_t)(b * NKV + kvh) * T_ * HD;

    const uint32_t sQhi = smem_u32(smem);
    const uint32_t sQlo = sQhi + AQMAT;
    const uint32_t sKV0 = sQlo + AQMAT;

    {
        #pragma unroll
        for (int i = 0; i < 16; i++) {
            int idx = i * 256 + tid;
            int mat = idx >> 11;
            int rem = idx & 2047;
            int row = rem >> 4, c = rem & 15;
            const __nv_bfloat16* src = (mat ? Qlo : Qhi) + qg + (size_t)row * HD + c * 8;
            cp_async16((mat ? sQlo : sQhi) + row * AROWB + c * 16, src);
        }
    }
    const void* kvsrc[4] = {Khi, Klo, Vhi, Vlo};
    auto load_kv = [&](int kt, int st) {
        uint32_t sb = sKV0 + st * AKVST;
        const size_t base = kg + (size_t)kt * 64 * HD;
        #pragma unroll
        for (int i = 0; i < 16; i++) {
            int idx = i * 256 + tid;
            int mat = idx >> 10;
            int rem = idx & 1023;
            int row = rem >> 4, c = rem & 15;
            cp_async16(sb + mat * AKVMAT + row * AROWB + c * 16,
                       (const char*)kvsrc[mat] + 2 * (base + (size_t)row * HD + c * 8));
        }
        cp_commit();
    };
    load_kv(0, 0);

    float oacc[16][4];
    #pragma unroll
    for (int jn = 0; jn < 16; jn++)
        #pragma unroll
        for (int e = 0; e < 4; e++) oacc[jn][e] = 0.f;
    float mrow[2] = {-1e30f, -1e30f};
    float lrow[2] = {0.f, 0.f};

    const int nkt = 2 * qt + 2;

    for (int kt = 0; kt < nkt; kt++) {
        if (kt + 1 < nkt) { load_kv(kt + 1, (kt + 1) & 1); cp_wait<1>(); }
        else              { cp_wait<0>(); }
        __syncthreads();

        const uint32_t sb  = sKV0 + (kt & 1) * AKVST;
        const uint32_t sKh = sb, sKl = sb + AKVMAT;
        const uint32_t sVh = sb + 2 * AKVMAT, sVl = sb + 3 * AKVMAT;

        float sacc[8][4];
        #pragma unroll
        for (int j = 0; j < 8; j++)
            #pragma unroll
            for (int e = 0; e < 4; e++) sacc[j][e] = 0.f;

        #pragma unroll
        for (int kk = 0; kk < 8; kk++) {
            uint32_t ah[4], al[4];
            const int arow  = wid * 16 + (lid & 15);
            const int akcol = kk * 16 + ((lid & 16) ? 8 : 0);
            uint32_t qaddr = sQhi + arow * AROWB + akcol * 2;
            ldsm4(ah, qaddr);
            ldsm4(al, qaddr + AQMAT);
            #pragma unroll
            for (int np = 0; np < 4; np++) {
                uint32_t bh4[4], bl4[4];
                const int brow  = np * 16 + (lid & 7) + ((lid & 16) ? 8 : 0);
                const int bkcol = kk * 16 + ((lid & 8) ? 8 : 0);
                uint32_t kaddr = brow * AROWB + bkcol * 2;
                ldsm4(bh4, sKh + kaddr);
                ldsm4(bl4, sKl + kaddr);
                #pragma unroll
                for (int jj = 0; jj < 2; jj++) {
                    const int j = 2 * np + jj, q = jj * 2;
                    mma_bf16(sacc[j], ah, bh4[q], bh4[q + 1]);
                    mma_bf16(sacc[j], ah, bl4[q], bl4[q + 1]);
                    mma_bf16(sacc[j], al, bh4[q], bh4[q + 1]);
                }
            }
        }

        const int kv0 = kt * 64;
        if (kv0 + 63 > qt * 128) {
            const int rbase = qt * 128 + wid * 16 + (lid >> 2);
            #pragma unroll
            for (int j = 0; j < 8; j++)
                #pragma unroll
                for (int e = 0; e < 4; e++) {
                    int col = kv0 + j * 8 + 2 * (lid & 3) + (e & 1);
                    int row = rbase + (e >> 1) * 8;
                    if (col > row) sacc[j][e] = -1e30f;
                }
        }

        float mnew[2];
        #pragma unroll
        for (int h2 = 0; h2 < 2; h2++) {
            float tm = -1e30f;
            #pragma unroll
            for (int j = 0; j < 8; j++)
                tm = fmaxf(tm, fmaxf(sacc[j][h2 * 2], sacc[j][h2 * 2 + 1]));
            tm = fmaxf(tm, __shfl_xor_sync(0xffffffffu, tm, 1));
            tm = fmaxf(tm, __shfl_xor_sync(0xffffffffu, tm, 2));
            mnew[h2] = fmaxf(mrow[h2], tm);
        }

        uint32_t pfrag[8][2];
        float sum0 = 0.f, sum1 = 0.f;
        #pragma unroll
        for (int j = 0; j < 8; j++) {
            float e0, e1;
            pfrag[j][0] = ex2_pack(sacc[j][0] - mnew[0], sacc[j][1] - mnew[0], e0, e1);
            sum0 += e0 + e1;
            pfrag[j][1] = ex2_pack(sacc[j][2] - mnew[1], sacc[j][3] - mnew[1], e0, e1);
            sum1 += e0 + e1;
        }
        sum0 += __shfl_xor_sync(0xffffffffu, sum0, 1);
        sum0 += __shfl_xor_sync(0xffffffffu, sum0, 2);
        sum1 += __shfl_xor_sync(0xffffffffu, sum1, 1);
        sum1 += __shfl_xor_sync(0xffffffffu, sum1, 2);

        #pragma unroll
        for (int h2 = 0; h2 < 2; h2++) {
            float corr = ex2f(mrow[h2] - mnew[h2]);
            lrow[h2] = lrow[h2] * corr + (h2 ? sum1 : sum0);
            mrow[h2] = mnew[h2];
            #pragma unroll
            for (int jn = 0; jn < 16; jn++) {
                oacc[jn][h2 * 2]     *= corr;
                oacc[jn][h2 * 2 + 1] *= corr;
            }
        }

        #pragma unroll
        for (int ks = 0; ks < 4; ks++) {
            uint32_t pf[4];
            pf[0] = pfrag[2 * ks][0];
            pf[1] = pfrag[2 * ks][1];
            pf[2] = pfrag[2 * ks + 1][0];
            pf[3] = pfrag[2 * ks + 1][1];
            #pragma unroll
            for (int np = 0; np < 8; np++) {
                uint32_t vh4[4], vl4[4];
                const int vrow = ks * 16 + (lid & 7) + 8 * ((lid >> 3) & 1);
                const int vcol = np * 16 + 8 * (lid >> 4);
                uint32_t vaddr = vrow * AROWB + vcol * 2;
                ldsm4t(vh4, sVh + vaddr);
                ldsm4t(vl4, sVl + vaddr);
                #pragma unroll
                for (int jj = 0; jj < 2; jj++) {
                    const int jn = 2 * np + jj, q = jj * 2;
                    mma_f16(oacc[jn], pf, vh4[q], vh4[q + 1]);
                    mma_f16(oacc[jn], pf, vl4[q], vl4[q + 1]);
                }
            }
        }
        __syncthreads();
    }

    // ---- epilogue: normalize, write single f16 y[b, t, h*128 + d]
    #pragma unroll
    for (int h2 = 0; h2 < 2; h2++) {
        float inv = 1.f / lrow[h2];
        int row_t = qt * 128 + wid * 16 + (lid >> 2) + 8 * h2;
        size_t base = ((size_t)b * T_ + row_t) * C_ + h * HD;
        #pragma unroll
        for (int jn = 0; jn < 16; jn++) {
            int col = jn * 8 + 2 * (lid & 3);
            __half2 hv = __floats2half2_rn(oacc[jn][h2 * 2] * inv,
                                           oacc[jn][h2 * 2 + 1] * inv);
            *(__half2*)(Yh + base + col) = hv;
        }
    }
}

// ---------------------------------------------------------------------------
extern "C" void kernel_launch(void* const* d_in, const int* in_sizes, int n_in,
                              void* d_out, int out_size)
{
    const float* x    = (const float*)d_in[0];
    const float* fcos = (const float*)d_in[1];
    const float* fsin = (const float*)d_in[2];
    const float* wq   = (const float*)d_in[3];
    const float* wk   = (const float*)d_in[4];
    const float* wv   = (const float*)d_in[5];
    const float* wo   = (const float*)d_in[6];
    float* out = (float*)d_out;

    float *qp, *kp, *vp;
    cudaGetSymbolAddress((void**)&qp, g_q);
    cudaGetSymbolAddress((void**)&kp, g_k);
    cudaGetSymbolAddress((void**)&vp, g_v);

    __nv_bfloat16 *xhi, *xlo, *qhi, *qlo, *khi, *klo, *wqhi, *wqlo, *wkvhi, *wkvlo;
    __half *vhi, *vlo, *yh, *wohi, *wolo;
    cudaGetSymbolAddress((void**)&xhi, g_xhi);     cudaGetSymbolAddress((void**)&xlo, g_xlo);
    cudaGetSymbolAddress((void**)&yh, g_yh);
    cudaGetSymbolAddress((void**)&qhi, g_qhi);     cudaGetSymbolAddress((void**)&qlo, g_qlo);
    cudaGetSymbolAddress((void**)&khi, g_khi);     cudaGetSymbolAddress((void**)&klo, g_klo);
    cudaGetSymbolAddress((void**)&vhi, g_vhi);     cudaGetSymbolAddress((void**)&vlo, g_vlo);
    cudaGetSymbolAddress((void**)&wqhi, g_wqhi);   cudaGetSymbolAddress((void**)&wqlo, g_wqlo);
    cudaGetSymbolAddress((void**)&wkvhi, g_wkvhi); cudaGetSymbolAddress((void**)&wkvlo, g_wkvlo);
    cudaGetSymbolAddress((void**)&wohi, g_wohi_h); cudaGetSymbolAddress((void**)&wolo, g_wolo_h);

    const int M = B_ * T_;    // 4096
    const int NW = NKV * HD;  // 512

    // fp32 -> hi/lo splits of inputs/weights
    {
        int n4;
        n4 = (M * C_) / 4;
        cvt_hilo<<<(n4 + 255) / 256, 256>>>((const float4*)x, (__nv_bfloat162*)xhi, (__nv_bfloat162*)xlo, n4);
        n4 = (C_ * C_) / 4;
        cvt_hilo<<<(n4 + 255) / 256, 256>>>((const float4*)wq, (__nv_bfloat162*)wqhi, (__nv_bfloat162*)wqlo, n4);
        cvt_hilo_h<<<(n4 + 255) / 256, 256>>>((const float4*)wo, (__half2*)wohi, (__half2*)wolo, n4);
        n4 = (NW * C_) / 4;
        cvt_hilo<<<(n4 + 255) / 256, 256>>>((const float4*)wk, (__nv_bfloat162*)wkvhi, (__nv_bfloat162*)wkvlo, n4);
        cvt_hilo<<<(n4 + 255) / 256, 256>>>((const float4*)wv,
            (__nv_bfloat162*)(wkvhi + (size_t)NW * C_), (__nv_bfloat162*)(wkvlo + (size_t)NW * C_), n4);
    }

    cudaFuncSetAttribute(gemm_mma, cudaFuncAttributeMaxDynamicSharedMemorySize, GSM_TOTAL);
    cudaFuncSetAttribute(gemm_f16_2t, cudaFuncAttributeMaxDynamicSharedMemorySize, G2SM_TOTAL);

    // Q projection + merged KV projection (scatter into [B, H, T, D])
    gemm_mma<<<dim3(C_ / 128, M / 128), 256, GSM_TOTAL>>>(xhi, xlo, wqhi, wqlo, qp, nullptr, C_, C_, 1, NH);
    gemm_mma<<<dim3((2 * NW) / 128, M / 128), 256, GSM_TOTAL>>>(xhi, xlo, wkvhi, wkvlo, kp, vp, C_, 2 * NW, 2, NKV);

    // RoPE -> bf16 hi/lo (Q pre-scaled by SCALE*log2e for base-2 softmax)
    rope_hilo<<<(B_ * NH  * T_ * 64) / 256, 256>>>(qp, fcos, fsin,
        (__nv_bfloat162*)qhi, (__nv_bfloat162*)qlo, QSCL);
    rope_hilo<<<(B_ * NKV * T_ * 64) / 256, 256>>>(kp, fcos, fsin,
        (__nv_bfloat162*)khi, (__nv_bfloat162*)klo, 1.0f);
    // V -> f16 hi/lo
    {
        int n4 = (B_ * NKV * T_ * HD) / 4;
        cvt_hilo_h<<<(n4 + 255) / 256, 256>>>((const float4*)vp, (__half2*)vhi, (__half2*)vlo, n4);
    }

    // Tensor-core flash attention -> f16 y
    cudaFuncSetAttribute(attn_mma, cudaFuncAttributeMaxDynamicSharedMemorySize, ASM_TOTAL);
    attn_mma<<<dim3(T_ / 128, B_ * NH), 256, ASM_TOTAL>>>(qhi, qlo, khi, klo, vhi, vlo, yh);

    // Output projection: f16 2-term
    gemm_f16_2t<<<dim3(C_ / 128, M / 128), 256, G2SM_TOTAL>>>(yh, wohi, wolo, out, C_, C_);
}

// round 9
// speedup vs baseline: 1.6209x; 1.3189x over previous
#include <cuda_runtime.h>
#include <cuda_bf16.h>
#include <cuda_fp16.h>
#include <math.h>
#include <stdint.h>

#define B_   2
#define T_   2048
#define C_   2048
#define NH   16
#define NKV  4
#define HD   128
#define QSCL  0.1275495818259719f            // (1/sqrt(128)) * log2(e)

// ---------------------------------------------------------------------------
// Scratch (device globals; no allocation allowed)
// ---------------------------------------------------------------------------
__device__ __half g_xs [(size_t)B_ * T_ * C_];                // f16 x
__device__ __half g_wh [(size_t)3 * C_ / 2 * C_];             // [wq;wk;wv] hi (3072 x 2048)
__device__ __half g_wl [(size_t)3 * C_ / 2 * C_];             //              lo
__device__ __half g_qh [(size_t)B_ * NH  * T_ * HD];          // Q f16 (QSCL-scaled, roped)
__device__ __half g_khi[(size_t)B_ * NKV * T_ * HD];          // K f16 hi (roped)
__device__ __half g_klo[(size_t)B_ * NKV * T_ * HD];
__device__ __half g_vhi[(size_t)B_ * NKV * T_ * HD];
__device__ __half g_vlo[(size_t)B_ * NKV * T_ * HD];
__device__ __half g_yh [(size_t)B_ * T_ * C_];                // attn out f16
__device__ __half g_woh[(size_t)C_ * C_];
__device__ __half g_wol[(size_t)C_ * C_];

// ---------------------------------------------------------------------------
// PTX helpers — arch-agnostic (sm_80+)
// ---------------------------------------------------------------------------
__device__ __forceinline__ uint32_t smem_u32(const void* p) {
    uint32_t a;
    asm("{ .reg .u64 t; cvta.to.shared.u64 t, %1; cvt.u32.u64 %0, t; }"
        : "=r"(a) : "l"(p));
    return a;
}
__device__ __forceinline__ void cp_async16(uint32_t saddr, const void* gaddr) {
    asm volatile("cp.async.cg.shared.global [%0], [%1], 16;"
                 :: "r"(saddr), "l"(gaddr));
}
__device__ __forceinline__ void cp_commit() { asm volatile("cp.async.commit_group;"); }
template <int N> __device__ __forceinline__ void cp_wait() {
    asm volatile("cp.async.wait_group %0;" :: "n"(N));
}
__device__ __forceinline__ void ldsm4(uint32_t* r, uint32_t addr) {
    asm volatile("ldmatrix.sync.aligned.m8n8.x4.shared.b16 {%0,%1,%2,%3}, [%4];"
                 : "=r"(r[0]), "=r"(r[1]), "=r"(r[2]), "=r"(r[3]) : "r"(addr));
}
__device__ __forceinline__ void ldsm4t(uint32_t* r, uint32_t addr) {
    asm volatile("ldmatrix.sync.aligned.m8n8.x4.trans.shared.b16 {%0,%1,%2,%3}, [%4];"
                 : "=r"(r[0]), "=r"(r[1]), "=r"(r[2]), "=r"(r[3]) : "r"(addr));
}
__device__ __forceinline__ void mma_f16(float* c, const uint32_t* a,
                                        uint32_t b0, uint32_t b1) {
    asm volatile(
        "mma.sync.aligned.m16n8k16.row.col.f32.f16.f16.f32 "
        "{%0,%1,%2,%3}, {%4,%5,%6,%7}, {%8,%9}, {%0,%1,%2,%3};"
        : "+f"(c[0]), "+f"(c[1]), "+f"(c[2]), "+f"(c[3])
        : "r"(a[0]), "r"(a[1]), "r"(a[2]), "r"(a[3]), "r"(b0), "r"(b1));
}
__device__ __forceinline__ float ex2f(float x) {
    float y; asm("ex2.approx.f32 %0, %1;" : "=f"(y) : "f"(x)); return y;
}
__device__ __forceinline__ uint32_t ex2_pack(float s0, float s1,
                                             float& e0, float& e1) {
    uint32_t t;
    asm("{\n\t.reg .b16 l, h;\n\t"
        "cvt.rn.f16x2.f32 %0, %4, %3;\n\t"
        "ex2.approx.f16x2 %0, %0;\n\t"
        "mov.b32 {l, h}, %0;\n\t"
        "cvt.f32.f16 %1, l;\n\t"
        "cvt.f32.f16 %2, h;\n\t}"
        : "=r"(t), "=f"(e0), "=f"(e1) : "f"(s0), "f"(s1));
    return t;
}
__device__ __forceinline__ void pack_hilo_h(float x, float y, uint32_t& hi, uint32_t& lo) {
    __half hx = __float2half(x), hy = __float2half(y);
    __half lx = __float2half(x - __half2float(hx));
    __half ly = __float2half(y - __half2float(hy));
    __half2 h2(hx, hy), l2(lx, ly);
    hi = *reinterpret_cast<uint32_t*>(&h2);
    lo = *reinterpret_cast<uint32_t*>(&l2);
}

// ---------------------------------------------------------------------------
// fp32 -> f16 single
// ---------------------------------------------------------------------------
__global__ void cvt_f16(const float4* __restrict__ in, __half2* __restrict__ o2, int n4)
{
    int i = blockIdx.x * blockDim.x + threadIdx.x;
    if (i >= n4) return;
    float4 v = in[i];
    o2[2 * i + 0] = __floats2half2_rn(v.x, v.y);
    o2[2 * i + 1] = __floats2half2_rn(v.z, v.w);
}

// fp32 -> f16 hi/lo split
__global__ void cvt_hilo_h(const float4* __restrict__ in,
                           __half2* __restrict__ hi2,
                           __half2* __restrict__ lo2, int n4)
{
    int i = blockIdx.x * blockDim.x + threadIdx.x;
    if (i >= n4) return;
    float4 v = in[i];
    uint32_t h0, l0, h1, l1;
    pack_hilo_h(v.x, v.y, h0, l0);
    pack_hilo_h(v.z, v.w, h1, l1);
    hi2[2 * i + 0] = *reinterpret_cast<__half2*>(&h0);
    hi2[2 * i + 1] = *reinterpret_cast<__half2*>(&h1);
    lo2[2 * i + 0] = *reinterpret_cast<__half2*>(&l0);
    lo2[2 * i + 1] = *reinterpret_cast<__half2*>(&l1);
}

// ---------------------------------------------------------------------------
// f16 2-term GEMM (NT): acc = A * (Whi + Wlo)^T, fp32 accum.
// 128x128 CTA tile, BK=32, 2-stage cp.async, 256 threads (2x4 warps).
// mode 0: fp32 row-major out.
// mode 1: fused QKV epilogue — col<2048: RoPE+QSCL -> Qh f16;
//         col in [2048,2560): RoPE -> Khi/Klo; col >= 2560: Vhi/Vlo.
// ---------------------------------------------------------------------------
#define G2MAT  10240
#define G2STG  30720
#define G2SM_TOTAL (2 * G2STG)

__global__ __launch_bounds__(256) void gemm_f16(
    const __half* __restrict__ A,
    const __half* __restrict__ Whi, const __half* __restrict__ Wlo,
    float* __restrict__ Cout,
    __half* __restrict__ Qh, __half* __restrict__ Khi, __half* __restrict__ Klo,
    __half* __restrict__ Vhi, __half* __restrict__ Vlo,
    const float* __restrict__ fcos, const float* __restrict__ fsin,
    int K, int N, int mode)
{
    extern __shared__ char smem[];
    const int tid = threadIdx.x;
    const int lid = tid & 31, wid = tid >> 5;
    const int wm = wid & 1, wn = wid >> 1;
    const int bm = blockIdx.y, bn = blockIdx.x;

    const __half* srcs[3];
    srcs[0] = A   + (size_t)bm * 128 * K;
    srcs[1] = Whi + (size_t)bn * 128 * K;
    srcs[2] = Wlo + (size_t)bn * 128 * K;

    float acc[4][4][4];
    #pragma unroll
    for (int mi = 0; mi < 4; mi++)
        #pragma unroll
        for (int ni = 0; ni < 4; ni++)
            #pragma unroll
            for (int e = 0; e < 4; e++) acc[mi][ni][e] = 0.f;

    const int nst = K >> 5;

    auto load_stage = [&](int s) {
        char* base = smem + (s & 1) * G2STG;
        const int k0 = s << 5;
        #pragma unroll
        for (int m = 0; m < 3; m++) {
            const __half* src = srcs[m] + k0;
            char* dst = base + m * G2MAT;
            #pragma unroll
            for (int j = 0; j < 2; j++) {
                int idx = j * 256 + tid;
                int row = idx >> 2;
                int c   = idx & 3;
                cp_async16(smem_u32(dst + row * 80 + c * 16),
                           src + (size_t)row * K + c * 8);
            }
        }
        cp_commit();
    };

    load_stage(0);

    for (int s = 0; s < nst; s++) {
        if (s + 1 < nst) { load_stage(s + 1); cp_wait<1>(); }
        else             { cp_wait<0>(); }
        __syncthreads();

        const uint32_t sb = smem_u32(smem + (s & 1) * G2STG);
        #pragma unroll
        for (int kk = 0; kk < 2; kk++) {
            uint32_t ah[4][4], bh[2][4], bl[2][4];
            const int arow  = wm * 64 + (lid & 15);
            const int akcol = kk * 16 + ((lid & 16) ? 8 : 0);
            #pragma unroll
            for (int mi = 0; mi < 4; mi++)
                ldsm4(ah[mi], sb + (arow + mi * 16) * 80 + akcol * 2);
            const int brow  = wn * 32 + (lid & 7) + ((lid & 16) ? 8 : 0);
            const int bkcol = kk * 16 + ((lid & 8) ? 8 : 0);
            #pragma unroll
            for (int p = 0; p < 2; p++) {
                uint32_t addr = sb + G2MAT + (brow + p * 16) * 80 + bkcol * 2;
                ldsm4(bh[p], addr);
                ldsm4(bl[p], addr + G2MAT);
            }
            #pragma unroll
            for (int mi = 0; mi < 4; mi++)
                #pragma unroll
                for (int ni = 0; ni < 4; ni++) {
                    const int p = ni >> 1, q = (ni & 1) * 2;
                    mma_f16(acc[mi][ni], ah[mi], bh[p][q], bh[p][q + 1]);
                    mma_f16(acc[mi][ni], ah[mi], bl[p][q], bl[p][q + 1]);
                }
        }
        __syncthreads();
    }

    const int r0c = lid >> 2, cc = (lid & 3) * 2;
    #pragma unroll
    for (int mi = 0; mi < 4; mi++) {
        #pragma unroll
        for (int ni = 0; ni < 4; ni++) {
            int row = bm * 128 + wm * 64 + mi * 16 + r0c;
            int col = bn * 128 + wn * 32 + ni * 8 + cc;
            #pragma unroll
            for (int half = 0; half < 2; half++) {
                int rr = row + half * 8;
                float v0 = acc[mi][ni][half * 2], v1 = acc[mi][ni][half * 2 + 1];
                if (mode == 0) {
                    *(float2*)(Cout + (size_t)rr * N + col) = make_float2(v0, v1);
                } else {
                    const int b = rr >> 11, t = rr & (T_ - 1);
                    const int ht = col >> 7, d = col & (HD - 1);
                    if (ht < NH) {          // Q: RoPE + QSCL, f16 single
                        float c = fcos[t * 64 + (d >> 1)];
                        float sn = fsin[t * 64 + (d >> 1)];
                        float r0 = (v0 * c - v1 * sn) * QSCL;
                        float r1 = (v0 * sn + v1 * c) * QSCL;
                        *(__half2*)(Qh + ((((size_t)b * NH + ht) * T_ + t) * HD + d)) =
                            __floats2half2_rn(r0, r1);
                    } else if (ht < NH + NKV) {   // K: RoPE, f16 hi/lo
                        int h = ht - NH;
                        float c = fcos[t * 64 + (d >> 1)];
                        float sn = fsin[t * 64 + (d >> 1)];
                        float r0 = v0 * c - v1 * sn;
                        float r1 = v0 * sn + v1 * c;
                        uint32_t hi, lo;
                        pack_hilo_h(r0, r1, hi, lo);
                        size_t off = (((size_t)b * NKV + h) * T_ + t) * HD + d;
                        *(uint32_t*)(Khi + off) = hi;
                        *(uint32_t*)(Klo + off) = lo;
                    } else {                      // V: f16 hi/lo
                        int h = ht - NH - NKV;
                        uint32_t hi, lo;
                        pack_hilo_h(v0, v1, hi, lo);
                        size_t off = (((size_t)b * NKV + h) * T_ + t) * HD + d;
                        *(uint32_t*)(Vhi + off) = hi;
                        *(uint32_t*)(Vlo + off) = lo;
                    }
                }
            }
        }
    }
}

// ---------------------------------------------------------------------------
// Tensor-core causal flash attention — all f16.
// S = Q(K_hi+K_lo)^T 2-term; softmax via ex2.f16x2; PV 2-term.
// ---------------------------------------------------------------------------
#define AROWB  272
#define AQMAT  34816                 // 128 * 272
#define AKVMAT 17408                 // 64 * 272
#define AKVST  (4 * AKVMAT)
#define ASM_TOTAL (AQMAT + 2 * AKVST)   // 174080

__global__ __launch_bounds__(256, 1) void attn_mma(
    const __half* __restrict__ Qh,
    const __half* __restrict__ Khi, const __half* __restrict__ Klo,
    const __half* __restrict__ Vhi, const __half* __restrict__ Vlo,
    __half* __restrict__ Yh)
{
    extern __shared__ char smem[];
    const int tid = threadIdx.x;
    const int lid = tid & 31, wid = tid >> 5;
    const int qt = (T_ / 128 - 1) - blockIdx.x;
    const int bh = blockIdx.y;
    const int b  = bh >> 4, h = bh & 15;
    const int kvh = h >> 2;

    const size_t qg = ((size_t)(b * NH + h) * T_ + qt * 128) * HD;
    const size_t kg = (size_t)(b * NKV + kvh) * T_ * HD;

    const uint32_t sQ   = smem_u32(smem);
    const uint32_t sKV0 = sQ + AQMAT;

    {   // Q: 2048 16B-chunks
        #pragma unroll
        for (int i = 0; i < 8; i++) {
            int idx = i * 256 + tid;
            int row = idx >> 4, c = idx & 15;
            cp_async16(sQ + row * AROWB + c * 16, Qh + qg + (size_t)row * HD + c * 8);
        }
    }
    const __half* kvsrc[4] = {Khi, Klo, Vhi, Vlo};
    auto load_kv = [&](int kt, int st) {
        uint32_t sb = sKV0 + st * AKVST;
        const size_t base = kg + (size_t)kt * 64 * HD;
        #pragma unroll
        for (int i = 0; i < 16; i++) {
            int idx = i * 256 + tid;
            int mat = idx >> 10;
            int rem = idx & 1023;
            int row = rem >> 4, c = rem & 15;
            cp_async16(sb + mat * AKVMAT + row * AROWB + c * 16,
                       kvsrc[mat] + base + (size_t)row * HD + c * 8);
        }
        cp_commit();
    };
    load_kv(0, 0);

    float oacc[16][4];
    #pragma unroll
    for (int jn = 0; jn < 16; jn++)
        #pragma unroll
        for (int e = 0; e < 4; e++) oacc[jn][e] = 0.f;
    float mrow[2] = {-1e30f, -1e30f};
    float lrow[2] = {0.f, 0.f};

    const int nkt = 2 * qt + 2;

    for (int kt = 0; kt < nkt; kt++) {
        if (kt + 1 < nkt) { load_kv(kt + 1, (kt + 1) & 1); cp_wait<1>(); }
        else              { cp_wait<0>(); }
        __syncthreads();

        const uint32_t sb  = sKV0 + (kt & 1) * AKVST;
        const uint32_t sKh = sb, sKl = sb + AKVMAT;
        const uint32_t sVh = sb + 2 * AKVMAT, sVl = sb + 3 * AKVMAT;

        // ---- S = Q K^T (f16 2-term)
        float sacc[8][4];
        #pragma unroll
        for (int j = 0; j < 8; j++)
            #pragma unroll
            for (int e = 0; e < 4; e++) sacc[j][e] = 0.f;

        #pragma unroll
        for (int kk = 0; kk < 8; kk++) {
            uint32_t ah[4];
            const int arow  = wid * 16 + (lid & 15);
            const int akcol = kk * 16 + ((lid & 16) ? 8 : 0);
            ldsm4(ah, sQ + arow * AROWB + akcol * 2);
            #pragma unroll
            for (int np = 0; np < 4; np++) {
                uint32_t bh4[4], bl4[4];
                const int brow  = np * 16 + (lid & 7) + ((lid & 16) ? 8 : 0);
                const int bkcol = kk * 16 + ((lid & 8) ? 8 : 0);
                uint32_t kaddr = brow * AROWB + bkcol * 2;
                ldsm4(bh4, sKh + kaddr);
                ldsm4(bl4, sKl + kaddr);
                #pragma unroll
                for (int jj = 0; jj < 2; jj++) {
                    const int j = 2 * np + jj, q = jj * 2;
                    mma_f16(sacc[j], ah, bh4[q], bh4[q + 1]);
                    mma_f16(sacc[j], ah, bl4[q], bl4[q + 1]);
                }
            }
        }

        // ---- causal mask (diagonal tiles only)
        const int kv0 = kt * 64;
        if (kv0 + 63 > qt * 128) {
            const int rbase = qt * 128 + wid * 16 + (lid >> 2);
            #pragma unroll
            for (int j = 0; j < 8; j++)
                #pragma unroll
                for (int e = 0; e < 4; e++) {
                    int col = kv0 + j * 8 + 2 * (lid & 3) + (e & 1);
                    int row = rbase + (e >> 1) * 8;
                    if (col > row) sacc[j][e] = -1e30f;
                }
        }

        // ---- online softmax (base-2, f16x2 exp -> P fragments)
        float mnew[2];
        #pragma unroll
        for (int h2 = 0; h2 < 2; h2++) {
            float tm = -1e30f;
            #pragma unroll
            for (int j = 0; j < 8; j++)
                tm = fmaxf(tm, fmaxf(sacc[j][h2 * 2], sacc[j][h2 * 2 + 1]));
            tm = fmaxf(tm, __shfl_xor_sync(0xffffffffu, tm, 1));
            tm = fmaxf(tm, __shfl_xor_sync(0xffffffffu, tm, 2));
            mnew[h2] = fmaxf(mrow[h2], tm);
        }

        uint32_t pfrag[8][2];
        float sum0 = 0.f, sum1 = 0.f;
        #pragma unroll
        for (int j = 0; j < 8; j++) {
            float e0, e1;
            pfrag[j][0] = ex2_pack(sacc[j][0] - mnew[0], sacc[j][1] - mnew[0], e0, e1);
            sum0 += e0 + e1;
            pfrag[j][1] = ex2_pack(sacc[j][2] - mnew[1], sacc[j][3] - mnew[1], e0, e1);
            sum1 += e0 + e1;
        }
        sum0 += __shfl_xor_sync(0xffffffffu, sum0, 1);
        sum0 += __shfl_xor_sync(0xffffffffu, sum0, 2);
        sum1 += __shfl_xor_sync(0xffffffffu, sum1, 1);
        sum1 += __shfl_xor_sync(0xffffffffu, sum1, 2);

        #pragma unroll
        for (int h2 = 0; h2 < 2; h2++) {
            float corr = ex2f(mrow[h2] - mnew[h2]);
            lrow[h2] = lrow[h2] * corr + (h2 ? sum1 : sum0);
            mrow[h2] = mnew[h2];
            #pragma unroll
            for (int jn = 0; jn < 16; jn++) {
                oacc[jn][h2 * 2]     *= corr;
                oacc[jn][h2 * 2 + 1] *= corr;
            }
        }

        // ---- O += P V (f16, 2-term)
        #pragma unroll
        for (int ks = 0; ks < 4; ks++) {
            uint32_t pf[4];
            pf[0] = pfrag[2 * ks][0];
            pf[1] = pfrag[2 * ks][1];
            pf[2] = pfrag[2 * ks + 1][0];
            pf[3] = pfrag[2 * ks + 1][1];
            #pragma unroll
            for (int np = 0; np < 8; np++) {
                uint32_t vh4[4], vl4[4];
                const int vrow = ks * 16 + (lid & 7) + 8 * ((lid >> 3) & 1);
                const int vcol = np * 16 + 8 * (lid >> 4);
                uint32_t vaddr = vrow * AROWB + vcol * 2;
                ldsm4t(vh4, sVh + vaddr);
                ldsm4t(vl4, sVl + vaddr);
                #pragma unroll
                for (int jj = 0; jj < 2; jj++) {
                    const int jn = 2 * np + jj, q = jj * 2;
                    mma_f16(oacc[jn], pf, vh4[q], vh4[q + 1]);
                    mma_f16(oacc[jn], pf, vl4[q], vl4[q + 1]);
                }
            }
        }
        __syncthreads();
    }

    // ---- epilogue: normalize, write f16 y[b, t, h*128 + d]
    #pragma unroll
    for (int h2 = 0; h2 < 2; h2++) {
        float inv = 1.f / lrow[h2];
        int row_t = qt * 128 + wid * 16 + (lid >> 2) + 8 * h2;
        size_t base = ((size_t)b * T_ + row_t) * C_ + h * HD;
        #pragma unroll
        for (int jn = 0; jn < 16; jn++) {
            int col = jn * 8 + 2 * (lid & 3);
            *(__half2*)(Yh + base + col) =
                __floats2half2_rn(oacc[jn][h2 * 2] * inv, oacc[jn][h2 * 2 + 1] * inv);
        }
    }
}

// ---------------------------------------------------------------------------
extern "C" void kernel_launch(void* const* d_in, const int* in_sizes, int n_in,
                              void* d_out, int out_size)
{
    const float* x    = (const float*)d_in[0];
    const float* fcos = (const float*)d_in[1];
    const float* fsin = (const float*)d_in[2];
    const float* wq   = (const float*)d_in[3];
    const float* wk   = (const float*)d_in[4];
    const float* wv   = (const float*)d_in[5];
    const float* wo   = (const float*)d_in[6];
    float* out = (float*)d_out;

    __half *xs, *wh, *wl, *qh, *khi, *klo, *vhi, *vlo, *yh, *woh, *wol;
    cudaGetSymbolAddress((void**)&xs,  g_xs);
    cudaGetSymbolAddress((void**)&wh,  g_wh);
    cudaGetSymbolAddress((void**)&wl,  g_wl);
    cudaGetSymbolAddress((void**)&qh,  g_qh);
    cudaGetSymbolAddress((void**)&khi, g_khi);
    cudaGetSymbolAddress((void**)&klo, g_klo);
    cudaGetSymbolAddress((void**)&vhi, g_vhi);
    cudaGetSymbolAddress((void**)&vlo, g_vlo);
    cudaGetSymbolAddress((void**)&yh,  g_yh);
    cudaGetSymbolAddress((void**)&woh, g_woh);
    cudaGetSymbolAddress((void**)&wol, g_wol);

    const int M  = B_ * T_;    // 4096
    const int NW = NKV * HD;   // 512
    const int NQKV = C_ + 2 * NW;  // 3072

    // Converts: x -> f16; weights -> f16 hi/lo (wq,wk,wv into merged buffer)
    {
        int n4;
        n4 = (M * C_) / 4;
        cvt_f16<<<(n4 + 255) / 256, 256>>>((const float4*)x, (__half2*)xs, n4);
        n4 = (C_ * C_) / 4;
        cvt_hilo_h<<<(n4 + 255) / 256, 256>>>((const float4*)wq, (__half2*)wh, (__half2*)wl, n4);
        cvt_hilo_h<<<(n4 + 255) / 256, 256>>>((const float4*)wo, (__half2*)woh, (__half2*)wol, n4);
        n4 = (NW * C_) / 4;
        cvt_hilo_h<<<(n4 + 255) / 256, 256>>>((const float4*)wk,
            (__half2*)(wh + (size_t)C_ * C_), (__half2*)(wl + (size_t)C_ * C_), n4);
        cvt_hilo_h<<<(n4 + 255) / 256, 256>>>((const float4*)wv,
            (__half2*)(wh + (size_t)(C_ + NW) * C_), (__half2*)(wl + (size_t)(C_ + NW) * C_), n4);
    }

    cudaFuncSetAttribute(gemm_f16, cudaFuncAttributeMaxDynamicSharedMemorySize, G2SM_TOTAL);
    cudaFuncSetAttribute(attn_mma, cudaFuncAttributeMaxDynamicSharedMemorySize, ASM_TOTAL);

    // Merged QKV projection with fused RoPE epilogue
    gemm_f16<<<dim3(NQKV / 128, M / 128), 256, G2SM_TOTAL>>>(
        xs, wh, wl, nullptr, qh, khi, klo, vhi, vlo, fcos, fsin, C_, NQKV, 1);

    // Flash attention -> f16 y
    attn_mma<<<dim3(T_ / 128, B_ * NH), 256, ASM_TOTAL>>>(qh, khi, klo, vhi, vlo, yh);

    // Output projection (f16 2-term, fp32 out)
    gemm_f16<<<dim3(C_ / 128, M / 128), 256, G2SM_TOTAL>>>(
        yh, woh, wol, out, nullptr, nullptr, nullptr, nullptr, nullptr,
        nullptr, nullptr, C_, C_, 0);
}

// round 10
// speedup vs baseline: 1.9451x; 1.2000x over previous
#include <cuda_runtime.h>
#include <cuda_bf16.h>
#include <cuda_fp16.h>
#include <math.h>
#include <stdint.h>

#define B_   2
#define T_   2048
#define C_   2048
#define NH   16
#define NKV  4
#define HD   128
#define QSCL  0.1275495818259719f            // (1/sqrt(128)) * log2(e)

// ---------------------------------------------------------------------------
// Scratch (device globals; no allocation allowed)
// ---------------------------------------------------------------------------
__device__ __half g_xs [(size_t)B_ * T_ * C_];                // f16 x
__device__ __half g_wh [(size_t)3 * C_ / 2 * C_];             // [wq;wk;wv] hi (3072 x 2048)
__device__ __half g_wl [(size_t)3 * C_ / 2 * C_];             //              lo
__device__ __half g_qh [(size_t)B_ * NH  * T_ * HD];          // Q f16 (QSCL-scaled, roped)
__device__ __half g_khi[(size_t)B_ * NKV * T_ * HD];          // K f16 hi (roped)
__device__ __half g_klo[(size_t)B_ * NKV * T_ * HD];
__device__ __half g_vh [(size_t)B_ * NKV * T_ * HD];          // V f16 single
__device__ __half g_yh [(size_t)B_ * T_ * C_];                // attn out f16
__device__ __half g_woh[(size_t)C_ * C_];                     // wo f16 single

// ---------------------------------------------------------------------------
// PTX helpers — arch-agnostic (sm_80+)
// ---------------------------------------------------------------------------
__device__ __forceinline__ uint32_t smem_u32(const void* p) {
    uint32_t a;
    asm("{ .reg .u64 t; cvta.to.shared.u64 t, %1; cvt.u32.u64 %0, t; }"
        : "=r"(a) : "l"(p));
    return a;
}
__device__ __forceinline__ void cp_async16(uint32_t saddr, const void* gaddr) {
    asm volatile("cp.async.cg.shared.global [%0], [%1], 16;"
                 :: "r"(saddr), "l"(gaddr));
}
__device__ __forceinline__ void cp_commit() { asm volatile("cp.async.commit_group;"); }
template <int N> __device__ __forceinline__ void cp_wait() {
    asm volatile("cp.async.wait_group %0;" :: "n"(N));
}
__device__ __forceinline__ void ldsm4(uint32_t* r, uint32_t addr) {
    asm volatile("ldmatrix.sync.aligned.m8n8.x4.shared.b16 {%0,%1,%2,%3}, [%4];"
                 : "=r"(r[0]), "=r"(r[1]), "=r"(r[2]), "=r"(r[3]) : "r"(addr));
}
__device__ __forceinline__ void ldsm4t(uint32_t* r, uint32_t addr) {
    asm volatile("ldmatrix.sync.aligned.m8n8.x4.trans.shared.b16 {%0,%1,%2,%3}, [%4];"
                 : "=r"(r[0]), "=r"(r[1]), "=r"(r[2]), "=r"(r[3]) : "r"(addr));
}
__device__ __forceinline__ void mma_f16(float* c, const uint32_t* a,
                                        uint32_t b0, uint32_t b1) {
    asm volatile(
        "mma.sync.aligned.m16n8k16.row.col.f32.f16.f16.f32 "
        "{%0,%1,%2,%3}, {%4,%5,%6,%7}, {%8,%9}, {%0,%1,%2,%3};"
        : "+f"(c[0]), "+f"(c[1]), "+f"(c[2]), "+f"(c[3])
        : "r"(a[0]), "r"(a[1]), "r"(a[2]), "r"(a[3]), "r"(b0), "r"(b1));
}
__device__ __forceinline__ float ex2f(float x) {
    float y; asm("ex2.approx.f32 %0, %1;" : "=f"(y) : "f"(x)); return y;
}
__device__ __forceinline__ uint32_t ex2_pack(float s0, float s1,
                                             float& e0, float& e1) {
    uint32_t t;
    asm("{\n\t.reg .b16 l, h;\n\t"
        "cvt.rn.f16x2.f32 %0, %4, %3;\n\t"
        "ex2.approx.f16x2 %0, %0;\n\t"
        "mov.b32 {l, h}, %0;\n\t"
        "cvt.f32.f16 %1, l;\n\t"
        "cvt.f32.f16 %2, h;\n\t}"
        : "=r"(t), "=f"(e0), "=f"(e1) : "f"(s0), "f"(s1));
    return t;
}
__device__ __forceinline__ void pack_hilo_h(float x, float y, uint32_t& hi, uint32_t& lo) {
    __half hx = __float2half(x), hy = __float2half(y);
    __half lx = __float2half(x - __half2float(hx));
    __half ly = __float2half(y - __half2float(hy));
    __half2 h2(hx, hy), l2(lx, ly);
    hi = *reinterpret_cast<uint32_t*>(&h2);
    lo = *reinterpret_cast<uint32_t*>(&l2);
}

// ---------------------------------------------------------------------------
// fp32 -> f16 single
// ---------------------------------------------------------------------------
__global__ void cvt_f16(const float4* __restrict__ in, __half2* __restrict__ o2, int n4)
{
    int i = blockIdx.x * blockDim.x + threadIdx.x;
    if (i >= n4) return;
    float4 v = in[i];
    o2[2 * i + 0] = __floats2half2_rn(v.x, v.y);
    o2[2 * i + 1] = __floats2half2_rn(v.z, v.w);
}

// fp32 -> f16 hi/lo split
__global__ void cvt_hilo_h(const float4* __restrict__ in,
                           __half2* __restrict__ hi2,
                           __half2* __restrict__ lo2, int n4)
{
    int i = blockIdx.x * blockDim.x + threadIdx.x;
    if (i >= n4) return;
    float4 v = in[i];
    uint32_t h0, l0, h1, l1;
    pack_hilo_h(v.x, v.y, h0, l0);
    pack_hilo_h(v.z, v.w, h1, l1);
    hi2[2 * i + 0] = *reinterpret_cast<__half2*>(&h0);
    hi2[2 * i + 1] = *reinterpret_cast<__half2*>(&h1);
    lo2[2 * i + 0] = *reinterpret_cast<__half2*>(&l0);
    lo2[2 * i + 1] = *reinterpret_cast<__half2*>(&l1);
}

// ---------------------------------------------------------------------------
// f16 GEMM (NT): acc = A * (Whi [+ Wlo])^T, fp32 accum.  NW = 1 or 2 W terms.
// 128x128 CTA tile, BK=32, 3-stage cp.async pipeline, 256 threads (2x4 warps).
// mode 0: fp32 row-major out.
// mode 1: fused QKV epilogue — Q: RoPE+QSCL f16; K: RoPE f16 hi/lo; V: f16.
// ---------------------------------------------------------------------------
#define G2MAT  10240

template <int NW>
__global__ __launch_bounds__(256) void gemm_f16(
    const __half* __restrict__ A,
    const __half* __restrict__ Whi, const __half* __restrict__ Wlo,
    float* __restrict__ Cout,
    __half* __restrict__ Qh, __half* __restrict__ Khi, __half* __restrict__ Klo,
    __half* __restrict__ Vh,
    const float* __restrict__ fcos, const float* __restrict__ fsin,
    int K, int N, int mode)
{
    constexpr int NMAT = 1 + NW;
    constexpr int STG  = NMAT * G2MAT;
    extern __shared__ char smem[];
    const int tid = threadIdx.x;
    const int lid = tid & 31, wid = tid >> 5;
    const int wm = wid & 1, wn = wid >> 1;
    const int bm = blockIdx.y, bn = blockIdx.x;

    const __half* srcs[NMAT];
    srcs[0] = A   + (size_t)bm * 128 * K;
    srcs[1] = Whi + (size_t)bn * 128 * K;
    if (NW == 2) srcs[2] = Wlo + (size_t)bn * 128 * K;

    float acc[4][4][4];
    #pragma unroll
    for (int mi = 0; mi < 4; mi++)
        #pragma unroll
        for (int ni = 0; ni < 4; ni++)
            #pragma unroll
            for (int e = 0; e < 4; e++) acc[mi][ni][e] = 0.f;

    const int nst = K >> 5;

    auto load_stage = [&](int s) {
        char* base = smem + (s % 3) * STG;
        const int k0 = s << 5;
        #pragma unroll
        for (int m = 0; m < NMAT; m++) {
            const __half* src = srcs[m] + k0;
            char* dst = base + m * G2MAT;
            #pragma unroll
            for (int j = 0; j < 2; j++) {
                int idx = j * 256 + tid;
                int row = idx >> 2;
                int c   = idx & 3;
                cp_async16(smem_u32(dst + row * 80 + c * 16),
                           src + (size_t)row * K + c * 8);
            }
        }
        cp_commit();
    };

    load_stage(0);
    load_stage(1);

    for (int s = 0; s < nst; s++) {
        cp_wait<1>();
        __syncthreads();
        if (s + 2 < nst) load_stage(s + 2);

        const uint32_t sb = smem_u32(smem + (s % 3) * STG);
        #pragma unroll
        for (int kk = 0; kk < 2; kk++) {
            uint32_t ah[4][4], bh[2][4], bl[2][4];
            const int arow  = wm * 64 + (lid & 15);
            const int akcol = kk * 16 + ((lid & 16) ? 8 : 0);
            #pragma unroll
            for (int mi = 0; mi < 4; mi++)
                ldsm4(ah[mi], sb + (arow + mi * 16) * 80 + akcol * 2);
            const int brow  = wn * 32 + (lid & 7) + ((lid & 16) ? 8 : 0);
            const int bkcol = kk * 16 + ((lid & 8) ? 8 : 0);
            #pragma unroll
            for (int p = 0; p < 2; p++) {
                uint32_t addr = sb + G2MAT + (brow + p * 16) * 80 + bkcol * 2;
                ldsm4(bh[p], addr);
                if (NW == 2) ldsm4(bl[p], addr + G2MAT);
            }
            #pragma unroll
            for (int mi = 0; mi < 4; mi++)
                #pragma unroll
                for (int ni = 0; ni < 4; ni++) {
                    const int p = ni >> 1, q = (ni & 1) * 2;
                    mma_f16(acc[mi][ni], ah[mi], bh[p][q], bh[p][q + 1]);
                    if (NW == 2) mma_f16(acc[mi][ni], ah[mi], bl[p][q], bl[p][q + 1]);
                }
        }
        __syncthreads();
    }

    const int r0c = lid >> 2, cc = (lid & 3) * 2;
    #pragma unroll
    for (int mi = 0; mi < 4; mi++) {
        #pragma unroll
        for (int ni = 0; ni < 4; ni++) {
            int row = bm * 128 + wm * 64 + mi * 16 + r0c;
            int col = bn * 128 + wn * 32 + ni * 8 + cc;
            #pragma unroll
            for (int half = 0; half < 2; half++) {
                int rr = row + half * 8;
                float v0 = acc[mi][ni][half * 2], v1 = acc[mi][ni][half * 2 + 1];
                if (mode == 0) {
                    *(float2*)(Cout + (size_t)rr * N + col) = make_float2(v0, v1);
                } else {
                    const int b = rr >> 11, t = rr & (T_ - 1);
                    const int ht = col >> 7, d = col & (HD - 1);
                    if (ht < NH) {          // Q: RoPE + QSCL, f16 single
                        float c = fcos[t * 64 + (d >> 1)];
                        float sn = fsin[t * 64 + (d >> 1)];
                        float r0 = (v0 * c - v1 * sn) * QSCL;
                        float r1 = (v0 * sn + v1 * c) * QSCL;
                        *(__half2*)(Qh + ((((size_t)b * NH + ht) * T_ + t) * HD + d)) =
                            __floats2half2_rn(r0, r1);
                    } else if (ht < NH + NKV) {   // K: RoPE, f16 hi/lo
                        int h = ht - NH;
                        float c = fcos[t * 64 + (d >> 1)];
                        float sn = fsin[t * 64 + (d >> 1)];
                        float r0 = v0 * c - v1 * sn;
                        float r1 = v0 * sn + v1 * c;
                        uint32_t hi, lo;
                        pack_hilo_h(r0, r1, hi, lo);
                        size_t off = (((size_t)b * NKV + h) * T_ + t) * HD + d;
                        *(uint32_t*)(Khi + off) = hi;
                        *(uint32_t*)(Klo + off) = lo;
                    } else {                      // V: f16 single
                        int h = ht - NH - NKV;
                        size_t off = (((size_t)b * NKV + h) * T_ + t) * HD + d;
                        *(__half2*)(Vh + off) = __floats2half2_rn(v0, v1);
                    }
                }
            }
        }
    }
}

// ---------------------------------------------------------------------------
// Tensor-core causal flash attention — all f16.
// S = Q(K_hi+K_lo)^T 2-term; softmax via ex2.f16x2; PV 1-term.
// KV stage: Khi, Klo, V (3 matrices).
// ---------------------------------------------------------------------------
#define AROWB  272
#define AQMAT  34816                 // 128 * 272
#define AKVMAT 17408                 // 64 * 272
#define AKVST  (3 * AKVMAT)
#define ASM_TOTAL (AQMAT + 2 * AKVST)   // 139264

__global__ __launch_bounds__(256, 1) void attn_mma(
    const __half* __restrict__ Qh,
    const __half* __restrict__ Khi, const __half* __restrict__ Klo,
    const __half* __restrict__ Vh,
    __half* __restrict__ Yh)
{
    extern __shared__ char smem[];
    const int tid = threadIdx.x;
    const int lid = tid & 31, wid = tid >> 5;
    const int qt = (T_ / 128 - 1) - blockIdx.x;
    const int bh = blockIdx.y;
    const int b  = bh >> 4, h = bh & 15;
    const int kvh = h >> 2;

    const size_t qg = ((size_t)(b * NH + h) * T_ + qt * 128) * HD;
    const size_t kg = (size_t)(b * NKV + kvh) * T_ * HD;

    const uint32_t sQ   = smem_u32(smem);
    const uint32_t sKV0 = sQ + AQMAT;

    {   // Q: 2048 16B-chunks
        #pragma unroll
        for (int i = 0; i < 8; i++) {
            int idx = i * 256 + tid;
            int row = idx >> 4, c = idx & 15;
            cp_async16(sQ + row * AROWB + c * 16, Qh + qg + (size_t)row * HD + c * 8);
        }
    }
    const __half* kvsrc[3] = {Khi, Klo, Vh};
    auto load_kv = [&](int kt, int st) {
        uint32_t sb = sKV0 + st * AKVST;
        const size_t base = kg + (size_t)kt * 64 * HD;
        #pragma unroll
        for (int i = 0; i < 12; i++) {
            int idx = i * 256 + tid;
            int mat = idx >> 10;
            int rem = idx & 1023;
            int row = rem >> 4, c = rem & 15;
            cp_async16(sb + mat * AKVMAT + row * AROWB + c * 16,
                       kvsrc[mat] + base + (size_t)row * HD + c * 8);
        }
        cp_commit();
    };
    load_kv(0, 0);

    float oacc[16][4];
    #pragma unroll
    for (int jn = 0; jn < 16; jn++)
        #pragma unroll
        for (int e = 0; e < 4; e++) oacc[jn][e] = 0.f;
    float mrow[2] = {-1e30f, -1e30f};
    float lrow[2] = {0.f, 0.f};

    const int nkt = 2 * qt + 2;

    for (int kt = 0; kt < nkt; kt++) {
        if (kt + 1 < nkt) { load_kv(kt + 1, (kt + 1) & 1); cp_wait<1>(); }
        else              { cp_wait<0>(); }
        __syncthreads();

        const uint32_t sb  = sKV0 + (kt & 1) * AKVST;
        const uint32_t sKh = sb, sKl = sb + AKVMAT;
        const uint32_t sV  = sb + 2 * AKVMAT;

        // ---- S = Q K^T (f16 2-term)
        float sacc[8][4];
        #pragma unroll
        for (int j = 0; j < 8; j++)
            #pragma unroll
            for (int e = 0; e < 4; e++) sacc[j][e] = 0.f;

        #pragma unroll
        for (int kk = 0; kk < 8; kk++) {
            uint32_t ah[4];
            const int arow  = wid * 16 + (lid & 15);
            const int akcol = kk * 16 + ((lid & 16) ? 8 : 0);
            ldsm4(ah, sQ + arow * AROWB + akcol * 2);
            #pragma unroll
            for (int np = 0; np < 4; np++) {
                uint32_t bh4[4], bl4[4];
                const int brow  = np * 16 + (lid & 7) + ((lid & 16) ? 8 : 0);
                const int bkcol = kk * 16 + ((lid & 8) ? 8 : 0);
                uint32_t kaddr = brow * AROWB + bkcol * 2;
                ldsm4(bh4, sKh + kaddr);
                ldsm4(bl4, sKl + kaddr);
                #pragma unroll
                for (int jj = 0; jj < 2; jj++) {
                    const int j = 2 * np + jj, q = jj * 2;
                    mma_f16(sacc[j], ah, bh4[q], bh4[q + 1]);
                    mma_f16(sacc[j], ah, bl4[q], bl4[q + 1]);
                }
            }
        }

        // ---- causal mask (diagonal tiles only)
        const int kv0 = kt * 64;
        if (kv0 + 63 > qt * 128) {
            const int rbase = qt * 128 + wid * 16 + (lid >> 2);
            #pragma unroll
            for (int j = 0; j < 8; j++)
                #pragma unroll
                for (int e = 0; e < 4; e++) {
                    int col = kv0 + j * 8 + 2 * (lid & 3) + (e & 1);
                    int row = rbase + (e >> 1) * 8;
                    if (col > row) sacc[j][e] = -1e30f;
                }
        }

        // ---- online softmax (base-2, f16x2 exp -> P fragments)
        float mnew[2];
        #pragma unroll
        for (int h2 = 0; h2 < 2; h2++) {
            float tm = -1e30f;
            #pragma unroll
            for (int j = 0; j < 8; j++)
                tm = fmaxf(tm, fmaxf(sacc[j][h2 * 2], sacc[j][h2 * 2 + 1]));
            tm = fmaxf(tm, __shfl_xor_sync(0xffffffffu, tm, 1));
            tm = fmaxf(tm, __shfl_xor_sync(0xffffffffu, tm, 2));
            mnew[h2] = fmaxf(mrow[h2], tm);
        }

        uint32_t pfrag[8][2];
        float sum0 = 0.f, sum1 = 0.f;
        #pragma unroll
        for (int j = 0; j < 8; j++) {
            float e0, e1;
            pfrag[j][0] = ex2_pack(sacc[j][0] - mnew[0], sacc[j][1] - mnew[0], e0, e1);
            sum0 += e0 + e1;
            pfrag[j][1] = ex2_pack(sacc[j][2] - mnew[1], sacc[j][3] - mnew[1], e0, e1);
            sum1 += e0 + e1;
        }
        sum0 += __shfl_xor_sync(0xffffffffu, sum0, 1);
        sum0 += __shfl_xor_sync(0xffffffffu, sum0, 2);
        sum1 += __shfl_xor_sync(0xffffffffu, sum1, 1);
        sum1 += __shfl_xor_sync(0xffffffffu, sum1, 2);

        #pragma unroll
        for (int h2 = 0; h2 < 2; h2++) {
            float corr = ex2f(mrow[h2] - mnew[h2]);
            lrow[h2] = lrow[h2] * corr + (h2 ? sum1 : sum0);
            mrow[h2] = mnew[h2];
            #pragma unroll
            for (int jn = 0; jn < 16; jn++) {
                oacc[jn][h2 * 2]     *= corr;
                oacc[jn][h2 * 2 + 1] *= corr;
            }
        }

        // ---- O += P V (f16, 1-term)
        #pragma unroll
        for (int ks = 0; ks < 4; ks++) {
            uint32_t pf[4];
            pf[0] = pfrag[2 * ks][0];
            pf[1] = pfrag[2 * ks][1];
            pf[2] = pfrag[2 * ks + 1][0];
            pf[3] = pfrag[2 * ks + 1][1];
            #pragma unroll
            for (int np = 0; np < 8; np++) {
                uint32_t vh4[4];
                const int vrow = ks * 16 + (lid & 7) + 8 * ((lid >> 3) & 1);
                const int vcol = np * 16 + 8 * (lid >> 4);
                ldsm4t(vh4, sV + vrow * AROWB + vcol * 2);
                #pragma unroll
                for (int jj = 0; jj < 2; jj++) {
                    const int jn = 2 * np + jj, q = jj * 2;
                    mma_f16(oacc[jn], pf, vh4[q], vh4[q + 1]);
                }
            }
        }
        __syncthreads();
    }

    // ---- epilogue: normalize, write f16 y[b, t, h*128 + d]
    #pragma unroll
    for (int h2 = 0; h2 < 2; h2++) {
        float inv = 1.f / lrow[h2];
        int row_t = qt * 128 + wid * 16 + (lid >> 2) + 8 * h2;
        size_t base = ((size_t)b * T_ + row_t) * C_ + h * HD;
        #pragma unroll
        for (int jn = 0; jn < 16; jn++) {
            int col = jn * 8 + 2 * (lid & 3);
            *(__half2*)(Yh + base + col) =
                __floats2half2_rn(oacc[jn][h2 * 2] * inv, oacc[jn][h2 * 2 + 1] * inv);
        }
    }
}

// ---------------------------------------------------------------------------
extern "C" void kernel_launch(void* const* d_in, const int* in_sizes, int n_in,
                              void* d_out, int out_size)
{
    const float* x    = (const float*)d_in[0];
    const float* fcos = (const float*)d_in[1];
    const float* fsin = (const float*)d_in[2];
    const float* wq   = (const float*)d_in[3];
    const float* wk   = (const float*)d_in[4];
    const float* wv   = (const float*)d_in[5];
    const float* wo   = (const float*)d_in[6];
    float* out = (float*)d_out;

    __half *xs, *wh, *wl, *qh, *khi, *klo, *vh, *yh, *woh;
    cudaGetSymbolAddress((void**)&xs,  g_xs);
    cudaGetSymbolAddress((void**)&wh,  g_wh);
    cudaGetSymbolAddress((void**)&wl,  g_wl);
    cudaGetSymbolAddress((void**)&qh,  g_qh);
    cudaGetSymbolAddress((void**)&khi, g_khi);
    cudaGetSymbolAddress((void**)&klo, g_klo);
    cudaGetSymbolAddress((void**)&vh,  g_vh);
    cudaGetSymbolAddress((void**)&yh,  g_yh);
    cudaGetSymbolAddress((void**)&woh, g_woh);

    const int M  = B_ * T_;    // 4096
    const int NW_ = NKV * HD;  // 512
    const int NQKV = C_ + 2 * NW_;  // 3072

    // Converts: x,wo -> f16; wq/wk/wv -> f16 hi/lo (merged)
    {
        int n4;
        n4 = (M * C_) / 4;
        cvt_f16<<<(n4 + 255) / 256, 256>>>((const float4*)x, (__half2*)xs, n4);
        n4 = (C_ * C_) / 4;
        cvt_f16<<<(n4 + 255) / 256, 256>>>((const float4*)wo, (__half2*)woh, n4);
        cvt_hilo_h<<<(n4 + 255) / 256, 256>>>((const float4*)wq, (__half2*)wh, (__half2*)wl, n4);
        n4 = (NW_ * C_) / 4;
        cvt_hilo_h<<<(n4 + 255) / 256, 256>>>((const float4*)wk,
            (__half2*)(wh + (size_t)C_ * C_), (__half2*)(wl + (size_t)C_ * C_), n4);
        cvt_hilo_h<<<(n4 + 255) / 256, 256>>>((const float4*)wv,
            (__half2*)(wh + (size_t)(C_ + NW_) * C_), (__half2*)(wl + (size_t)(C_ + NW_) * C_), n4);
    }

    const int SM2 = 3 * 3 * G2MAT;   // 3 stages x 3 mats = 92160
    const int SM1 = 3 * 2 * G2MAT;   // 3 stages x 2 mats = 61440
    cudaFuncSetAttribute(gemm_f16<2>, cudaFuncAttributeMaxDynamicSharedMemorySize, SM2);
    cudaFuncSetAttribute(gemm_f16<1>, cudaFuncAttributeMaxDynamicSharedMemorySize, SM1);
    cudaFuncSetAttribute(attn_mma, cudaFuncAttributeMaxDynamicSharedMemorySize, ASM_TOTAL);

    // Merged QKV projection with fused RoPE epilogue (2-term)
    gemm_f16<2><<<dim3(NQKV / 128, M / 128), 256, SM2>>>(
        xs, wh, wl, nullptr, qh, khi, klo, vh, fcos, fsin, C_, NQKV, 1);

    // Flash attention -> f16 y
    attn_mma<<<dim3(T_ / 128, B_ * NH), 256, ASM_TOTAL>>>(qh, khi, klo, vh, yh);

    // Output projection (f16 1-term, fp32 out)
    gemm_f16<1><<<dim3(C_ / 128, M / 128), 256, SM1>>>(
        yh, woh, nullptr, out, nullptr, nullptr, nullptr, nullptr,
        nullptr, nullptr, C_, C_, 0);
}

// round 11
// speedup vs baseline: 2.1244x; 1.0922x over previous
#include <cuda_runtime.h>
#include <cuda_bf16.h>
#include <cuda_fp16.h>
#include <math.h>
#include <stdint.h>

#define B_   2
#define T_   2048
#define C_   2048
#define NH   16
#define NKV  4
#define HD   128
#define QSCL  0.1275495818259719f            // (1/sqrt(128)) * log2(e)

// ---------------------------------------------------------------------------
// Scratch (device globals; no allocation allowed)
// ---------------------------------------------------------------------------
__device__ __half g_xs [(size_t)B_ * T_ * C_];                // f16 x
__device__ __half g_wh [(size_t)3 * C_ / 2 * C_];             // [wq;wk;wv] hi (3072 x 2048)
__device__ __half g_wl [(size_t)3 * C_ / 2 * C_];             //              lo
__device__ __half g_qh [(size_t)B_ * NH  * T_ * HD];          // Q f16 (QSCL-scaled, roped)
__device__ __half g_kh [(size_t)B_ * NKV * T_ * HD];          // K f16 single (roped)
__device__ __half g_vh [(size_t)B_ * NKV * T_ * HD];          // V f16 single
__device__ __half g_yh [(size_t)B_ * T_ * C_];                // attn out f16
__device__ __half g_woh[(size_t)C_ * C_];                     // wo f16 single

// ---------------------------------------------------------------------------
// PTX helpers — arch-agnostic (sm_80+)
// ---------------------------------------------------------------------------
__device__ __forceinline__ uint32_t smem_u32(const void* p) {
    uint32_t a;
    asm("{ .reg .u64 t; cvta.to.shared.u64 t, %1; cvt.u32.u64 %0, t; }"
        : "=r"(a) : "l"(p));
    return a;
}
__device__ __forceinline__ void cp_async16(uint32_t saddr, const void* gaddr) {
    asm volatile("cp.async.cg.shared.global [%0], [%1], 16;"
                 :: "r"(saddr), "l"(gaddr));
}
__device__ __forceinline__ void cp_commit() { asm volatile("cp.async.commit_group;"); }
template <int N> __device__ __forceinline__ void cp_wait() {
    asm volatile("cp.async.wait_group %0;" :: "n"(N));
}
__device__ __forceinline__ void ldsm4(uint32_t* r, uint32_t addr) {
    asm volatile("ldmatrix.sync.aligned.m8n8.x4.shared.b16 {%0,%1,%2,%3}, [%4];"
                 : "=r"(r[0]), "=r"(r[1]), "=r"(r[2]), "=r"(r[3]) : "r"(addr));
}
__device__ __forceinline__ void ldsm4t(uint32_t* r, uint32_t addr) {
    asm volatile("ldmatrix.sync.aligned.m8n8.x4.trans.shared.b16 {%0,%1,%2,%3}, [%4];"
                 : "=r"(r[0]), "=r"(r[1]), "=r"(r[2]), "=r"(r[3]) : "r"(addr));
}
__device__ __forceinline__ void mma_f16(float* c, const uint32_t* a,
                                        uint32_t b0, uint32_t b1) {
    asm volatile(
        "mma.sync.aligned.m16n8k16.row.col.f32.f16.f16.f32 "
        "{%0,%1,%2,%3}, {%4,%5,%6,%7}, {%8,%9}, {%0,%1,%2,%3};"
        : "+f"(c[0]), "+f"(c[1]), "+f"(c[2]), "+f"(c[3])
        : "r"(a[0]), "r"(a[1]), "r"(a[2]), "r"(a[3]), "r"(b0), "r"(b1));
}
__device__ __forceinline__ float ex2f(float x) {
    float y; asm("ex2.approx.f32 %0, %1;" : "=f"(y) : "f"(x)); return y;
}
__device__ __forceinline__ uint32_t ex2_pack(float s0, float s1,
                                             float& e0, float& e1) {
    uint32_t t;
    asm("{\n\t.reg .b16 l, h;\n\t"
        "cvt.rn.f16x2.f32 %0, %4, %3;\n\t"
        "ex2.approx.f16x2 %0, %0;\n\t"
        "mov.b32 {l, h}, %0;\n\t"
        "cvt.f32.f16 %1, l;\n\t"
        "cvt.f32.f16 %2, h;\n\t}"
        : "=r"(t), "=f"(e0), "=f"(e1) : "f"(s0), "f"(s1));
    return t;
}
__device__ __forceinline__ void pack_hilo_h(float x, float y, uint32_t& hi, uint32_t& lo) {
    __half hx = __float2half(x), hy = __float2half(y);
    __half lx = __float2half(x - __half2float(hx));
    __half ly = __float2half(y - __half2float(hy));
    __half2 h2(hx, hy), l2(lx, ly);
    hi = *reinterpret_cast<uint32_t*>(&h2);
    lo = *reinterpret_cast<uint32_t*>(&l2);
}

// ---------------------------------------------------------------------------
// fp32 -> f16 single
// ---------------------------------------------------------------------------
__global__ void cvt_f16(const float4* __restrict__ in, __half2* __restrict__ o2, int n4)
{
    int i = blockIdx.x * blockDim.x + threadIdx.x;
    if (i >= n4) return;
    float4 v = in[i];
    o2[2 * i + 0] = __floats2half2_rn(v.x, v.y);
    o2[2 * i + 1] = __floats2half2_rn(v.z, v.w);
}

// fp32 -> f16 hi/lo split
__global__ void cvt_hilo_h(const float4* __restrict__ in,
                           __half2* __restrict__ hi2,
                           __half2* __restrict__ lo2, int n4)
{
    int i = blockIdx.x * blockDim.x + threadIdx.x;
    if (i >= n4) return;
    float4 v = in[i];
    uint32_t h0, l0, h1, l1;
    pack_hilo_h(v.x, v.y, h0, l0);
    pack_hilo_h(v.z, v.w, h1, l1);
    hi2[2 * i + 0] = *reinterpret_cast<__half2*>(&h0);
    hi2[2 * i + 1] = *reinterpret_cast<__half2*>(&h1);
    lo2[2 * i + 0] = *reinterpret_cast<__half2*>(&l0);
    lo2[2 * i + 1] = *reinterpret_cast<__half2*>(&l1);
}

// ---------------------------------------------------------------------------
// f16 GEMM (NT): acc = A * (Whi [+ Wlo])^T, fp32 accum.  NW = 1 or 2 W terms.
// 128x128 CTA tile, BK=32, 3-stage cp.async pipeline, 256 threads (2x4 warps).
// mode 0: fp32 row-major out.
// mode 1: fused QKV epilogue — Q: RoPE+QSCL f16; K: RoPE f16; V: f16.
// ---------------------------------------------------------------------------
#define G2MAT  10240

template <int NW>
__global__ __launch_bounds__(256) void gemm_f16(
    const __half* __restrict__ A,
    const __half* __restrict__ Whi, const __half* __restrict__ Wlo,
    float* __restrict__ Cout,
    __half* __restrict__ Qh, __half* __restrict__ Kh, __half* __restrict__ Vh,
    const float* __restrict__ fcos, const float* __restrict__ fsin,
    int K, int N, int mode)
{
    constexpr int NMAT = 1 + NW;
    constexpr int STG  = NMAT * G2MAT;
    extern __shared__ char smem[];
    const int tid = threadIdx.x;
    const int lid = tid & 31, wid = tid >> 5;
    const int wm = wid & 1, wn = wid >> 1;
    const int bm = blockIdx.y, bn = blockIdx.x;

    const __half* srcs[NMAT];
    srcs[0] = A   + (size_t)bm * 128 * K;
    srcs[1] = Whi + (size_t)bn * 128 * K;
    if (NW == 2) srcs[2] = Wlo + (size_t)bn * 128 * K;

    float acc[4][4][4];
    #pragma unroll
    for (int mi = 0; mi < 4; mi++)
        #pragma unroll
        for (int ni = 0; ni < 4; ni++)
            #pragma unroll
            for (int e = 0; e < 4; e++) acc[mi][ni][e] = 0.f;

    const int nst = K >> 5;

    auto load_stage = [&](int s) {
        char* base = smem + (s % 3) * STG;
        const int k0 = s << 5;
        #pragma unroll
        for (int m = 0; m < NMAT; m++) {
            const __half* src = srcs[m] + k0;
            char* dst = base + m * G2MAT;
            #pragma unroll
            for (int j = 0; j < 2; j++) {
                int idx = j * 256 + tid;
                int row = idx >> 2;
                int c   = idx & 3;
                cp_async16(smem_u32(dst + row * 80 + c * 16),
                           src + (size_t)row * K + c * 8);
            }
        }
        cp_commit();
    };

    load_stage(0);
    load_stage(1);

    for (int s = 0; s < nst; s++) {
        cp_wait<1>();
        __syncthreads();
        if (s + 2 < nst) load_stage(s + 2);

        const uint32_t sb = smem_u32(smem + (s % 3) * STG);
        #pragma unroll
        for (int kk = 0; kk < 2; kk++) {
            uint32_t ah[4][4], bh[2][4], bl[2][4];
            const int arow  = wm * 64 + (lid & 15);
            const int akcol = kk * 16 + ((lid & 16) ? 8 : 0);
            #pragma unroll
            for (int mi = 0; mi < 4; mi++)
                ldsm4(ah[mi], sb + (arow + mi * 16) * 80 + akcol * 2);
            const int brow  = wn * 32 + (lid & 7) + ((lid & 16) ? 8 : 0);
            const int bkcol = kk * 16 + ((lid & 8) ? 8 : 0);
            #pragma unroll
            for (int p = 0; p < 2; p++) {
                uint32_t addr = sb + G2MAT + (brow + p * 16) * 80 + bkcol * 2;
                ldsm4(bh[p], addr);
                if (NW == 2) ldsm4(bl[p], addr + G2MAT);
            }
            #pragma unroll
            for (int mi = 0; mi < 4; mi++)
                #pragma unroll
                for (int ni = 0; ni < 4; ni++) {
                    const int p = ni >> 1, q = (ni & 1) * 2;
                    mma_f16(acc[mi][ni], ah[mi], bh[p][q], bh[p][q + 1]);
                    if (NW == 2) mma_f16(acc[mi][ni], ah[mi], bl[p][q], bl[p][q + 1]);
                }
        }
        __syncthreads();
    }

    const int r0c = lid >> 2, cc = (lid & 3) * 2;
    #pragma unroll
    for (int mi = 0; mi < 4; mi++) {
        #pragma unroll
        for (int ni = 0; ni < 4; ni++) {
            int row = bm * 128 + wm * 64 + mi * 16 + r0c;
            int col = bn * 128 + wn * 32 + ni * 8 + cc;
            #pragma unroll
            for (int half = 0; half < 2; half++) {
                int rr = row + half * 8;
                float v0 = acc[mi][ni][half * 2], v1 = acc[mi][ni][half * 2 + 1];
                if (mode == 0) {
                    *(float2*)(Cout + (size_t)rr * N + col) = make_float2(v0, v1);
                } else {
                    const int b = rr >> 11, t = rr & (T_ - 1);
                    const int ht = col >> 7, d = col & (HD - 1);
                    if (ht < NH) {          // Q: RoPE + QSCL, f16 single
                        float c = fcos[t * 64 + (d >> 1)];
                        float sn = fsin[t * 64 + (d >> 1)];
                        float r0 = (v0 * c - v1 * sn) * QSCL;
                        float r1 = (v0 * sn + v1 * c) * QSCL;
                        *(__half2*)(Qh + ((((size_t)b * NH + ht) * T_ + t) * HD + d)) =
                            __floats2half2_rn(r0, r1);
                    } else if (ht < NH + NKV) {   // K: RoPE, f16 single
                        int h = ht - NH;
                        float c = fcos[t * 64 + (d >> 1)];
                        float sn = fsin[t * 64 + (d >> 1)];
                        float r0 = v0 * c - v1 * sn;
                        float r1 = v0 * sn + v1 * c;
                        size_t off = (((size_t)b * NKV + h) * T_ + t) * HD + d;
                        *(__half2*)(Kh + off) = __floats2half2_rn(r0, r1);
                    } else {                      // V: f16 single
                        int h = ht - NH - NKV;
                        size_t off = (((size_t)b * NKV + h) * T_ + t) * HD + d;
                        *(__half2*)(Vh + off) = __floats2half2_rn(v0, v1);
                    }
                }
            }
        }
    }
}

// ---------------------------------------------------------------------------
// Tensor-core causal flash attention — all f16 single precision operands.
// S = Q K^T 1-term; softmax via ex2.f16x2; PV 1-term.
// KV stage: K, V (2 matrices), double-buffered.
// ---------------------------------------------------------------------------
#define AROWB  272
#define AQMAT  34816                 // 128 * 272
#define AKVMAT 17408                 // 64 * 272
#define AKVST  (2 * AKVMAT)
#define ASM_TOTAL (AQMAT + 2 * AKVST)   // 104448

__global__ __launch_bounds__(256, 1) void attn_mma(
    const __half* __restrict__ Qh,
    const __half* __restrict__ Kh, const __half* __restrict__ Vh,
    __half* __restrict__ Yh)
{
    extern __shared__ char smem[];
    const int tid = threadIdx.x;
    const int lid = tid & 31, wid = tid >> 5;
    const int qt = (T_ / 128 - 1) - blockIdx.x;
    const int bh = blockIdx.y;
    const int b  = bh >> 4, h = bh & 15;
    const int kvh = h >> 2;

    const size_t qg = ((size_t)(b * NH + h) * T_ + qt * 128) * HD;
    const size_t kg = (size_t)(b * NKV + kvh) * T_ * HD;

    const uint32_t sQ   = smem_u32(smem);
    const uint32_t sKV0 = sQ + AQMAT;

    {   // Q: 2048 16B-chunks
        #pragma unroll
        for (int i = 0; i < 8; i++) {
            int idx = i * 256 + tid;
            int row = idx >> 4, c = idx & 15;
            cp_async16(sQ + row * AROWB + c * 16, Qh + qg + (size_t)row * HD + c * 8);
        }
    }
    const __half* kvsrc[2] = {Kh, Vh};
    auto load_kv = [&](int kt, int st) {
        uint32_t sb = sKV0 + st * AKVST;
        const size_t base = kg + (size_t)kt * 64 * HD;
        #pragma unroll
        for (int i = 0; i < 8; i++) {
            int idx = i * 256 + tid;
            int mat = idx >> 10;
            int rem = idx & 1023;
            int row = rem >> 4, c = rem & 15;
            cp_async16(sb + mat * AKVMAT + row * AROWB + c * 16,
                       kvsrc[mat] + base + (size_t)row * HD + c * 8);
        }
        cp_commit();
    };
    load_kv(0, 0);

    float oacc[16][4];
    #pragma unroll
    for (int jn = 0; jn < 16; jn++)
        #pragma unroll
        for (int e = 0; e < 4; e++) oacc[jn][e] = 0.f;
    float mrow[2] = {-1e30f, -1e30f};
    float lrow[2] = {0.f, 0.f};

    const int nkt = 2 * qt + 2;

    for (int kt = 0; kt < nkt; kt++) {
        if (kt + 1 < nkt) { load_kv(kt + 1, (kt + 1) & 1); cp_wait<1>(); }
        else              { cp_wait<0>(); }
        __syncthreads();

        const uint32_t sb = sKV0 + (kt & 1) * AKVST;
        const uint32_t sK = sb, sV = sb + AKVMAT;

        // ---- S = Q K^T (f16 1-term)
        float sacc[8][4];
        #pragma unroll
        for (int j = 0; j < 8; j++)
            #pragma unroll
            for (int e = 0; e < 4; e++) sacc[j][e] = 0.f;

        #pragma unroll
        for (int kk = 0; kk < 8; kk++) {
            uint32_t ah[4];
            const int arow  = wid * 16 + (lid & 15);
            const int akcol = kk * 16 + ((lid & 16) ? 8 : 0);
            ldsm4(ah, sQ + arow * AROWB + akcol * 2);
            #pragma unroll
            for (int np = 0; np < 4; np++) {
                uint32_t bh4[4];
                const int brow  = np * 16 + (lid & 7) + ((lid & 16) ? 8 : 0);
                const int bkcol = kk * 16 + ((lid & 8) ? 8 : 0);
                ldsm4(bh4, sK + brow * AROWB + bkcol * 2);
                #pragma unroll
                for (int jj = 0; jj < 2; jj++) {
                    const int j = 2 * np + jj, q = jj * 2;
                    mma_f16(sacc[j], ah, bh4[q], bh4[q + 1]);
                }
            }
        }

        // ---- causal mask (diagonal tiles only)
        const int kv0 = kt * 64;
        if (kv0 + 63 > qt * 128) {
            const int rbase = qt * 128 + wid * 16 + (lid >> 2);
            #pragma unroll
            for (int j = 0; j < 8; j++)
                #pragma unroll
                for (int e = 0; e < 4; e++) {
                    int col = kv0 + j * 8 + 2 * (lid & 3) + (e & 1);
                    int row = rbase + (e >> 1) * 8;
                    if (col > row) sacc[j][e] = -1e30f;
                }
        }

        // ---- online softmax (base-2, f16x2 exp -> P fragments)
        float mnew[2];
        #pragma unroll
        for (int h2 = 0; h2 < 2; h2++) {
            float tm = -1e30f;
            #pragma unroll
            for (int j = 0; j < 8; j++)
                tm = fmaxf(tm, fmaxf(sacc[j][h2 * 2], sacc[j][h2 * 2 + 1]));
            tm = fmaxf(tm, __shfl_xor_sync(0xffffffffu, tm, 1));
            tm = fmaxf(tm, __shfl_xor_sync(0xffffffffu, tm, 2));
            mnew[h2] = fmaxf(mrow[h2], tm);
        }

        uint32_t pfrag[8][2];
        float sum0 = 0.f, sum1 = 0.f;
        #pragma unroll
        for (int j = 0; j < 8; j++) {
            float e0, e1;
            pfrag[j][0] = ex2_pack(sacc[j][0] - mnew[0], sacc[j][1] - mnew[0], e0, e1);
            sum0 += e0 + e1;
            pfrag[j][1] = ex2_pack(sacc[j][2] - mnew[1], sacc[j][3] - mnew[1], e0, e1);
            sum1 += e0 + e1;
        }
        sum0 += __shfl_xor_sync(0xffffffffu, sum0, 1);
        sum0 += __shfl_xor_sync(0xffffffffu, sum0, 2);
        sum1 += __shfl_xor_sync(0xffffffffu, sum1, 1);
        sum1 += __shfl_xor_sync(0xffffffffu, sum1, 2);

        #pragma unroll
        for (int h2 = 0; h2 < 2; h2++) {
            float corr = ex2f(mrow[h2] - mnew[h2]);
            lrow[h2] = lrow[h2] * corr + (h2 ? sum1 : sum0);
            mrow[h2] = mnew[h2];
            #pragma unroll
            for (int jn = 0; jn < 16; jn++) {
                oacc[jn][h2 * 2]     *= corr;
                oacc[jn][h2 * 2 + 1] *= corr;
            }
        }

        // ---- O += P V (f16, 1-term)
        #pragma unroll
        for (int ks = 0; ks < 4; ks++) {
            uint32_t pf[4];
            pf[0] = pfrag[2 * ks][0];
            pf[1] = pfrag[2 * ks][1];
            pf[2] = pfrag[2 * ks + 1][0];
            pf[3] = pfrag[2 * ks + 1][1];
            #pragma unroll
            for (int np = 0; np < 8; np++) {
                uint32_t vh4[4];
                const int vrow = ks * 16 + (lid & 7) + 8 * ((lid >> 3) & 1);
                const int vcol = np * 16 + 8 * (lid >> 4);
                ldsm4t(vh4, sV + vrow * AROWB + vcol * 2);
                #pragma unroll
                for (int jj = 0; jj < 2; jj++) {
                    const int jn = 2 * np + jj, q = jj * 2;
                    mma_f16(oacc[jn], pf, vh4[q], vh4[q + 1]);
                }
            }
        }
        __syncthreads();
    }

    // ---- epilogue: normalize, write f16 y[b, t, h*128 + d]
    #pragma unroll
    for (int h2 = 0; h2 < 2; h2++) {
        float inv = 1.f / lrow[h2];
        int row_t = qt * 128 + wid * 16 + (lid >> 2) + 8 * h2;
        size_t base = ((size_t)b * T_ + row_t) * C_ + h * HD;
        #pragma unroll
        for (int jn = 0; jn < 16; jn++) {
            int col = jn * 8 + 2 * (lid & 3);
            *(__half2*)(Yh + base + col) =
                __floats2half2_rn(oacc[jn][h2 * 2] * inv, oacc[jn][h2 * 2 + 1] * inv);
        }
    }
}

// ---------------------------------------------------------------------------
extern "C" void kernel_launch(void* const* d_in, const int* in_sizes, int n_in,
                              void* d_out, int out_size)
{
    const float* x    = (const float*)d_in[0];
    const float* fcos = (const float*)d_in[1];
    const float* fsin = (const float*)d_in[2];
    const float* wq   = (const float*)d_in[3];
    const float* wk   = (const float*)d_in[4];
    const float* wv   = (const float*)d_in[5];
    const float* wo   = (const float*)d_in[6];
    float* out = (float*)d_out;

    __half *xs, *wh, *wl, *qh, *kh, *vh, *yh, *woh;
    cudaGetSymbolAddress((void**)&xs,  g_xs);
    cudaGetSymbolAddress((void**)&wh,  g_wh);
    cudaGetSymbolAddress((void**)&wl,  g_wl);
    cudaGetSymbolAddress((void**)&qh,  g_qh);
    cudaGetSymbolAddress((void**)&kh,  g_kh);
    cudaGetSymbolAddress((void**)&vh,  g_vh);
    cudaGetSymbolAddress((void**)&yh,  g_yh);
    cudaGetSymbolAddress((void**)&woh, g_woh);

    const int M  = B_ * T_;    // 4096
    const int NW_ = NKV * HD;  // 512
    const int NQKV = C_ + 2 * NW_;  // 3072

    // Converts: x,wo -> f16; wq/wk/wv -> f16 hi/lo (merged weight buffer)
    {
        int n4;
        n4 = (M * C_) / 4;
        cvt_f16<<<(n4 + 255) / 256, 256>>>((const float4*)x, (__half2*)xs, n4);
        n4 = (C_ * C_) / 4;
        cvt_f16<<<(n4 + 255) / 256, 256>>>((const float4*)wo, (__half2*)woh, n4);
        cvt_hilo_h<<<(n4 + 255) / 256, 256>>>((const float4*)wq, (__half2*)wh, (__half2*)wl, n4);
        n4 = (NW_ * C_) / 4;
        cvt_hilo_h<<<(n4 + 255) / 256, 256>>>((const float4*)wk,
            (__half2*)(wh + (size_t)C_ * C_), (__half2*)(wl + (size_t)C_ * C_), n4);
        cvt_hilo_h<<<(n4 + 255) / 256, 256>>>((const float4*)wv,
            (__half2*)(wh + (size_t)(C_ + NW_) * C_), (__half2*)(wl + (size_t)(C_ + NW_) * C_), n4);
    }

    const int SM2 = 3 * 3 * G2MAT;   // 92160
    const int SM1 = 3 * 2 * G2MAT;   // 61440
    cudaFuncSetAttribute(gemm_f16<2>, cudaFuncAttributeMaxDynamicSharedMemorySize, SM2);
    cudaFuncSetAttribute(gemm_f16<1>, cudaFuncAttributeMaxDynamicSharedMemorySize, SM1);
    cudaFuncSetAttribute(attn_mma, cudaFuncAttributeMaxDynamicSharedMemorySize, ASM_TOTAL);

    // Merged QKV projection with fused RoPE epilogue (2-term weights)
    gemm_f16<2><<<dim3(NQKV / 128, M / 128), 256, SM2>>>(
        xs, wh, wl, nullptr, qh, kh, vh, fcos, fsin, C_, NQKV, 1);

    // Flash attention -> f16 y
    attn_mma<<<dim3(T_ / 128, B_ * NH), 256, ASM_TOTAL>>>(qh, kh, vh, yh);

    // Output projection (f16 1-term, fp32 out)
    gemm_f16<1><<<dim3(C_ / 128, M / 128), 256, SM1>>>(
        yh, woh, nullptr, out, nullptr, nullptr, nullptr,
        nullptr, nullptr, C_, C_, 0);
}

// round 12
// speedup vs baseline: 2.7220x; 1.2813x over previous
#include <cuda_runtime.h>
#include <cuda_bf16.h>
#include <cuda_fp16.h>
#include <math.h>
#include <stdint.h>

#define B_   2
#define T_   2048
#define C_   2048
#define NH   16
#define NKV  4
#define HD   128
#define QSCL  0.1275495818259719f            // (1/sqrt(128)) * log2(e)

// ---------------------------------------------------------------------------
// Scratch (device globals; no allocation allowed)
// ---------------------------------------------------------------------------
__device__ __half g_xs [(size_t)B_ * T_ * C_];                // f16 x
__device__ __half g_wh [(size_t)3 * C_ / 2 * C_];             // [wq;wk;wv] f16 (3072 x 2048)
__device__ __half g_qh [(size_t)B_ * NH  * T_ * HD];          // Q f16 (QSCL-scaled, roped)
__device__ __half g_kh [(size_t)B_ * NKV * T_ * HD];          // K f16 (roped)
__device__ __half g_vh [(size_t)B_ * NKV * T_ * HD];          // V f16
__device__ __half g_yh [(size_t)B_ * T_ * C_];                // attn out f16
__device__ __half g_woh[(size_t)C_ * C_];                     // wo f16

// ---------------------------------------------------------------------------
// PTX helpers — arch-agnostic (sm_80+)
// ---------------------------------------------------------------------------
__device__ __forceinline__ uint32_t smem_u32(const void* p) {
    uint32_t a;
    asm("{ .reg .u64 t; cvta.to.shared.u64 t, %1; cvt.u32.u64 %0, t; }"
        : "=r"(a) : "l"(p));
    return a;
}
__device__ __forceinline__ void cp_async16(uint32_t saddr, const void* gaddr) {
    asm volatile("cp.async.cg.shared.global [%0], [%1], 16;"
                 :: "r"(saddr), "l"(gaddr));
}
__device__ __forceinline__ void cp_commit() { asm volatile("cp.async.commit_group;"); }
template <int N> __device__ __forceinline__ void cp_wait() {
    asm volatile("cp.async.wait_group %0;" :: "n"(N));
}
__device__ __forceinline__ void ldsm4(uint32_t* r, uint32_t addr) {
    asm volatile("ldmatrix.sync.aligned.m8n8.x4.shared.b16 {%0,%1,%2,%3}, [%4];"
                 : "=r"(r[0]), "=r"(r[1]), "=r"(r[2]), "=r"(r[3]) : "r"(addr));
}
__device__ __forceinline__ void ldsm4t(uint32_t* r, uint32_t addr) {
    asm volatile("ldmatrix.sync.aligned.m8n8.x4.trans.shared.b16 {%0,%1,%2,%3}, [%4];"
                 : "=r"(r[0]), "=r"(r[1]), "=r"(r[2]), "=r"(r[3]) : "r"(addr));
}
__device__ __forceinline__ void mma_f16(float* c, const uint32_t* a,
                                        uint32_t b0, uint32_t b1) {
    asm volatile(
        "mma.sync.aligned.m16n8k16.row.col.f32.f16.f16.f32 "
        "{%0,%1,%2,%3}, {%4,%5,%6,%7}, {%8,%9}, {%0,%1,%2,%3};"
        : "+f"(c[0]), "+f"(c[1]), "+f"(c[2]), "+f"(c[3])
        : "r"(a[0]), "r"(a[1]), "r"(a[2]), "r"(a[3]), "r"(b0), "r"(b1));
}
__device__ __forceinline__ float ex2f(float x) {
    float y; asm("ex2.approx.f32 %0, %1;" : "=f"(y) : "f"(x)); return y;
}
__device__ __forceinline__ uint32_t ex2_pack(float s0, float s1,
                                             float& e0, float& e1) {
    uint32_t t;
    asm("{\n\t.reg .b16 l, h;\n\t"
        "cvt.rn.f16x2.f32 %0, %4, %3;\n\t"
        "ex2.approx.f16x2 %0, %0;\n\t"
        "mov.b32 {l, h}, %0;\n\t"
        "cvt.f32.f16 %1, l;\n\t"
        "cvt.f32.f16 %2, h;\n\t}"
        : "=r"(t), "=f"(e0), "=f"(e1) : "f"(s0), "f"(s1));
    return t;
}

// ---------------------------------------------------------------------------
// fp32 -> f16
// ---------------------------------------------------------------------------
__global__ void cvt_f16(const float4* __restrict__ in, __half2* __restrict__ o2, int n4)
{
    int i = blockIdx.x * blockDim.x + threadIdx.x;
    if (i >= n4) return;
    float4 v = in[i];
    o2[2 * i + 0] = __floats2half2_rn(v.x, v.y);
    o2[2 * i + 1] = __floats2half2_rn(v.z, v.w);
}

// ---------------------------------------------------------------------------
// f16 1-term GEMM (NT): acc = A * W^T, fp32 accum.
// 128x128 CTA tile, BK=32, 4-stage cp.async pipeline, 256 threads (2x4 warps).
// mode 0: fp32 row-major out.
// mode 1: fused QKV epilogue — Q: RoPE+QSCL f16; K: RoPE f16; V: f16.
// ---------------------------------------------------------------------------
#define G2MAT  10240
#define GSTG   (2 * G2MAT)           // 20480
#define GSM_TOTAL (4 * GSTG)         // 81920

__global__ __launch_bounds__(256) void gemm_f16(
    const __half* __restrict__ A, const __half* __restrict__ W,
    float* __restrict__ Cout,
    __half* __restrict__ Qh, __half* __restrict__ Kh, __half* __restrict__ Vh,
    const float* __restrict__ fcos, const float* __restrict__ fsin,
    int K, int N, int mode)
{
    extern __shared__ char smem[];
    const int tid = threadIdx.x;
    const int lid = tid & 31, wid = tid >> 5;
    const int wm = wid & 1, wn = wid >> 1;
    const int bm = blockIdx.y, bn = blockIdx.x;

    const __half* Asrc = A + (size_t)bm * 128 * K;
    const __half* Wsrc = W + (size_t)bn * 128 * K;

    float acc[4][4][4];
    #pragma unroll
    for (int mi = 0; mi < 4; mi++)
        #pragma unroll
        for (int ni = 0; ni < 4; ni++)
            #pragma unroll
            for (int e = 0; e < 4; e++) acc[mi][ni][e] = 0.f;

    const int nst = K >> 5;

    auto load_stage = [&](int s) {
        char* base = smem + (s & 3) * GSTG;
        const int k0 = s << 5;
        #pragma unroll
        for (int m = 0; m < 2; m++) {
            const __half* src = (m ? Wsrc : Asrc) + k0;
            char* dst = base + m * G2MAT;
            #pragma unroll
            for (int j = 0; j < 2; j++) {
                int idx = j * 256 + tid;
                int row = idx >> 2;
                int c   = idx & 3;
                cp_async16(smem_u32(dst + row * 80 + c * 16),
                           src + (size_t)row * K + c * 8);
            }
        }
        cp_commit();
    };

    load_stage(0);
    load_stage(1);
    load_stage(2);

    for (int s = 0; s < nst; s++) {
        if (s + 3 < nst) load_stage(s + 3); else cp_commit();
        cp_wait<3>();
        __syncthreads();

        const uint32_t sb = smem_u32(smem + (s & 3) * GSTG);
        #pragma unroll
        for (int kk = 0; kk < 2; kk++) {
            uint32_t ah[4][4], bh[2][4];
            const int arow  = wm * 64 + (lid & 15);
            const int akcol = kk * 16 + ((lid & 16) ? 8 : 0);
            #pragma unroll
            for (int mi = 0; mi < 4; mi++)
                ldsm4(ah[mi], sb + (arow + mi * 16) * 80 + akcol * 2);
            const int brow  = wn * 32 + (lid & 7) + ((lid & 16) ? 8 : 0);
            const int bkcol = kk * 16 + ((lid & 8) ? 8 : 0);
            #pragma unroll
            for (int p = 0; p < 2; p++)
                ldsm4(bh[p], sb + G2MAT + (brow + p * 16) * 80 + bkcol * 2);
            #pragma unroll
            for (int mi = 0; mi < 4; mi++)
                #pragma unroll
                for (int ni = 0; ni < 4; ni++) {
                    const int p = ni >> 1, q = (ni & 1) * 2;
                    mma_f16(acc[mi][ni], ah[mi], bh[p][q], bh[p][q + 1]);
                }
        }
        __syncthreads();
    }

    const int r0c = lid >> 2, cc = (lid & 3) * 2;
    #pragma unroll
    for (int mi = 0; mi < 4; mi++) {
        #pragma unroll
        for (int ni = 0; ni < 4; ni++) {
            int row = bm * 128 + wm * 64 + mi * 16 + r0c;
            int col = bn * 128 + wn * 32 + ni * 8 + cc;
            #pragma unroll
            for (int half = 0; half < 2; half++) {
                int rr = row + half * 8;
                float v0 = acc[mi][ni][half * 2], v1 = acc[mi][ni][half * 2 + 1];
                if (mode == 0) {
                    *(float2*)(Cout + (size_t)rr * N + col) = make_float2(v0, v1);
                } else {
                    const int b = rr >> 11, t = rr & (T_ - 1);
                    const int ht = col >> 7, d = col & (HD - 1);
                    if (ht < NH) {          // Q: RoPE + QSCL
                        float c = fcos[t * 64 + (d >> 1)];
                        float sn = fsin[t * 64 + (d >> 1)];
                        float r0 = (v0 * c - v1 * sn) * QSCL;
                        float r1 = (v0 * sn + v1 * c) * QSCL;
                        *(__half2*)(Qh + ((((size_t)b * NH + ht) * T_ + t) * HD + d)) =
                            __floats2half2_rn(r0, r1);
                    } else if (ht < NH + NKV) {   // K: RoPE
                        int h = ht - NH;
                        float c = fcos[t * 64 + (d >> 1)];
                        float sn = fsin[t * 64 + (d >> 1)];
                        float r0 = v0 * c - v1 * sn;
                        float r1 = v0 * sn + v1 * c;
                        size_t off = (((size_t)b * NKV + h) * T_ + t) * HD + d;
                        *(__half2*)(Kh + off) = __floats2half2_rn(r0, r1);
                    } else {                      // V
                        int h = ht - NH - NKV;
                        size_t off = (((size_t)b * NKV + h) * T_ + t) * HD + d;
                        *(__half2*)(Vh + off) = __floats2half2_rn(v0, v1);
                    }
                }
            }
        }
    }
}

// ---------------------------------------------------------------------------
// Tensor-core causal flash attention — all f16 single precision operands.
// S = Q K^T; softmax via ex2.f16x2; PV 1-term. (R11 core, passing.)
// ---------------------------------------------------------------------------
#define AROWB  272
#define AQMAT  34816                 // 128 * 272
#define AKVMAT 17408                 // 64 * 272
#define AKVST  (2 * AKVMAT)
#define ASM_TOTAL (AQMAT + 2 * AKVST)   // 104448

__global__ __launch_bounds__(256, 1) void attn_mma(
    const __half* __restrict__ Qh,
    const __half* __restrict__ Kh, const __half* __restrict__ Vh,
    __half* __restrict__ Yh)
{
    extern __shared__ char smem[];
    const int tid = threadIdx.x;
    const int lid = tid & 31, wid = tid >> 5;
    const int qt = (T_ / 128 - 1) - blockIdx.x;
    const int bh = blockIdx.y;
    const int b  = bh >> 4, h = bh & 15;
    const int kvh = h >> 2;

    const size_t qg = ((size_t)(b * NH + h) * T_ + qt * 128) * HD;
    const size_t kg = (size_t)(b * NKV + kvh) * T_ * HD;

    const uint32_t sQ   = smem_u32(smem);
    const uint32_t sKV0 = sQ + AQMAT;

    {   // Q: 2048 16B-chunks
        #pragma unroll
        for (int i = 0; i < 8; i++) {
            int idx = i * 256 + tid;
            int row = idx >> 4, c = idx & 15;
            cp_async16(sQ + row * AROWB + c * 16, Qh + qg + (size_t)row * HD + c * 8);
        }
    }
    const __half* kvsrc[2] = {Kh, Vh};
    auto load_kv = [&](int kt, int st) {
        uint32_t sb = sKV0 + st * AKVST;
        const size_t base = kg + (size_t)kt * 64 * HD;
        #pragma unroll
        for (int i = 0; i < 8; i++) {
            int idx = i * 256 + tid;
            int mat = idx >> 10;
            int rem = idx & 1023;
            int row = rem >> 4, c = rem & 15;
            cp_async16(sb + mat * AKVMAT + row * AROWB + c * 16,
                       kvsrc[mat] + base + (size_t)row * HD + c * 8);
        }
        cp_commit();
    };
    load_kv(0, 0);

    float oacc[16][4];
    #pragma unroll
    for (int jn = 0; jn < 16; jn++)
        #pragma unroll
        for (int e = 0; e < 4; e++) oacc[jn][e] = 0.f;
    float mrow[2] = {-1e30f, -1e30f};
    float lrow[2] = {0.f, 0.f};

    const int nkt = 2 * qt + 2;

    for (int kt = 0; kt < nkt; kt++) {
        if (kt + 1 < nkt) { load_kv(kt + 1, (kt + 1) & 1); cp_wait<1>(); }
        else              { cp_wait<0>(); }
        __syncthreads();

        const uint32_t sb = sKV0 + (kt & 1) * AKVST;
        const uint32_t sK = sb, sV = sb + AKVMAT;

        // ---- S = Q K^T
        float sacc[8][4];
        #pragma unroll
        for (int j = 0; j < 8; j++)
            #pragma unroll
            for (int e = 0; e < 4; e++) sacc[j][e] = 0.f;

        #pragma unroll
        for (int kk = 0; kk < 8; kk++) {
            uint32_t ah[4];
            const int arow  = wid * 16 + (lid & 15);
            const int akcol = kk * 16 + ((lid & 16) ? 8 : 0);
            ldsm4(ah, sQ + arow * AROWB + akcol * 2);
            #pragma unroll
            for (int np = 0; np < 4; np++) {
                uint32_t bh4[4];
                const int brow  = np * 16 + (lid & 7) + ((lid & 16) ? 8 : 0);
                const int bkcol = kk * 16 + ((lid & 8) ? 8 : 0);
                ldsm4(bh4, sK + brow * AROWB + bkcol * 2);
                #pragma unroll
                for (int jj = 0; jj < 2; jj++) {
                    const int j = 2 * np + jj, q = jj * 2;
                    mma_f16(sacc[j], ah, bh4[q], bh4[q + 1]);
                }
            }
        }

        // ---- causal mask (diagonal tiles only)
        const int kv0 = kt * 64;
        if (kv0 + 63 > qt * 128) {
            const int rbase = qt * 128 + wid * 16 + (lid >> 2);
            #pragma unroll
            for (int j = 0; j < 8; j++)
                #pragma unroll
                for (int e = 0; e < 4; e++) {
                    int col = kv0 + j * 8 + 2 * (lid & 3) + (e & 1);
                    int row = rbase + (e >> 1) * 8;
                    if (col > row) sacc[j][e] = -1e30f;
                }
        }

        // ---- online softmax (base-2, f16x2 exp -> P fragments)
        float mnew[2];
        #pragma unroll
        for (int h2 = 0; h2 < 2; h2++) {
            float tm = -1e30f;
            #pragma unroll
            for (int j = 0; j < 8; j++)
                tm = fmaxf(tm, fmaxf(sacc[j][h2 * 2], sacc[j][h2 * 2 + 1]));
            tm = fmaxf(tm, __shfl_xor_sync(0xffffffffu, tm, 1));
            tm = fmaxf(tm, __shfl_xor_sync(0xffffffffu, tm, 2));
            mnew[h2] = fmaxf(mrow[h2], tm);
        }

        uint32_t pfrag[8][2];
        float sum0 = 0.f, sum1 = 0.f;
        #pragma unroll
        for (int j = 0; j < 8; j++) {
            float e0, e1;
            pfrag[j][0] = ex2_pack(sacc[j][0] - mnew[0], sacc[j][1] - mnew[0], e0, e1);
            sum0 += e0 + e1;
            pfrag[j][1] = ex2_pack(sacc[j][2] - mnew[1], sacc[j][3] - mnew[1], e0, e1);
            sum1 += e0 + e1;
        }
        sum0 += __shfl_xor_sync(0xffffffffu, sum0, 1);
        sum0 += __shfl_xor_sync(0xffffffffu, sum0, 2);
        sum1 += __shfl_xor_sync(0xffffffffu, sum1, 1);
        sum1 += __shfl_xor_sync(0xffffffffu, sum1, 2);

        #pragma unroll
        for (int h2 = 0; h2 < 2; h2++) {
            float corr = ex2f(mrow[h2] - mnew[h2]);
            lrow[h2] = lrow[h2] * corr + (h2 ? sum1 : sum0);
            mrow[h2] = mnew[h2];
            #pragma unroll
            for (int jn = 0; jn < 16; jn++) {
                oacc[jn][h2 * 2]     *= corr;
                oacc[jn][h2 * 2 + 1] *= corr;
            }
        }

        // ---- O += P V
        #pragma unroll
        for (int ks = 0; ks < 4; ks++) {
            uint32_t pf[4];
            pf[0] = pfrag[2 * ks][0];
            pf[1] = pfrag[2 * ks][1];
            pf[2] = pfrag[2 * ks + 1][0];
            pf[3] = pfrag[2 * ks + 1][1];
            #pragma unroll
            for (int np = 0; np < 8; np++) {
                uint32_t vh4[4];
                const int vrow = ks * 16 + (lid & 7) + 8 * ((lid >> 3) & 1);
                const int vcol = np * 16 + 8 * (lid >> 4);
                ldsm4t(vh4, sV + vrow * AROWB + vcol * 2);
                #pragma unroll
                for (int jj = 0; jj < 2; jj++) {
                    const int jn = 2 * np + jj, q = jj * 2;
                    mma_f16(oacc[jn], pf, vh4[q], vh4[q + 1]);
                }
            }
        }
        __syncthreads();
    }

    // ---- epilogue: normalize, write f16 y[b, t, h*128 + d]
    #pragma unroll
    for (int h2 = 0; h2 < 2; h2++) {
        float inv = 1.f / lrow[h2];
        int row_t = qt * 128 + wid * 16 + (lid >> 2) + 8 * h2;
        size_t base = ((size_t)b * T_ + row_t) * C_ + h * HD;
        #pragma unroll
        for (int jn = 0; jn < 16; jn++) {
            int col = jn * 8 + 2 * (lid & 3);
            *(__half2*)(Yh + base + col) =
                __floats2half2_rn(oacc[jn][h2 * 2] * inv, oacc[jn][h2 * 2 + 1] * inv);
        }
    }
}

// ---------------------------------------------------------------------------
extern "C" void kernel_launch(void* const* d_in, const int* in_sizes, int n_in,
                              void* d_out, int out_size)
{
    const float* x    = (const float*)d_in[0];
    const float* fcos = (const float*)d_in[1];
    const float* fsin = (const float*)d_in[2];
    const float* wq   = (const float*)d_in[3];
    const float* wk   = (const float*)d_in[4];
    const float* wv   = (const float*)d_in[5];
    const float* wo   = (const float*)d_in[6];
    float* out = (float*)d_out;

    __half *xs, *wh, *qh, *kh, *vh, *yh, *woh;
    cudaGetSymbolAddress((void**)&xs,  g_xs);
    cudaGetSymbolAddress((void**)&wh,  g_wh);
    cudaGetSymbolAddress((void**)&qh,  g_qh);
    cudaGetSymbolAddress((void**)&kh,  g_kh);
    cudaGetSymbolAddress((void**)&vh,  g_vh);
    cudaGetSymbolAddress((void**)&yh,  g_yh);
    cudaGetSymbolAddress((void**)&woh, g_woh);

    const int M  = B_ * T_;    // 4096
    const int NW_ = NKV * HD;  // 512
    const int NQKV = C_ + 2 * NW_;  // 3072

    // Converts: everything -> single f16 (wq/wk/wv into merged weight buffer)
    {
        int n4;
        n4 = (M * C_) / 4;
        cvt_f16<<<(n4 + 255) / 256, 256>>>((const float4*)x, (__half2*)xs, n4);
        n4 = (C_ * C_) / 4;
        cvt_f16<<<(n4 + 255) / 256, 256>>>((const float4*)wq, (__half2*)wh, n4);
        cvt_f16<<<(n4 + 255) / 256, 256>>>((const float4*)wo, (__half2*)woh, n4);
        n4 = (NW_ * C_) / 4;
        cvt_f16<<<(n4 + 255) / 256, 256>>>((const float4*)wk, (__half2*)(wh + (size_t)C_ * C_), n4);
        cvt_f16<<<(n4 + 255) / 256, 256>>>((const float4*)wv, (__half2*)(wh + (size_t)(C_ + NW_) * C_), n4);
    }

    cudaFuncSetAttribute(gemm_f16, cudaFuncAttributeMaxDynamicSharedMemorySize, GSM_TOTAL);
    cudaFuncSetAttribute(attn_mma, cudaFuncAttributeMaxDynamicSharedMemorySize, ASM_TOTAL);

    // Merged QKV projection with fused RoPE epilogue (1-term weights)
    gemm_f16<<<dim3(NQKV / 128, M / 128), 256, GSM_TOTAL>>>(
        xs, wh, nullptr, qh, kh, vh, fcos, fsin, C_, NQKV, 1);

    // Flash attention -> f16 y
    attn_mma<<<dim3(T_ / 128, B_ * NH), 256, ASM_TOTAL>>>(qh, kh, vh, yh);

    // Output projection (f16 1-term, fp32 out)
    gemm_f16<<<dim3(C_ / 128, M / 128), 256, GSM_TOTAL>>>(
        yh, woh, out, nullptr, nullptr, nullptr, nullptr, nullptr, C_, C_, 0);
}

// round 13
// speedup vs baseline: 2.7848x; 1.0231x over previous
#include <cuda_runtime.h>
#include <cuda_bf16.h>
#include <cuda_fp16.h>
#include <math.h>
#include <stdint.h>

#define B_   2
#define T_   2048
#define C_   2048
#define NH   16
#define NKV  4
#define HD   128
#define QSCL  0.1275495818259719f            // (1/sqrt(128)) * log2(e)

// ---------------------------------------------------------------------------
// Scratch (device globals; no allocation allowed)
// ---------------------------------------------------------------------------
__device__ __half g_xs [(size_t)B_ * T_ * C_];                // f16 x
__device__ __half g_wh [(size_t)3 * C_ / 2 * C_];             // [wq;wk;wv] f16 (3072 x 2048)
__device__ __half g_qh [(size_t)B_ * NH  * T_ * HD];          // Q f16 (QSCL-scaled, roped)
__device__ __half g_kh [(size_t)B_ * NKV * T_ * HD];          // K f16 (roped)
__device__ __half g_vh [(size_t)B_ * NKV * T_ * HD];          // V f16
__device__ __half g_yh [(size_t)B_ * T_ * C_];                // attn out f16
__device__ __half g_woh[(size_t)C_ * C_];                     // wo f16

// ---------------------------------------------------------------------------
// PTX helpers — arch-agnostic (sm_80+)
// ---------------------------------------------------------------------------
__device__ __forceinline__ uint32_t smem_u32(const void* p) {
    uint32_t a;
    asm("{ .reg .u64 t; cvta.to.shared.u64 t, %1; cvt.u32.u64 %0, t; }"
        : "=r"(a) : "l"(p));
    return a;
}
__device__ __forceinline__ void cp_async16(uint32_t saddr, const void* gaddr) {
    asm volatile("cp.async.cg.shared.global [%0], [%1], 16;"
                 :: "r"(saddr), "l"(gaddr));
}
__device__ __forceinline__ void cp_commit() { asm volatile("cp.async.commit_group;"); }
template <int N> __device__ __forceinline__ void cp_wait() {
    asm volatile("cp.async.wait_group %0;" :: "n"(N));
}
__device__ __forceinline__ void ldsm4(uint32_t* r, uint32_t addr) {
    asm volatile("ldmatrix.sync.aligned.m8n8.x4.shared.b16 {%0,%1,%2,%3}, [%4];"
                 : "=r"(r[0]), "=r"(r[1]), "=r"(r[2]), "=r"(r[3]) : "r"(addr));
}
__device__ __forceinline__ void ldsm4t(uint32_t* r, uint32_t addr) {
    asm volatile("ldmatrix.sync.aligned.m8n8.x4.trans.shared.b16 {%0,%1,%2,%3}, [%4];"
                 : "=r"(r[0]), "=r"(r[1]), "=r"(r[2]), "=r"(r[3]) : "r"(addr));
}
__device__ __forceinline__ void mma_f16(float* c, const uint32_t* a,
                                        uint32_t b0, uint32_t b1) {
    asm volatile(
        "mma.sync.aligned.m16n8k16.row.col.f32.f16.f16.f32 "
        "{%0,%1,%2,%3}, {%4,%5,%6,%7}, {%8,%9}, {%0,%1,%2,%3};"
        : "+f"(c[0]), "+f"(c[1]), "+f"(c[2]), "+f"(c[3])
        : "r"(a[0]), "r"(a[1]), "r"(a[2]), "r"(a[3]), "r"(b0), "r"(b1));
}
__device__ __forceinline__ float ex2f(float x) {
    float y; asm("ex2.approx.f32 %0, %1;" : "=f"(y) : "f"(x)); return y;
}
// Pack (s0,s1) -> f16x2, exp2 once via MUFU; result IS the f16 P fragment.
__device__ __forceinline__ uint32_t ex2p(float s0, float s1) {
    uint32_t t;
    asm("{\n\tcvt.rn.f16x2.f32 %0, %2, %1;\n\t"
        "ex2.approx.f16x2 %0, %0;\n\t}"
        : "=r"(t) : "f"(s0), "f"(s1));
    return t;
}

// ---------------------------------------------------------------------------
// Merged fp32 -> f16 convert (x, wq, wo, wk, wv in one launch)
// ---------------------------------------------------------------------------
#define N4_X   (B_ * T_ * C_ / 4)        // 2097152
#define N4_WQ  (C_ * C_ / 4)             // 1048576
#define N4_WKV (NKV * HD * C_ / 4)       // 262144
#define N4_TOT (N4_X + 2 * N4_WQ + 2 * N4_WKV)

__global__ void cvt_all(const float4* __restrict__ x, const float4* __restrict__ wq,
                        const float4* __restrict__ wk, const float4* __restrict__ wv,
                        const float4* __restrict__ wo,
                        __half2* __restrict__ xs, __half2* __restrict__ wh,
                        __half2* __restrict__ woh)
{
    int i = blockIdx.x * blockDim.x + threadIdx.x;
    if (i >= N4_TOT) return;
    const float4* src; __half2* dst; int off;
    if (i < N4_X)                    { src = x;  dst = xs;  off = i; }
    else if (i < N4_X + N4_WQ)       { src = wq; dst = wh;  off = i - N4_X; }
    else if (i < N4_X + 2 * N4_WQ)   { src = wo; dst = woh; off = i - N4_X - N4_WQ; }
    else if (i < N4_X + 2 * N4_WQ + N4_WKV) {
        src = wk; dst = wh + (size_t)C_ * C_ / 2;
        off = i - N4_X - 2 * N4_WQ;
    } else {
        src = wv; dst = wh + (size_t)(C_ + NKV * HD) * C_ / 2;
        off = i - N4_X - 2 * N4_WQ - N4_WKV;
    }
    float4 v = src[off];
    dst[2 * off + 0] = __floats2half2_rn(v.x, v.y);
    dst[2 * off + 1] = __floats2half2_rn(v.z, v.w);
}

// ---------------------------------------------------------------------------
// f16 1-term GEMM (NT): acc = A * W^T, fp32 accum.  (R12 core, passing.)
// 128x128 CTA tile, BK=32, 4-stage cp.async pipeline, 256 threads (2x4 warps).
// mode 0: fp32 row-major out.
// mode 1: fused QKV epilogue — Q: RoPE+QSCL f16; K: RoPE f16; V: f16.
// ---------------------------------------------------------------------------
#define G2MAT  10240
#define GSTG   (2 * G2MAT)           // 20480
#define GSM_TOTAL (4 * GSTG)         // 81920

__global__ __launch_bounds__(256) void gemm_f16(
    const __half* __restrict__ A, const __half* __restrict__ W,
    float* __restrict__ Cout,
    __half* __restrict__ Qh, __half* __restrict__ Kh, __half* __restrict__ Vh,
    const float* __restrict__ fcos, const float* __restrict__ fsin,
    int K, int N, int mode)
{
    extern __shared__ char smem[];
    const int tid = threadIdx.x;
    const int lid = tid & 31, wid = tid >> 5;
    const int wm = wid & 1, wn = wid >> 1;
    const int bm = blockIdx.y, bn = blockIdx.x;

    const __half* Asrc = A + (size_t)bm * 128 * K;
    const __half* Wsrc = W + (size_t)bn * 128 * K;

    float acc[4][4][4];
    #pragma unroll
    for (int mi = 0; mi < 4; mi++)
        #pragma unroll
        for (int ni = 0; ni < 4; ni++)
            #pragma unroll
            for (int e = 0; e < 4; e++) acc[mi][ni][e] = 0.f;

    const int nst = K >> 5;

    auto load_stage = [&](int s) {
        char* base = smem + (s & 3) * GSTG;
        const int k0 = s << 5;
        #pragma unroll
        for (int m = 0; m < 2; m++) {
            const __half* src = (m ? Wsrc : Asrc) + k0;
            char* dst = base + m * G2MAT;
            #pragma unroll
            for (int j = 0; j < 2; j++) {
                int idx = j * 256 + tid;
                int row = idx >> 2;
                int c   = idx & 3;
                cp_async16(smem_u32(dst + row * 80 + c * 16),
                           src + (size_t)row * K + c * 8);
            }
        }
        cp_commit();
    };

    load_stage(0);
    load_stage(1);
    load_stage(2);

    for (int s = 0; s < nst; s++) {
        if (s + 3 < nst) load_stage(s + 3); else cp_commit();
        cp_wait<3>();
        __syncthreads();

        const uint32_t sb = smem_u32(smem + (s & 3) * GSTG);
        #pragma unroll
        for (int kk = 0; kk < 2; kk++) {
            uint32_t ah[4][4], bh[2][4];
            const int arow  = wm * 64 + (lid & 15);
            const int akcol = kk * 16 + ((lid & 16) ? 8 : 0);
            #pragma unroll
            for (int mi = 0; mi < 4; mi++)
                ldsm4(ah[mi], sb + (arow + mi * 16) * 80 + akcol * 2);
            const int brow  = wn * 32 + (lid & 7) + ((lid & 16) ? 8 : 0);
            const int bkcol = kk * 16 + ((lid & 8) ? 8 : 0);
            #pragma unroll
            for (int p = 0; p < 2; p++)
                ldsm4(bh[p], sb + G2MAT + (brow + p * 16) * 80 + bkcol * 2);
            #pragma unroll
            for (int mi = 0; mi < 4; mi++)
                #pragma unroll
                for (int ni = 0; ni < 4; ni++) {
                    const int p = ni >> 1, q = (ni & 1) * 2;
                    mma_f16(acc[mi][ni], ah[mi], bh[p][q], bh[p][q + 1]);
                }
        }
        __syncthreads();
    }

    const int r0c = lid >> 2, cc = (lid & 3) * 2;
    #pragma unroll
    for (int mi = 0; mi < 4; mi++) {
        #pragma unroll
        for (int ni = 0; ni < 4; ni++) {
            int row = bm * 128 + wm * 64 + mi * 16 + r0c;
            int col = bn * 128 + wn * 32 + ni * 8 + cc;
            #pragma unroll
            for (int half = 0; half < 2; half++) {
                int rr = row + half * 8;
                float v0 = acc[mi][ni][half * 2], v1 = acc[mi][ni][half * 2 + 1];
                if (mode == 0) {
                    *(float2*)(Cout + (size_t)rr * N + col) = make_float2(v0, v1);
                } else {
                    const int b = rr >> 11, t = rr & (T_ - 1);
                    const int ht = col >> 7, d = col & (HD - 1);
                    if (ht < NH) {          // Q: RoPE + QSCL
                        float c = fcos[t * 64 + (d >> 1)];
                        float sn = fsin[t * 64 + (d >> 1)];
                        float r0 = (v0 * c - v1 * sn) * QSCL;
                        float r1 = (v0 * sn + v1 * c) * QSCL;
                        *(__half2*)(Qh + ((((size_t)b * NH + ht) * T_ + t) * HD + d)) =
                            __floats2half2_rn(r0, r1);
                    } else if (ht < NH + NKV) {   // K: RoPE
                        int h = ht - NH;
                        float c = fcos[t * 64 + (d >> 1)];
                        float sn = fsin[t * 64 + (d >> 1)];
                        float r0 = v0 * c - v1 * sn;
                        float r1 = v0 * sn + v1 * c;
                        size_t off = (((size_t)b * NKV + h) * T_ + t) * HD + d;
                        *(__half2*)(Kh + off) = __floats2half2_rn(r0, r1);
                    } else {                      // V
                        int h = ht - NH - NKV;
                        size_t off = (((size_t)b * NKV + h) * T_ + t) * HD + d;
                        *(__half2*)(Vh + off) = __floats2half2_rn(v0, v1);
                    }
                }
            }
        }
    }
}

// ---------------------------------------------------------------------------
// Tensor-core causal flash attention — all f16 operands.
// S = Q K^T; softmax via ex2.f16x2; row sums l via mma with all-ones B
// (full cross-quad reduction in the tensor core — no shuffles, no unpacks).
// ---------------------------------------------------------------------------
#define AROWB  272
#define AQMAT  34816                 // 128 * 272
#define AKVMAT 17408                 // 64 * 272
#define AKVST  (2 * AKVMAT)
#define ASM_TOTAL (AQMAT + 2 * AKVST)   // 104448
#define ONES2  0x3C003C00u           // f16x2 {1.0, 1.0}

__global__ __launch_bounds__(256, 1) void attn_mma(
    const __half* __restrict__ Qh,
    const __half* __restrict__ Kh, const __half* __restrict__ Vh,
    __half* __restrict__ Yh)
{
    extern __shared__ char smem[];
    const int tid = threadIdx.x;
    const int lid = tid & 31, wid = tid >> 5;
    const int qt = (T_ / 128 - 1) - blockIdx.x;
    const int bh = blockIdx.y;
    const int b  = bh >> 4, h = bh & 15;
    const int kvh = h >> 2;

    const size_t qg = ((size_t)(b * NH + h) * T_ + qt * 128) * HD;
    const size_t kg = (size_t)(b * NKV + kvh) * T_ * HD;

    const uint32_t sQ   = smem_u32(smem);
    const uint32_t sKV0 = sQ + AQMAT;

    {   // Q: 2048 16B-chunks
        #pragma unroll
        for (int i = 0; i < 8; i++) {
            int idx = i * 256 + tid;
            int row = idx >> 4, c = idx & 15;
            cp_async16(sQ + row * AROWB + c * 16, Qh + qg + (size_t)row * HD + c * 8);
        }
    }
    const __half* kvsrc[2] = {Kh, Vh};
    auto load_kv = [&](int kt, int st) {
        uint32_t sb = sKV0 + st * AKVST;
        const size_t base = kg + (size_t)kt * 64 * HD;
        #pragma unroll
        for (int i = 0; i < 8; i++) {
            int idx = i * 256 + tid;
            int mat = idx >> 10;
            int rem = idx & 1023;
            int row = rem >> 4, c = rem & 15;
            cp_async16(sb + mat * AKVMAT + row * AROWB + c * 16,
                       kvsrc[mat] + base + (size_t)row * HD + c * 8);
        }
        cp_commit();
    };
    load_kv(0, 0);

    float oacc[16][4];
    #pragma unroll
    for (int jn = 0; jn < 16; jn++)
        #pragma unroll
        for (int e = 0; e < 4; e++) oacc[jn][e] = 0.f;
    float mrow[2] = {-1e30f, -1e30f};
    float lrow[2] = {0.f, 0.f};

    const int nkt = 2 * qt + 2;

    for (int kt = 0; kt < nkt; kt++) {
        if (kt + 1 < nkt) { load_kv(kt + 1, (kt + 1) & 1); cp_wait<1>(); }
        else              { cp_wait<0>(); }
        __syncthreads();

        const uint32_t sb = sKV0 + (kt & 1) * AKVST;
        const uint32_t sK = sb, sV = sb + AKVMAT;

        // ---- S = Q K^T
        float sacc[8][4];
        #pragma unroll
        for (int j = 0; j < 8; j++)
            #pragma unroll
            for (int e = 0; e < 4; e++) sacc[j][e] = 0.f;

        #pragma unroll
        for (int kk = 0; kk < 8; kk++) {
            uint32_t ah[4];
            const int arow  = wid * 16 + (lid & 15);
            const int akcol = kk * 16 + ((lid & 16) ? 8 : 0);
            ldsm4(ah, sQ + arow * AROWB + akcol * 2);
            #pragma unroll
            for (int np = 0; np < 4; np++) {
                uint32_t bh4[4];
                const int brow  = np * 16 + (lid & 7) + ((lid & 16) ? 8 : 0);
                const int bkcol = kk * 16 + ((lid & 8) ? 8 : 0);
                ldsm4(bh4, sK + brow * AROWB + bkcol * 2);
                #pragma unroll
                for (int jj = 0; jj < 2; jj++) {
                    const int j = 2 * np + jj, q = jj * 2;
                    mma_f16(sacc[j], ah, bh4[q], bh4[q + 1]);
                }
            }
        }

        // ---- causal mask (diagonal tiles only)
        const int kv0 = kt * 64;
        if (kv0 + 63 > qt * 128) {
            const int rbase = qt * 128 + wid * 16 + (lid >> 2);
            #pragma unroll
            for (int j = 0; j < 8; j++)
                #pragma unroll
                for (int e = 0; e < 4; e++) {
                    int col = kv0 + j * 8 + 2 * (lid & 3) + (e & 1);
                    int row = rbase + (e >> 1) * 8;
                    if (col > row) sacc[j][e] = -1e30f;
                }
        }

        // ---- online softmax: row max (shuffles), exp (f16x2 MUFU),
        //      row sums via mma against all-ones B (no unpack, no shuffles)
        float mnew[2];
        #pragma unroll
        for (int h2 = 0; h2 < 2; h2++) {
            float tm = -1e30f;
            #pragma unroll
            for (int j = 0; j < 8; j++)
                tm = fmaxf(tm, fmaxf(sacc[j][h2 * 2], sacc[j][h2 * 2 + 1]));
            tm = fmaxf(tm, __shfl_xor_sync(0xffffffffu, tm, 1));
            tm = fmaxf(tm, __shfl_xor_sync(0xffffffffu, tm, 2));
            mnew[h2] = fmaxf(mrow[h2], tm);
        }

        uint32_t pfrag[8][2];
        #pragma unroll
        for (int j = 0; j < 8; j++) {
            pfrag[j][0] = ex2p(sacc[j][0] - mnew[0], sacc[j][1] - mnew[0]);
            pfrag[j][1] = ex2p(sacc[j][2] - mnew[1], sacc[j][3] - mnew[1]);
        }

        float lacc[4] = {0.f, 0.f, 0.f, 0.f};
        #pragma unroll
        for (int ks = 0; ks < 4; ks++) {
            uint32_t pf[4];
            pf[0] = pfrag[2 * ks][0];
            pf[1] = pfrag[2 * ks][1];
            pf[2] = pfrag[2 * ks + 1][0];
            pf[3] = pfrag[2 * ks + 1][1];
            mma_f16(lacc, pf, ONES2, ONES2);
        }
        // lacc[0] = full row sum (row r), lacc[2] = row r+8.

        #pragma unroll
        for (int h2 = 0; h2 < 2; h2++) {
            float corr = ex2f(mrow[h2] - mnew[h2]);
            lrow[h2] = lrow[h2] * corr + (h2 ? lacc[2] : lacc[0]);
            mrow[h2] = mnew[h2];
            #pragma unroll
            for (int jn = 0; jn < 16; jn++) {
                oacc[jn][h2 * 2]     *= corr;
                oacc[jn][h2 * 2 + 1] *= corr;
            }
        }

        // ---- O += P V
        #pragma unroll
        for (int ks = 0; ks < 4; ks++) {
            uint32_t pf[4];
            pf[0] = pfrag[2 * ks][0];
            pf[1] = pfrag[2 * ks][1];
            pf[2] = pfrag[2 * ks + 1][0];
            pf[3] = pfrag[2 * ks + 1][1];
            #pragma unroll
            for (int np = 0; np < 8; np++) {
                uint32_t vh4[4];
                const int vrow = ks * 16 + (lid & 7) + 8 * ((lid >> 3) & 1);
                const int vcol = np * 16 + 8 * (lid >> 4);
                ldsm4t(vh4, sV + vrow * AROWB + vcol * 2);
                #pragma unroll
                for (int jj = 0; jj < 2; jj++) {
                    const int jn = 2 * np + jj, q = jj * 2;
                    mma_f16(oacc[jn], pf, vh4[q], vh4[q + 1]);
                }
            }
        }
        __syncthreads();
    }

    // ---- epilogue: normalize, write f16 y[b, t, h*128 + d]
    #pragma unroll
    for (int h2 = 0; h2 < 2; h2++) {
        float inv = 1.f / lrow[h2];
        int row_t = qt * 128 + wid * 16 + (lid >> 2) + 8 * h2;
        size_t base = ((size_t)b * T_ + row_t) * C_ + h * HD;
        #pragma unroll
        for (int jn = 0; jn < 16; jn++) {
            int col = jn * 8 + 2 * (lid & 3);
            *(__half2*)(Yh + base + col) =
                __floats2half2_rn(oacc[jn][h2 * 2] * inv, oacc[jn][h2 * 2 + 1] * inv);
        }
    }
}

// ---------------------------------------------------------------------------
extern "C" void kernel_launch(void* const* d_in, const int* in_sizes, int n_in,
                              void* d_out, int out_size)
{
    const float* x    = (const float*)d_in[0];
    const float* fcos = (const float*)d_in[1];
    const float* fsin = (const float*)d_in[2];
    const float* wq   = (const float*)d_in[3];
    const float* wk   = (const float*)d_in[4];
    const float* wv   = (const float*)d_in[5];
    const float* wo   = (const float*)d_in[6];
    float* out = (float*)d_out;

    __half *xs, *wh, *qh, *kh, *vh, *yh, *woh;
    cudaGetSymbolAddress((void**)&xs,  g_xs);
    cudaGetSymbolAddress((void**)&wh,  g_wh);
    cudaGetSymbolAddress((void**)&qh,  g_qh);
    cudaGetSymbolAddress((void**)&kh,  g_kh);
    cudaGetSymbolAddress((void**)&vh,  g_vh);
    cudaGetSymbolAddress((void**)&yh,  g_yh);
    cudaGetSymbolAddress((void**)&woh, g_woh);

    const int M  = B_ * T_;    // 4096
    const int NW_ = NKV * HD;  // 512
    const int NQKV = C_ + 2 * NW_;  // 3072

    // Single merged convert launch: x, wq, wo, wk, wv -> f16
    cvt_all<<<(N4_TOT + 255) / 256, 256>>>(
        (const float4*)x, (const float4*)wq, (const float4*)wk,
        (const float4*)wv, (const float4*)wo,
        (__half2*)xs, (__half2*)wh, (__half2*)woh);

    cudaFuncSetAttribute(gemm_f16, cudaFuncAttributeMaxDynamicSharedMemorySize, GSM_TOTAL);
    cudaFuncSetAttribute(attn_mma, cudaFuncAttributeMaxDynamicSharedMemorySize, ASM_TOTAL);

    // Merged QKV projection with fused RoPE epilogue
    gemm_f16<<<dim3(NQKV / 128, M / 128), 256, GSM_TOTAL>>>(
        xs, wh, nullptr, qh, kh, vh, fcos, fsin, C_, NQKV, 1);

    // Flash attention -> f16 y
    attn_mma<<<dim3(T_ / 128, B_ * NH), 256, ASM_TOTAL>>>(qh, kh, vh, yh);

    // Output projection (fp32 out)
    gemm_f16<<<dim3(C_ / 128, M / 128), 256, GSM_TOTAL>>>(
        yh, woh, out, nullptr, nullptr, nullptr, nullptr, nullptr, C_, C_, 0);
}

// round 14
// speedup vs baseline: 2.9578x; 1.0621x over previous
#include <cuda_runtime.h>
#include <cuda_bf16.h>
#include <cuda_fp16.h>
#include <math.h>
#include <stdint.h>

#define B_   2
#define T_   2048
#define C_   2048
#define NH   16
#define NKV  4
#define HD   128
#define QSCL  0.1275495818259719f            // (1/sqrt(128)) * log2(e)

// ---------------------------------------------------------------------------
// Scratch (device globals; no allocation allowed)
// ---------------------------------------------------------------------------
__device__ __half g_xs [(size_t)B_ * T_ * C_];                // f16 x
__device__ __half g_wh [(size_t)3 * C_ / 2 * C_];             // [wq;wk;wv] f16
__device__ __half g_qh [(size_t)B_ * NH  * T_ * HD];          // Q f16 (QSCL, roped)
__device__ __half g_kh [(size_t)B_ * NKV * T_ * HD];          // K f16 (roped)
__device__ __half g_vh [(size_t)B_ * NKV * T_ * HD];          // V f16
__device__ __half g_yh [(size_t)B_ * T_ * C_];                // attn out f16
__device__ __half g_woh[(size_t)C_ * C_];                     // wo f16

// ---------------------------------------------------------------------------
// PTX helpers — arch-agnostic (sm_80+)
// ---------------------------------------------------------------------------
__device__ __forceinline__ uint32_t smem_u32(const void* p) {
    uint32_t a;
    asm("{ .reg .u64 t; cvta.to.shared.u64 t, %1; cvt.u32.u64 %0, t; }"
        : "=r"(a) : "l"(p));
    return a;
}
__device__ __forceinline__ void cp_async16(uint32_t saddr, const void* gaddr) {
    asm volatile("cp.async.cg.shared.global [%0], [%1], 16;"
                 :: "r"(saddr), "l"(gaddr));
}
__device__ __forceinline__ void cp_commit() { asm volatile("cp.async.commit_group;"); }
template <int N> __device__ __forceinline__ void cp_wait() {
    asm volatile("cp.async.wait_group %0;" :: "n"(N));
}
__device__ __forceinline__ void ldsm4(uint32_t* r, uint32_t addr) {
    asm volatile("ldmatrix.sync.aligned.m8n8.x4.shared.b16 {%0,%1,%2,%3}, [%4];"
                 : "=r"(r[0]), "=r"(r[1]), "=r"(r[2]), "=r"(r[3]) : "r"(addr));
}
__device__ __forceinline__ void ldsm4t(uint32_t* r, uint32_t addr) {
    asm volatile("ldmatrix.sync.aligned.m8n8.x4.trans.shared.b16 {%0,%1,%2,%3}, [%4];"
                 : "=r"(r[0]), "=r"(r[1]), "=r"(r[2]), "=r"(r[3]) : "r"(addr));
}
__device__ __forceinline__ void mma_f16(float* c, const uint32_t* a,
                                        uint32_t b0, uint32_t b1) {
    asm volatile(
        "mma.sync.aligned.m16n8k16.row.col.f32.f16.f16.f32 "
        "{%0,%1,%2,%3}, {%4,%5,%6,%7}, {%8,%9}, {%0,%1,%2,%3};"
        : "+f"(c[0]), "+f"(c[1]), "+f"(c[2]), "+f"(c[3])
        : "r"(a[0]), "r"(a[1]), "r"(a[2]), "r"(a[3]), "r"(b0), "r"(b1));
}
__device__ __forceinline__ float ex2f(float x) {
    float y; asm("ex2.approx.f32 %0, %1;" : "=f"(y) : "f"(x)); return y;
}
__device__ __forceinline__ uint32_t ex2p(float s0, float s1) {
    uint32_t t;
    asm("{\n\tcvt.rn.f16x2.f32 %0, %2, %1;\n\t"
        "ex2.approx.f16x2 %0, %0;\n\t}"
        : "=r"(t) : "f"(s0), "f"(s1));
    return t;
}

// ---------------------------------------------------------------------------
// Merged fp32 -> f16 convert (x, wq, wo, wk, wv in one launch)
// ---------------------------------------------------------------------------
#define N4_X   (B_ * T_ * C_ / 4)
#define N4_WQ  (C_ * C_ / 4)
#define N4_WKV (NKV * HD * C_ / 4)
#define N4_TOT (N4_X + 2 * N4_WQ + 2 * N4_WKV)

__global__ void cvt_all(const float4* __restrict__ x, const float4* __restrict__ wq,
                        const float4* __restrict__ wk, const float4* __restrict__ wv,
                        const float4* __restrict__ wo,
                        __half2* __restrict__ xs, __half2* __restrict__ wh,
                        __half2* __restrict__ woh)
{
    int i = blockIdx.x * blockDim.x + threadIdx.x;
    if (i >= N4_TOT) return;
    const float4* src; __half2* dst; int off;
    if (i < N4_X)                    { src = x;  dst = xs;  off = i; }
    else if (i < N4_X + N4_WQ)       { src = wq; dst = wh;  off = i - N4_X; }
    else if (i < N4_X + 2 * N4_WQ)   { src = wo; dst = woh; off = i - N4_X - N4_WQ; }
    else if (i < N4_X + 2 * N4_WQ + N4_WKV) {
        src = wk; dst = wh + (size_t)C_ * C_ / 2;
        off = i - N4_X - 2 * N4_WQ;
    } else {
        src = wv; dst = wh + (size_t)(C_ + NKV * HD) * C_ / 2;
        off = i - N4_X - 2 * N4_WQ - N4_WKV;
    }
    float4 v = src[off];
    dst[2 * off + 0] = __floats2half2_rn(v.x, v.y);
    dst[2 * off + 1] = __floats2half2_rn(v.z, v.w);
}

// ---------------------------------------------------------------------------
// f16 1-term GEMM (NT): acc = A * W^T, fp32 accum.
// 128x128 CTA tile, BK=64 per stage (4 kk between barriers), 2-stage cp.async,
// 256 threads (2x4 warps), row pitch 144B (64 halfs + 16B pad, conflict-free).
// mode 0: fp32 row-major out.
// mode 1: fused QKV epilogue — Q: RoPE+QSCL f16; K: RoPE f16; V: f16.
// ---------------------------------------------------------------------------
#define GROW   144
#define GMAT   (128 * GROW)          // 18432
#define GSTG   (2 * GMAT)            // 36864
#define GSM_TOTAL (2 * GSTG)         // 73728

__global__ __launch_bounds__(256) void gemm_f16(
    const __half* __restrict__ A, const __half* __restrict__ W,
    float* __restrict__ Cout,
    __half* __restrict__ Qh, __half* __restrict__ Kh, __half* __restrict__ Vh,
    const float* __restrict__ fcos, const float* __restrict__ fsin,
    int K, int N, int mode)
{
    extern __shared__ char smem[];
    const int tid = threadIdx.x;
    const int lid = tid & 31, wid = tid >> 5;
    const int wm = wid & 1, wn = wid >> 1;
    const int bm = blockIdx.y, bn = blockIdx.x;

    const __half* Asrc = A + (size_t)bm * 128 * K;
    const __half* Wsrc = W + (size_t)bn * 128 * K;

    float acc[4][4][4];
    #pragma unroll
    for (int mi = 0; mi < 4; mi++)
        #pragma unroll
        for (int ni = 0; ni < 4; ni++)
            #pragma unroll
            for (int e = 0; e < 4; e++) acc[mi][ni][e] = 0.f;

    const int nst = K >> 6;   // stages of BK=64

    auto load_stage = [&](int s) {
        char* base = smem + (s & 1) * GSTG;
        const int k0 = s << 6;
        #pragma unroll
        for (int m = 0; m < 2; m++) {
            const __half* src = (m ? Wsrc : Asrc) + k0;
            char* dst = base + m * GMAT;
            #pragma unroll
            for (int j = 0; j < 4; j++) {           // 1024 chunks per mat
                int idx = j * 256 + tid;
                int row = idx >> 3;
                int c   = idx & 7;
                cp_async16(smem_u32(dst + row * GROW + c * 16),
                           src + (size_t)row * K + c * 8);
            }
        }
        cp_commit();
    };

    load_stage(0);

    for (int s = 0; s < nst; s++) {
        if (s + 1 < nst) { load_stage(s + 1); cp_wait<1>(); }
        else             { cp_wait<0>(); }
        __syncthreads();

        const uint32_t sb = smem_u32(smem + (s & 1) * GSTG);
        #pragma unroll
        for (int kk = 0; kk < 4; kk++) {
            uint32_t ah[4][4], bh[2][4];
            const int arow  = wm * 64 + (lid & 15);
            const int akcol = kk * 16 + ((lid & 16) ? 8 : 0);
            #pragma unroll
            for (int mi = 0; mi < 4; mi++)
                ldsm4(ah[mi], sb + (arow + mi * 16) * GROW + akcol * 2);
            const int brow  = wn * 32 + (lid & 7) + ((lid & 16) ? 8 : 0);
            const int bkcol = kk * 16 + ((lid & 8) ? 8 : 0);
            #pragma unroll
            for (int p = 0; p < 2; p++)
                ldsm4(bh[p], sb + GMAT + (brow + p * 16) * GROW + bkcol * 2);
            #pragma unroll
            for (int mi = 0; mi < 4; mi++)
                #pragma unroll
                for (int ni = 0; ni < 4; ni++) {
                    const int p = ni >> 1, q = (ni & 1) * 2;
                    mma_f16(acc[mi][ni], ah[mi], bh[p][q], bh[p][q + 1]);
                }
        }
        __syncthreads();
    }

    const int r0c = lid >> 2, cc = (lid & 3) * 2;
    #pragma unroll
    for (int mi = 0; mi < 4; mi++) {
        #pragma unroll
        for (int ni = 0; ni < 4; ni++) {
            int row = bm * 128 + wm * 64 + mi * 16 + r0c;
            int col = bn * 128 + wn * 32 + ni * 8 + cc;
            #pragma unroll
            for (int half = 0; half < 2; half++) {
                int rr = row + half * 8;
                float v0 = acc[mi][ni][half * 2], v1 = acc[mi][ni][half * 2 + 1];
                if (mode == 0) {
                    *(float2*)(Cout + (size_t)rr * N + col) = make_float2(v0, v1);
                } else {
                    const int b = rr >> 11, t = rr & (T_ - 1);
                    const int ht = col >> 7, d = col & (HD - 1);
                    if (ht < NH) {          // Q: RoPE + QSCL
                        float c = fcos[t * 64 + (d >> 1)];
                        float sn = fsin[t * 64 + (d >> 1)];
                        float r0 = (v0 * c - v1 * sn) * QSCL;
                        float r1 = (v0 * sn + v1 * c) * QSCL;
                        *(__half2*)(Qh + ((((size_t)b * NH + ht) * T_ + t) * HD + d)) =
                            __floats2half2_rn(r0, r1);
                    } else if (ht < NH + NKV) {   // K: RoPE
                        int h = ht - NH;
                        float c = fcos[t * 64 + (d >> 1)];
                        float sn = fsin[t * 64 + (d >> 1)];
                        float r0 = v0 * c - v1 * sn;
                        float r1 = v0 * sn + v1 * c;
                        size_t off = (((size_t)b * NKV + h) * T_ + t) * HD + d;
                        *(__half2*)(Kh + off) = __floats2half2_rn(r0, r1);
                    } else {                      // V
                        int h = ht - NH - NKV;
                        size_t off = (((size_t)b * NKV + h) * T_ + t) * HD + d;
                        *(__half2*)(Vh + off) = __floats2half2_rn(v0, v1);
                    }
                }
            }
        }
    }
}

// ---------------------------------------------------------------------------
// Tensor-core causal flash attention — all f16 operands.
// 3-stage KV pipeline (depth-2 prefetch); row sums l via mma vs all-ones B.
// ---------------------------------------------------------------------------
#define AROWB  272
#define AQMAT  34816                 // 128 * 272
#define AKVMAT 17408                 // 64 * 272
#define AKVST  (2 * AKVMAT)
#define ASM_TOTAL (AQMAT + 3 * AKVST)   // 139264
#define ONES2  0x3C003C00u           // f16x2 {1.0, 1.0}

__global__ __launch_bounds__(256, 1) void attn_mma(
    const __half* __restrict__ Qh,
    const __half* __restrict__ Kh, const __half* __restrict__ Vh,
    __half* __restrict__ Yh)
{
    extern __shared__ char smem[];
    const int tid = threadIdx.x;
    const int lid = tid & 31, wid = tid >> 5;
    const int qt = (T_ / 128 - 1) - blockIdx.x;
    const int bh = blockIdx.y;
    const int b  = bh >> 4, h = bh & 15;
    const int kvh = h >> 2;

    const size_t qg = ((size_t)(b * NH + h) * T_ + qt * 128) * HD;
    const size_t kg = (size_t)(b * NKV + kvh) * T_ * HD;

    const uint32_t sQ   = smem_u32(smem);
    const uint32_t sKV0 = sQ + AQMAT;

    {   // Q: 2048 16B-chunks (grouped with stage-0 commit)
        #pragma unroll
        for (int i = 0; i < 8; i++) {
            int idx = i * 256 + tid;
            int row = idx >> 4, c = idx & 15;
            cp_async16(sQ + row * AROWB + c * 16, Qh + qg + (size_t)row * HD + c * 8);
        }
    }
    const __half* kvsrc[2] = {Kh, Vh};
    auto load_kv = [&](int kt, int st) {
        uint32_t sb = sKV0 + st * AKVST;
        const size_t base = kg + (size_t)kt * 64 * HD;
        #pragma unroll
        for (int i = 0; i < 8; i++) {
            int idx = i * 256 + tid;
            int mat = idx >> 10;
            int rem = idx & 1023;
            int row = rem >> 4, c = rem & 15;
            cp_async16(sb + mat * AKVMAT + row * AROWB + c * 16,
                       kvsrc[mat] + base + (size_t)row * HD + c * 8);
        }
        cp_commit();
    };

    const int nkt = 2 * qt + 2;
    load_kv(0, 0);
    load_kv(1, 1);

    float oacc[16][4];
    #pragma unroll
    for (int jn = 0; jn < 16; jn++)
        #pragma unroll
        for (int e = 0; e < 4; e++) oacc[jn][e] = 0.f;
    float mrow[2] = {-1e30f, -1e30f};
    float lrow[2] = {0.f, 0.f};

    for (int kt = 0; kt < nkt; kt++) {
        // depth-2 prefetch with constant group accounting (empty commit at tail)
        if (kt + 2 < nkt) {
            int st = (kt + 2) % 3;
            load_kv(kt + 2, st);
        } else {
            cp_commit();
        }
        cp_wait<2>();
        __syncthreads();

        const uint32_t sb = sKV0 + (kt % 3) * AKVST;
        const uint32_t sK = sb, sV = sb + AKVMAT;

        // ---- S = Q K^T
        float sacc[8][4];
        #pragma unroll
        for (int j = 0; j < 8; j++)
            #pragma unroll
            for (int e = 0; e < 4; e++) sacc[j][e] = 0.f;

        #pragma unroll
        for (int kk = 0; kk < 8; kk++) {
            uint32_t ah[4];
            const int arow  = wid * 16 + (lid & 15);
            const int akcol = kk * 16 + ((lid & 16) ? 8 : 0);
            ldsm4(ah, sQ + arow * AROWB + akcol * 2);
            #pragma unroll
            for (int np = 0; np < 4; np++) {
                uint32_t bh4[4];
                const int brow  = np * 16 + (lid & 7) + ((lid & 16) ? 8 : 0);
                const int bkcol = kk * 16 + ((lid & 8) ? 8 : 0);
                ldsm4(bh4, sK + brow * AROWB + bkcol * 2);
                #pragma unroll
                for (int jj = 0; jj < 2; jj++) {
                    const int j = 2 * np + jj, q = jj * 2;
                    mma_f16(sacc[j], ah, bh4[q], bh4[q + 1]);
                }
            }
        }

        // ---- causal mask (diagonal tiles only)
        const int kv0 = kt * 64;
        if (kv0 + 63 > qt * 128) {
            const int rbase = qt * 128 + wid * 16 + (lid >> 2);
            #pragma unroll
            for (int j = 0; j < 8; j++)
                #pragma unroll
                for (int e = 0; e < 4; e++) {
                    int col = kv0 + j * 8 + 2 * (lid & 3) + (e & 1);
                    int row = rbase + (e >> 1) * 8;
                    if (col > row) sacc[j][e] = -1e30f;
                }
        }

        // ---- online softmax: row max, f16x2 exp -> P fragments, l via mma
        float mnew[2];
        #pragma unroll
        for (int h2 = 0; h2 < 2; h2++) {
            float tm = -1e30f;
            #pragma unroll
            for (int j = 0; j < 8; j++)
                tm = fmaxf(tm, fmaxf(sacc[j][h2 * 2], sacc[j][h2 * 2 + 1]));
            tm = fmaxf(tm, __shfl_xor_sync(0xffffffffu, tm, 1));
            tm = fmaxf(tm, __shfl_xor_sync(0xffffffffu, tm, 2));
            mnew[h2] = fmaxf(mrow[h2], tm);
        }

        uint32_t pfrag[8][2];
        #pragma unroll
        for (int j = 0; j < 8; j++) {
            pfrag[j][0] = ex2p(sacc[j][0] - mnew[0], sacc[j][1] - mnew[0]);
            pfrag[j][1] = ex2p(sacc[j][2] - mnew[1], sacc[j][3] - mnew[1]);
        }

        float lacc[4] = {0.f, 0.f, 0.f, 0.f};
        #pragma unroll
        for (int ks = 0; ks < 4; ks++) {
            uint32_t pf[4];
            pf[0] = pfrag[2 * ks][0];
            pf[1] = pfrag[2 * ks][1];
            pf[2] = pfrag[2 * ks + 1][0];
            pf[3] = pfrag[2 * ks + 1][1];
            mma_f16(lacc, pf, ONES2, ONES2);
        }

        #pragma unroll
        for (int h2 = 0; h2 < 2; h2++) {
            float corr = ex2f(mrow[h2] - mnew[h2]);
            lrow[h2] = lrow[h2] * corr + (h2 ? lacc[2] : lacc[0]);
            mrow[h2] = mnew[h2];
            #pragma unroll
            for (int jn = 0; jn < 16; jn++) {
                oacc[jn][h2 * 2]     *= corr;
                oacc[jn][h2 * 2 + 1] *= corr;
            }
        }

        // ---- O += P V
        #pragma unroll
        for (int ks = 0; ks < 4; ks++) {
            uint32_t pf[4];
            pf[0] = pfrag[2 * ks][0];
            pf[1] = pfrag[2 * ks][1];
            pf[2] = pfrag[2 * ks + 1][0];
            pf[3] = pfrag[2 * ks + 1][1];
            #pragma unroll
            for (int np = 0; np < 8; np++) {
                uint32_t vh4[4];
                const int vrow = ks * 16 + (lid & 7) + 8 * ((lid >> 3) & 1);
                const int vcol = np * 16 + 8 * (lid >> 4);
                ldsm4t(vh4, sV + vrow * AROWB + vcol * 2);
                #pragma unroll
                for (int jj = 0; jj < 2; jj++) {
                    const int jn = 2 * np + jj, q = jj * 2;
                    mma_f16(oacc[jn], pf, vh4[q], vh4[q + 1]);
                }
            }
        }
        __syncthreads();
    }

    // ---- epilogue: normalize, write f16 y[b, t, h*128 + d]
    #pragma unroll
    for (int h2 = 0; h2 < 2; h2++) {
        float inv = 1.f / lrow[h2];
        int row_t = qt * 128 + wid * 16 + (lid >> 2) + 8 * h2;
        size_t base = ((size_t)b * T_ + row_t) * C_ + h * HD;
        #pragma unroll
        for (int jn = 0; jn < 16; jn++) {
            int col = jn * 8 + 2 * (lid & 3);
            *(__half2*)(Yh + base + col) =
                __floats2half2_rn(oacc[jn][h2 * 2] * inv, oacc[jn][h2 * 2 + 1] * inv);
        }
    }
}

// ---------------------------------------------------------------------------
extern "C" void kernel_launch(void* const* d_in, const int* in_sizes, int n_in,
                              void* d_out, int out_size)
{
    const float* x    = (const float*)d_in[0];
    const float* fcos = (const float*)d_in[1];
    const float* fsin = (const float*)d_in[2];
    const float* wq   = (const float*)d_in[3];
    const float* wk   = (const float*)d_in[4];
    const float* wv   = (const float*)d_in[5];
    const float* wo   = (const float*)d_in[6];
    float* out = (float*)d_out;

    __half *xs, *wh, *qh, *kh, *vh, *yh, *woh;
    cudaGetSymbolAddress((void**)&xs,  g_xs);
    cudaGetSymbolAddress((void**)&wh,  g_wh);
    cudaGetSymbolAddress((void**)&qh,  g_qh);
    cudaGetSymbolAddress((void**)&kh,  g_kh);
    cudaGetSymbolAddress((void**)&vh,  g_vh);
    cudaGetSymbolAddress((void**)&yh,  g_yh);
    cudaGetSymbolAddress((void**)&woh, g_woh);

    const int M  = B_ * T_;    // 4096
    const int NW_ = NKV * HD;  // 512
    const int NQKV = C_ + 2 * NW_;  // 3072

    // Single merged convert launch: x, wq, wo, wk, wv -> f16
    cvt_all<<<(N4_TOT + 255) / 256, 256>>>(
        (const float4*)x, (const float4*)wq, (const float4*)wk,
        (const float4*)wv, (const float4*)wo,
        (__half2*)xs, (__half2*)wh, (__half2*)woh);

    cudaFuncSetAttribute(gemm_f16, cudaFuncAttributeMaxDynamicSharedMemorySize, GSM_TOTAL);
    cudaFuncSetAttribute(attn_mma, cudaFuncAttributeMaxDynamicSharedMemorySize, ASM_TOTAL);

    // Merged QKV projection with fused RoPE epilogue
    gemm_f16<<<dim3(NQKV / 128, M / 128), 256, GSM_TOTAL>>>(
        xs, wh, nullptr, qh, kh, vh, fcos, fsin, C_, NQKV, 1);

    // Flash attention -> f16 y
    attn_mma<<<dim3(T_ / 128, B_ * NH), 256, ASM_TOTAL>>>(qh, kh, vh, yh);

    // Output projection (fp32 out)
    gemm_f16<<<dim3(C_ / 128, M / 128), 256, GSM_TOTAL>>>(
        yh, woh, out, nullptr, nullptr, nullptr, nullptr, nullptr, C_, C_, 0);
}

// round 15
// speedup vs baseline: 3.0542x; 1.0326x over previous
#include <cuda_runtime.h>
#include <cuda_bf16.h>
#include <cuda_fp16.h>
#include <math.h>
#include <stdint.h>

#define B_   2
#define T_   2048
#define C_   2048
#define NH   16
#define NKV  4
#define HD   128
#define QSCL  0.1275495818259719f            // (1/sqrt(128)) * log2(e)

// ---------------------------------------------------------------------------
// Scratch (device globals; no allocation allowed)
// ---------------------------------------------------------------------------
__device__ __half g_xs [(size_t)B_ * T_ * C_];                // f16 x
__device__ __half g_wh [(size_t)3 * C_ / 2 * C_];             // [wq;wk;wv] f16
__device__ __half g_qh [(size_t)B_ * NH  * T_ * HD];          // Q f16 (QSCL, roped)
__device__ __half g_kh [(size_t)B_ * NKV * T_ * HD];          // K f16 (roped)
__device__ __half g_vh [(size_t)B_ * NKV * T_ * HD];          // V f16
__device__ __half g_yh [(size_t)B_ * T_ * C_];                // attn out f16
__device__ __half g_woh[(size_t)C_ * C_];                     // wo f16

// ---------------------------------------------------------------------------
// PTX helpers — arch-agnostic (sm_80+)
// ---------------------------------------------------------------------------
__device__ __forceinline__ uint32_t smem_u32(const void* p) {
    uint32_t a;
    asm("{ .reg .u64 t; cvta.to.shared.u64 t, %1; cvt.u32.u64 %0, t; }"
        : "=r"(a) : "l"(p));
    return a;
}
__device__ __forceinline__ void cp_async16(uint32_t saddr, const void* gaddr) {
    asm volatile("cp.async.cg.shared.global [%0], [%1], 16;"
                 :: "r"(saddr), "l"(gaddr));
}
__device__ __forceinline__ void cp_commit() { asm volatile("cp.async.commit_group;"); }
template <int N> __device__ __forceinline__ void cp_wait() {
    asm volatile("cp.async.wait_group %0;" :: "n"(N));
}
__device__ __forceinline__ void ldsm4(uint32_t* r, uint32_t addr) {
    asm volatile("ldmatrix.sync.aligned.m8n8.x4.shared.b16 {%0,%1,%2,%3}, [%4];"
                 : "=r"(r[0]), "=r"(r[1]), "=r"(r[2]), "=r"(r[3]) : "r"(addr));
}
__device__ __forceinline__ void ldsm4t(uint32_t* r, uint32_t addr) {
    asm volatile("ldmatrix.sync.aligned.m8n8.x4.trans.shared.b16 {%0,%1,%2,%3}, [%4];"
                 : "=r"(r[0]), "=r"(r[1]), "=r"(r[2]), "=r"(r[3]) : "r"(addr));
}
__device__ __forceinline__ void mma_f16(float* c, const uint32_t* a,
                                        uint32_t b0, uint32_t b1) {
    asm volatile(
        "mma.sync.aligned.m16n8k16.row.col.f32.f16.f16.f32 "
        "{%0,%1,%2,%3}, {%4,%5,%6,%7}, {%8,%9}, {%0,%1,%2,%3};"
        : "+f"(c[0]), "+f"(c[1]), "+f"(c[2]), "+f"(c[3])
        : "r"(a[0]), "r"(a[1]), "r"(a[2]), "r"(a[3]), "r"(b0), "r"(b1));
}
__device__ __forceinline__ float ex2f(float x) {
    float y; asm("ex2.approx.f32 %0, %1;" : "=f"(y) : "f"(x)); return y;
}
__device__ __forceinline__ uint32_t ex2p(float s0, float s1) {
    uint32_t t;
    asm("{\n\tcvt.rn.f16x2.f32 %0, %2, %1;\n\t"
        "ex2.approx.f16x2 %0, %0;\n\t}"
        : "=r"(t) : "f"(s0), "f"(s1));
    return t;
}

// ---------------------------------------------------------------------------
// Merged fp32 -> f16 convert (x, wq, wo, wk, wv in one launch)
// ---------------------------------------------------------------------------
#define N4_X   (B_ * T_ * C_ / 4)
#define N4_WQ  (C_ * C_ / 4)
#define N4_WKV (NKV * HD * C_ / 4)
#define N4_TOT (N4_X + 2 * N4_WQ + 2 * N4_WKV)

__global__ void cvt_all(const float4* __restrict__ x, const float4* __restrict__ wq,
                        const float4* __restrict__ wk, const float4* __restrict__ wv,
                        const float4* __restrict__ wo,
                        __half2* __restrict__ xs, __half2* __restrict__ wh,
                        __half2* __restrict__ woh)
{
    int i = blockIdx.x * blockDim.x + threadIdx.x;
    if (i >= N4_TOT) return;
    const float4* src; __half2* dst; int off;
    if (i < N4_X)                    { src = x;  dst = xs;  off = i; }
    else if (i < N4_X + N4_WQ)       { src = wq; dst = wh;  off = i - N4_X; }
    else if (i < N4_X + 2 * N4_WQ)   { src = wo; dst = woh; off = i - N4_X - N4_WQ; }
    else if (i < N4_X + 2 * N4_WQ + N4_WKV) {
        src = wk; dst = wh + (size_t)C_ * C_ / 2;
        off = i - N4_X - 2 * N4_WQ;
    } else {
        src = wv; dst = wh + (size_t)(C_ + NKV * HD) * C_ / 2;
        off = i - N4_X - 2 * N4_WQ - N4_WKV;
    }
    float4 v = src[off];
    dst[2 * off + 0] = __floats2half2_rn(v.x, v.y);
    dst[2 * off + 1] = __floats2half2_rn(v.z, v.w);
}

// ---------------------------------------------------------------------------
// f16 1-term GEMM (NT) — R14 core, frozen (passing, tensor=49.6%).
// 128x128 CTA tile, BK=64/stage, 2-stage cp.async, 256 threads.
// ---------------------------------------------------------------------------
#define GROW   144
#define GMAT   (128 * GROW)          // 18432
#define GSTG   (2 * GMAT)            // 36864
#define GSM_TOTAL (2 * GSTG)         // 73728

__global__ __launch_bounds__(256) void gemm_f16(
    const __half* __restrict__ A, const __half* __restrict__ W,
    float* __restrict__ Cout,
    __half* __restrict__ Qh, __half* __restrict__ Kh, __half* __restrict__ Vh,
    const float* __restrict__ fcos, const float* __restrict__ fsin,
    int K, int N, int mode)
{
    extern __shared__ char smem[];
    const int tid = threadIdx.x;
    const int lid = tid & 31, wid = tid >> 5;
    const int wm = wid & 1, wn = wid >> 1;
    const int bm = blockIdx.y, bn = blockIdx.x;

    const __half* Asrc = A + (size_t)bm * 128 * K;
    const __half* Wsrc = W + (size_t)bn * 128 * K;

    float acc[4][4][4];
    #pragma unroll
    for (int mi = 0; mi < 4; mi++)
        #pragma unroll
        for (int ni = 0; ni < 4; ni++)
            #pragma unroll
            for (int e = 0; e < 4; e++) acc[mi][ni][e] = 0.f;

    const int nst = K >> 6;

    auto load_stage = [&](int s) {
        char* base = smem + (s & 1) * GSTG;
        const int k0 = s << 6;
        #pragma unroll
        for (int m = 0; m < 2; m++) {
            const __half* src = (m ? Wsrc : Asrc) + k0;
            char* dst = base + m * GMAT;
            #pragma unroll
            for (int j = 0; j < 4; j++) {
                int idx = j * 256 + tid;
                int row = idx >> 3;
                int c   = idx & 7;
                cp_async16(smem_u32(dst + row * GROW + c * 16),
                           src + (size_t)row * K + c * 8);
            }
        }
        cp_commit();
    };

    load_stage(0);

    for (int s = 0; s < nst; s++) {
        if (s + 1 < nst) { load_stage(s + 1); cp_wait<1>(); }
        else             { cp_wait<0>(); }
        __syncthreads();

        const uint32_t sb = smem_u32(smem + (s & 1) * GSTG);
        #pragma unroll
        for (int kk = 0; kk < 4; kk++) {
            uint32_t ah[4][4], bh[2][4];
            const int arow  = wm * 64 + (lid & 15);
            const int akcol = kk * 16 + ((lid & 16) ? 8 : 0);
            #pragma unroll
            for (int mi = 0; mi < 4; mi++)
                ldsm4(ah[mi], sb + (arow + mi * 16) * GROW + akcol * 2);
            const int brow  = wn * 32 + (lid & 7) + ((lid & 16) ? 8 : 0);
            const int bkcol = kk * 16 + ((lid & 8) ? 8 : 0);
            #pragma unroll
            for (int p = 0; p < 2; p++)
                ldsm4(bh[p], sb + GMAT + (brow + p * 16) * GROW + bkcol * 2);
            #pragma unroll
            for (int mi = 0; mi < 4; mi++)
                #pragma unroll
                for (int ni = 0; ni < 4; ni++) {
                    const int p = ni >> 1, q = (ni & 1) * 2;
                    mma_f16(acc[mi][ni], ah[mi], bh[p][q], bh[p][q + 1]);
                }
        }
        __syncthreads();
    }

    const int r0c = lid >> 2, cc = (lid & 3) * 2;
    #pragma unroll
    for (int mi = 0; mi < 4; mi++) {
        #pragma unroll
        for (int ni = 0; ni < 4; ni++) {
            int row = bm * 128 + wm * 64 + mi * 16 + r0c;
            int col = bn * 128 + wn * 32 + ni * 8 + cc;
            #pragma unroll
            for (int half = 0; half < 2; half++) {
                int rr = row + half * 8;
                float v0 = acc[mi][ni][half * 2], v1 = acc[mi][ni][half * 2 + 1];
                if (mode == 0) {
                    *(float2*)(Cout + (size_t)rr * N + col) = make_float2(v0, v1);
                } else {
                    const int b = rr >> 11, t = rr & (T_ - 1);
                    const int ht = col >> 7, d = col & (HD - 1);
                    if (ht < NH) {
                        float c = fcos[t * 64 + (d >> 1)];
                        float sn = fsin[t * 64 + (d >> 1)];
                        float r0 = (v0 * c - v1 * sn) * QSCL;
                        float r1 = (v0 * sn + v1 * c) * QSCL;
                        *(__half2*)(Qh + ((((size_t)b * NH + ht) * T_ + t) * HD + d)) =
                            __floats2half2_rn(r0, r1);
                    } else if (ht < NH + NKV) {
                        int h = ht - NH;
                        float c = fcos[t * 64 + (d >> 1)];
                        float sn = fsin[t * 64 + (d >> 1)];
                        float r0 = v0 * c - v1 * sn;
                        float r1 = v0 * sn + v1 * c;
                        size_t off = (((size_t)b * NKV + h) * T_ + t) * HD + d;
                        *(__half2*)(Kh + off) = __floats2half2_rn(r0, r1);
                    } else {
                        int h = ht - NH - NKV;
                        size_t off = (((size_t)b * NKV + h) * T_ + t) * HD + d;
                        *(__half2*)(Vh + off) = __floats2half2_rn(v0, v1);
                    }
                }
            }
        }
    }
}

// ---------------------------------------------------------------------------
// Tensor-core causal flash attention — BN=128 KV tiles (softmax overhead /2).
// All f16 operands; row sums via mma vs all-ones B; 2-stage KV double buffer.
// ---------------------------------------------------------------------------
#define AROWB  272
#define AQMAT  34816                 // 128 * 272
#define AKVMAT 34816                 // 128 * 272
#define AKVST  (2 * AKVMAT)          // 69632
#define ASM_TOTAL (AQMAT + 2 * AKVST)   // 174080
#define ONES2  0x3C003C00u

__global__ __launch_bounds__(256, 1) void attn_mma(
    const __half* __restrict__ Qh,
    const __half* __restrict__ Kh, const __half* __restrict__ Vh,
    __half* __restrict__ Yh)
{
    extern __shared__ char smem[];
    const int tid = threadIdx.x;
    const int lid = tid & 31, wid = tid >> 5;
    const int qt = (T_ / 128 - 1) - blockIdx.x;   // heavy tiles first
    const int bh = blockIdx.y;
    const int b  = bh >> 4, h = bh & 15;
    const int kvh = h >> 2;

    const size_t qg = ((size_t)(b * NH + h) * T_ + qt * 128) * HD;
    const size_t kg = (size_t)(b * NKV + kvh) * T_ * HD;

    const uint32_t sQ   = smem_u32(smem);
    const uint32_t sKV0 = sQ + AQMAT;

    {   // Q: 2048 16B-chunks
        #pragma unroll
        for (int i = 0; i < 8; i++) {
            int idx = i * 256 + tid;
            int row = idx >> 4, c = idx & 15;
            cp_async16(sQ + row * AROWB + c * 16, Qh + qg + (size_t)row * HD + c * 8);
        }
    }
    const __half* kvsrc[2] = {Kh, Vh};
    auto load_kv = [&](int kt, int st) {
        uint32_t sb = sKV0 + st * AKVST;
        const size_t base = kg + (size_t)kt * 128 * HD;
        #pragma unroll
        for (int i = 0; i < 16; i++) {
            int idx = i * 256 + tid;
            int mat = idx >> 11;
            int rem = idx & 2047;
            int row = rem >> 4, c = rem & 15;
            cp_async16(sb + mat * AKVMAT + row * AROWB + c * 16,
                       kvsrc[mat] + base + (size_t)row * HD + c * 8);
        }
        cp_commit();
    };
    load_kv(0, 0);

    float oacc[16][4];
    #pragma unroll
    for (int jn = 0; jn < 16; jn++)
        #pragma unroll
        for (int e = 0; e < 4; e++) oacc[jn][e] = 0.f;
    float mrow[2] = {-1e30f, -1e30f};
    float lrow[2] = {0.f, 0.f};

    const int nkt = qt + 1;       // 128-row kv tiles, causal

    for (int kt = 0; kt < nkt; kt++) {
        if (kt + 1 < nkt) { load_kv(kt + 1, (kt + 1) & 1); cp_wait<1>(); }
        else              { cp_wait<0>(); }
        __syncthreads();

        const uint32_t sb = sKV0 + (kt & 1) * AKVST;
        const uint32_t sK = sb, sV = sb + AKVMAT;

        // ---- S = Q K^T over 128 kv rows (16 n8-tiles)
        float sacc[16][4];
        #pragma unroll
        for (int j = 0; j < 16; j++)
            #pragma unroll
            for (int e = 0; e < 4; e++) sacc[j][e] = 0.f;

        #pragma unroll
        for (int kk = 0; kk < 8; kk++) {
            uint32_t ah[4];
            const int arow  = wid * 16 + (lid & 15);
            const int akcol = kk * 16 + ((lid & 16) ? 8 : 0);
            ldsm4(ah, sQ + arow * AROWB + akcol * 2);
            #pragma unroll
            for (int np = 0; np < 8; np++) {
                uint32_t bh4[4];
                const int brow  = np * 16 + (lid & 7) + ((lid & 16) ? 8 : 0);
                const int bkcol = kk * 16 + ((lid & 8) ? 8 : 0);
                ldsm4(bh4, sK + brow * AROWB + bkcol * 2);
                #pragma unroll
                for (int jj = 0; jj < 2; jj++) {
                    const int j = 2 * np + jj, q = jj * 2;
                    mma_f16(sacc[j], ah, bh4[q], bh4[q + 1]);
                }
            }
        }

        // ---- causal mask (diagonal tile only: kt == qt)
        if (kt == qt) {
            const int kv0 = kt * 128;
            const int rbase = qt * 128 + wid * 16 + (lid >> 2);
            #pragma unroll
            for (int j = 0; j < 16; j++)
                #pragma unroll
                for (int e = 0; e < 4; e++) {
                    int col = kv0 + j * 8 + 2 * (lid & 3) + (e & 1);
                    int row = rbase + (e >> 1) * 8;
                    if (col > row) sacc[j][e] = -1e30f;
                }
        }

        // ---- online softmax: row max, f16x2 exp -> P fragments, l via mma
        float mnew[2];
        #pragma unroll
        for (int h2 = 0; h2 < 2; h2++) {
            float tm = -1e30f;
            #pragma unroll
            for (int j = 0; j < 16; j++)
                tm = fmaxf(tm, fmaxf(sacc[j][h2 * 2], sacc[j][h2 * 2 + 1]));
            tm = fmaxf(tm, __shfl_xor_sync(0xffffffffu, tm, 1));
            tm = fmaxf(tm, __shfl_xor_sync(0xffffffffu, tm, 2));
            mnew[h2] = fmaxf(mrow[h2], tm);
        }

        uint32_t pfrag[16][2];
        #pragma unroll
        for (int j = 0; j < 16; j++) {
            pfrag[j][0] = ex2p(sacc[j][0] - mnew[0], sacc[j][1] - mnew[0]);
            pfrag[j][1] = ex2p(sacc[j][2] - mnew[1], sacc[j][3] - mnew[1]);
        }

        float lacc[4] = {0.f, 0.f, 0.f, 0.f};
        #pragma unroll
        for (int ks = 0; ks < 8; ks++) {
            uint32_t pf[4];
            pf[0] = pfrag[2 * ks][0];
            pf[1] = pfrag[2 * ks][1];
            pf[2] = pfrag[2 * ks + 1][0];
            pf[3] = pfrag[2 * ks + 1][1];
            mma_f16(lacc, pf, ONES2, ONES2);
        }

        #pragma unroll
        for (int h2 = 0; h2 < 2; h2++) {
            float corr = ex2f(mrow[h2] - mnew[h2]);
            lrow[h2] = lrow[h2] * corr + (h2 ? lacc[2] : lacc[0]);
            mrow[h2] = mnew[h2];
            #pragma unroll
            for (int jn = 0; jn < 16; jn++) {
                oacc[jn][h2 * 2]     *= corr;
                oacc[jn][h2 * 2 + 1] *= corr;
            }
        }

        // ---- O += P V (128 kv rows: 8 ks steps)
        #pragma unroll
        for (int ks = 0; ks < 8; ks++) {
            uint32_t pf[4];
            pf[0] = pfrag[2 * ks][0];
            pf[1] = pfrag[2 * ks][1];
            pf[2] = pfrag[2 * ks + 1][0];
            pf[3] = pfrag[2 * ks + 1][1];
            #pragma unroll
            for (int np = 0; np < 8; np++) {
                uint32_t vh4[4];
                const int vrow = ks * 16 + (lid & 7) + 8 * ((lid >> 3) & 1);
                const int vcol = np * 16 + 8 * (lid >> 4);
                ldsm4t(vh4, sV + vrow * AROWB + vcol * 2);
                #pragma unroll
                for (int jj = 0; jj < 2; jj++) {
                    const int jn = 2 * np + jj, q = jj * 2;
                    mma_f16(oacc[jn], pf, vh4[q], vh4[q + 1]);
                }
            }
        }
        __syncthreads();
    }

    // ---- epilogue: normalize, write f16 y[b, t, h*128 + d]
    #pragma unroll
    for (int h2 = 0; h2 < 2; h2++) {
        float inv = 1.f / lrow[h2];
        int row_t = qt * 128 + wid * 16 + (lid >> 2) + 8 * h2;
        size_t base = ((size_t)b * T_ + row_t) * C_ + h * HD;
        #pragma unroll
        for (int jn = 0; jn < 16; jn++) {
            int col = jn * 8 + 2 * (lid & 3);
            *(__half2*)(Yh + base + col) =
                __floats2half2_rn(oacc[jn][h2 * 2] * inv, oacc[jn][h2 * 2 + 1] * inv);
        }
    }
}

// ---------------------------------------------------------------------------
extern "C" void kernel_launch(void* const* d_in, const int* in_sizes, int n_in,
                              void* d_out, int out_size)
{
    const float* x    = (const float*)d_in[0];
    const float* fcos = (const float*)d_in[1];
    const float* fsin = (const float*)d_in[2];
    const float* wq   = (const float*)d_in[3];
    const float* wk   = (const float*)d_in[4];
    const float* wv   = (const float*)d_in[5];
    const float* wo   = (const float*)d_in[6];
    float* out = (float*)d_out;

    __half *xs, *wh, *qh, *kh, *vh, *yh, *woh;
    cudaGetSymbolAddress((void**)&xs,  g_xs);
    cudaGetSymbolAddress((void**)&wh,  g_wh);
    cudaGetSymbolAddress((void**)&qh,  g_qh);
    cudaGetSymbolAddress((void**)&kh,  g_kh);
    cudaGetSymbolAddress((void**)&vh,  g_vh);
    cudaGetSymbolAddress((void**)&yh,  g_yh);
    cudaGetSymbolAddress((void**)&woh, g_woh);

    const int M  = B_ * T_;    // 4096
    const int NW_ = NKV * HD;  // 512
    const int NQKV = C_ + 2 * NW_;  // 3072

    // Single merged convert launch: x, wq, wo, wk, wv -> f16
    cvt_all<<<(N4_TOT + 255) / 256, 256>>>(
        (const float4*)x, (const float4*)wq, (const float4*)wk,
        (const float4*)wv, (const float4*)wo,
        (__half2*)xs, (__half2*)wh, (__half2*)woh);

    cudaFuncSetAttribute(gemm_f16, cudaFuncAttributeMaxDynamicSharedMemorySize, GSM_TOTAL);
    cudaFuncSetAttribute(attn_mma, cudaFuncAttributeMaxDynamicSharedMemorySize, ASM_TOTAL);

    // Merged QKV projection with fused RoPE epilogue
    gemm_f16<<<dim3(NQKV / 128, M / 128), 256, GSM_TOTAL>>>(
        xs, wh, nullptr, qh, kh, vh, fcos, fsin, C_, NQKV, 1);

    // Flash attention -> f16 y (BN=128 kv tiles)
    attn_mma<<<dim3(T_ / 128, B_ * NH), 256, ASM_TOTAL>>>(qh, kh, vh, yh);

    // Output projection (fp32 out)
    gemm_f16<<<dim3(C_ / 128, M / 128), 256, GSM_TOTAL>>>(
        yh, woh, out, nullptr, nullptr, nullptr, nullptr, nullptr, C_, C_, 0);
}

// round 16
// speedup vs baseline: 3.0701x; 1.0052x over previous
#include <cuda_runtime.h>
#include <cuda_bf16.h>
#include <cuda_fp16.h>
#include <math.h>
#include <stdint.h>

#define B_   2
#define T_   2048
#define C_   2048
#define NH   16
#define NKV  4
#define HD   128
#define QSCL  0.1275495818259719f            // (1/sqrt(128)) * log2(e)

// ---------------------------------------------------------------------------
// Scratch (device globals; no allocation allowed)
// ---------------------------------------------------------------------------
__device__ __half g_xs [(size_t)B_ * T_ * C_];                // f16 x
__device__ __half g_wh [(size_t)3 * C_ / 2 * C_];             // [wq;wk;wv] f16
__device__ __half g_qh [(size_t)B_ * NH  * T_ * HD];          // Q f16 (QSCL, roped)
__device__ __half g_kh [(size_t)B_ * NKV * T_ * HD];          // K f16 (roped)
__device__ __half g_vh [(size_t)B_ * NKV * T_ * HD];          // V f16
__device__ __half g_yh [(size_t)B_ * T_ * C_];                // attn out f16
__device__ __half g_woh[(size_t)C_ * C_];                     // wo f16

// ---------------------------------------------------------------------------
// PTX helpers — arch-agnostic (sm_80+)
// ---------------------------------------------------------------------------
__device__ __forceinline__ uint32_t smem_u32(const void* p) {
    uint32_t a;
    asm("{ .reg .u64 t; cvta.to.shared.u64 t, %1; cvt.u32.u64 %0, t; }"
        : "=r"(a) : "l"(p));
    return a;
}
__device__ __forceinline__ void cp_async16(uint32_t saddr, const void* gaddr) {
    asm volatile("cp.async.cg.shared.global [%0], [%1], 16;"
                 :: "r"(saddr), "l"(gaddr));
}
__device__ __forceinline__ void cp_commit() { asm volatile("cp.async.commit_group;"); }
template <int N> __device__ __forceinline__ void cp_wait() {
    asm volatile("cp.async.wait_group %0;" :: "n"(N));
}
__device__ __forceinline__ void ldsm4(uint32_t* r, uint32_t addr) {
    asm volatile("ldmatrix.sync.aligned.m8n8.x4.shared.b16 {%0,%1,%2,%3}, [%4];"
                 : "=r"(r[0]), "=r"(r[1]), "=r"(r[2]), "=r"(r[3]) : "r"(addr));
}
__device__ __forceinline__ void ldsm4t(uint32_t* r, uint32_t addr) {
    asm volatile("ldmatrix.sync.aligned.m8n8.x4.trans.shared.b16 {%0,%1,%2,%3}, [%4];"
                 : "=r"(r[0]), "=r"(r[1]), "=r"(r[2]), "=r"(r[3]) : "r"(addr));
}
__device__ __forceinline__ void mma_f16(float* c, const uint32_t* a,
                                        uint32_t b0, uint32_t b1) {
    asm volatile(
        "mma.sync.aligned.m16n8k16.row.col.f32.f16.f16.f32 "
        "{%0,%1,%2,%3}, {%4,%5,%6,%7}, {%8,%9}, {%0,%1,%2,%3};"
        : "+f"(c[0]), "+f"(c[1]), "+f"(c[2]), "+f"(c[3])
        : "r"(a[0]), "r"(a[1]), "r"(a[2]), "r"(a[3]), "r"(b0), "r"(b1));
}
__device__ __forceinline__ float ex2f(float x) {
    float y; asm("ex2.approx.f32 %0, %1;" : "=f"(y) : "f"(x)); return y;
}
__device__ __forceinline__ uint32_t ex2p(float s0, float s1) {
    uint32_t t;
    asm("{\n\tcvt.rn.f16x2.f32 %0, %2, %1;\n\t"
        "ex2.approx.f16x2 %0, %0;\n\t}"
        : "=r"(t) : "f"(s0), "f"(s1));
    return t;
}

// ---------------------------------------------------------------------------
// Merged fp32 -> f16 convert (x, wq, wo, wk, wv in one launch)
// ---------------------------------------------------------------------------
#define N4_X   (B_ * T_ * C_ / 4)
#define N4_WQ  (C_ * C_ / 4)
#define N4_WKV (NKV * HD * C_ / 4)
#define N4_TOT (N4_X + 2 * N4_WQ + 2 * N4_WKV)

__global__ void cvt_all(const float4* __restrict__ x, const float4* __restrict__ wq,
                        const float4* __restrict__ wk, const float4* __restrict__ wv,
                        const float4* __restrict__ wo,
                        __half2* __restrict__ xs, __half2* __restrict__ wh,
                        __half2* __restrict__ woh)
{
    int i = blockIdx.x * blockDim.x + threadIdx.x;
    if (i >= N4_TOT) return;
    const float4* src; __half2* dst; int off;
    if (i < N4_X)                    { src = x;  dst = xs;  off = i; }
    else if (i < N4_X + N4_WQ)       { src = wq; dst = wh;  off = i - N4_X; }
    else if (i < N4_X + 2 * N4_WQ)   { src = wo; dst = woh; off = i - N4_X - N4_WQ; }
    else if (i < N4_X + 2 * N4_WQ + N4_WKV) {
        src = wk; dst = wh + (size_t)C_ * C_ / 2;
        off = i - N4_X - 2 * N4_WQ;
    } else {
        src = wv; dst = wh + (size_t)(C_ + NKV * HD) * C_ / 2;
        off = i - N4_X - 2 * N4_WQ - N4_WKV;
    }
    float4 v = src[off];
    dst[2 * off + 0] = __floats2half2_rn(v.x, v.y);
    dst[2 * off + 1] = __floats2half2_rn(v.z, v.w);
}

// ---------------------------------------------------------------------------
// f16 1-term GEMM (NT) — R14 core, frozen (tensor≈50% = mma.sync ceiling).
// 128x128 CTA tile, BK=64/stage, 2-stage cp.async, 256 threads.
// ---------------------------------------------------------------------------
#define GROW   144
#define GMAT   (128 * GROW)          // 18432
#define GSTG   (2 * GMAT)            // 36864
#define GSM_TOTAL (2 * GSTG)         // 73728

__global__ __launch_bounds__(256) void gemm_f16(
    const __half* __restrict__ A, const __half* __restrict__ W,
    float* __restrict__ Cout,
    __half* __restrict__ Qh, __half* __restrict__ Kh, __half* __restrict__ Vh,
    const float* __restrict__ fcos, const float* __restrict__ fsin,
    int K, int N, int mode)
{
    extern __shared__ char smem[];
    const int tid = threadIdx.x;
    const int lid = tid & 31, wid = tid >> 5;
    const int wm = wid & 1, wn = wid >> 1;
    const int bm = blockIdx.y, bn = blockIdx.x;

    const __half* Asrc = A + (size_t)bm * 128 * K;
    const __half* Wsrc = W + (size_t)bn * 128 * K;

    float acc[4][4][4];
    #pragma unroll
    for (int mi = 0; mi < 4; mi++)
        #pragma unroll
        for (int ni = 0; ni < 4; ni++)
            #pragma unroll
            for (int e = 0; e < 4; e++) acc[mi][ni][e] = 0.f;

    const int nst = K >> 6;

    auto load_stage = [&](int s) {
        char* base = smem + (s & 1) * GSTG;
        const int k0 = s << 6;
        #pragma unroll
        for (int m = 0; m < 2; m++) {
            const __half* src = (m ? Wsrc : Asrc) + k0;
            char* dst = base + m * GMAT;
            #pragma unroll
            for (int j = 0; j < 4; j++) {
                int idx = j * 256 + tid;
                int row = idx >> 3;
                int c   = idx & 7;
                cp_async16(smem_u32(dst + row * GROW + c * 16),
                           src + (size_t)row * K + c * 8);
            }
        }
        cp_commit();
    };

    load_stage(0);

    for (int s = 0; s < nst; s++) {
        if (s + 1 < nst) { load_stage(s + 1); cp_wait<1>(); }
        else             { cp_wait<0>(); }
        __syncthreads();

        const uint32_t sb = smem_u32(smem + (s & 1) * GSTG);
        #pragma unroll
        for (int kk = 0; kk < 4; kk++) {
            uint32_t ah[4][4], bh[2][4];
            const int arow  = wm * 64 + (lid & 15);
            const int akcol = kk * 16 + ((lid & 16) ? 8 : 0);
            #pragma unroll
            for (int mi = 0; mi < 4; mi++)
                ldsm4(ah[mi], sb + (arow + mi * 16) * GROW + akcol * 2);
            const int brow  = wn * 32 + (lid & 7) + ((lid & 16) ? 8 : 0);
            const int bkcol = kk * 16 + ((lid & 8) ? 8 : 0);
            #pragma unroll
            for (int p = 0; p < 2; p++)
                ldsm4(bh[p], sb + GMAT + (brow + p * 16) * GROW + bkcol * 2);
            #pragma unroll
            for (int mi = 0; mi < 4; mi++)
                #pragma unroll
                for (int ni = 0; ni < 4; ni++) {
                    const int p = ni >> 1, q = (ni & 1) * 2;
                    mma_f16(acc[mi][ni], ah[mi], bh[p][q], bh[p][q + 1]);
                }
        }
        __syncthreads();
    }

    const int r0c = lid >> 2, cc = (lid & 3) * 2;
    #pragma unroll
    for (int mi = 0; mi < 4; mi++) {
        #pragma unroll
        for (int ni = 0; ni < 4; ni++) {
            int row = bm * 128 + wm * 64 + mi * 16 + r0c;
            int col = bn * 128 + wn * 32 + ni * 8 + cc;
            #pragma unroll
            for (int half = 0; half < 2; half++) {
                int rr = row + half * 8;
                float v0 = acc[mi][ni][half * 2], v1 = acc[mi][ni][half * 2 + 1];
                if (mode == 0) {
                    *(float2*)(Cout + (size_t)rr * N + col) = make_float2(v0, v1);
                } else {
                    const int b = rr >> 11, t = rr & (T_ - 1);
                    const int ht = col >> 7, d = col & (HD - 1);
                    if (ht < NH) {
                        float c = fcos[t * 64 + (d >> 1)];
                        float sn = fsin[t * 64 + (d >> 1)];
                        float r0 = (v0 * c - v1 * sn) * QSCL;
                        float r1 = (v0 * sn + v1 * c) * QSCL;
                        *(__half2*)(Qh + ((((size_t)b * NH + ht) * T_ + t) * HD + d)) =
                            __floats2half2_rn(r0, r1);
                    } else if (ht < NH + NKV) {
                        int h = ht - NH;
                        float c = fcos[t * 64 + (d >> 1)];
                        float sn = fsin[t * 64 + (d >> 1)];
                        float r0 = v0 * c - v1 * sn;
                        float r1 = v0 * sn + v1 * c;
                        size_t off = (((size_t)b * NKV + h) * T_ + t) * HD + d;
                        *(__half2*)(Kh + off) = __floats2half2_rn(r0, r1);
                    } else {
                        int h = ht - NH - NKV;
                        size_t off = (((size_t)b * NKV + h) * T_ + t) * HD + d;
                        *(__half2*)(Vh + off) = __floats2half2_rn(v0, v1);
                    }
                }
            }
        }
    }
}

// ---------------------------------------------------------------------------
// Tensor-core causal flash attention — BN=128 KV tiles, Q fragments hoisted
// into registers (loaded once), 3-stage KV ring with depth-2 prefetch.
// Q stages through ring slot 2 before the loop reaches it.
// ---------------------------------------------------------------------------
#define AROWB  272
#define AKVMAT 34816                 // 128 * 272
#define AKVST  (2 * AKVMAT)          // 69632
#define ASM_TOTAL (3 * AKVST)        // 208896
#define ONES2  0x3C003C00u

__global__ __launch_bounds__(256, 1) void attn_mma(
    const __half* __restrict__ Qh,
    const __half* __restrict__ Kh, const __half* __restrict__ Vh,
    __half* __restrict__ Yh)
{
    extern __shared__ char smem[];
    const int tid = threadIdx.x;
    const int lid = tid & 31, wid = tid >> 5;
    const int qt = (T_ / 128 - 1) - blockIdx.x;   // heavy tiles first
    const int bh = blockIdx.y;
    const int b  = bh >> 4, h = bh & 15;
    const int kvh = h >> 2;

    const size_t qg = ((size_t)(b * NH + h) * T_ + qt * 128) * HD;
    const size_t kg = (size_t)(b * NKV + kvh) * T_ * HD;

    const uint32_t sKV0 = smem_u32(smem);
    const uint32_t sQ   = sKV0 + 2 * AKVST;      // ring slot 2 (temp for Q)

    // Q -> smem (own cp.async group)
    {
        #pragma unroll
        for (int i = 0; i < 8; i++) {
            int idx = i * 256 + tid;
            int row = idx >> 4, c = idx & 15;
            cp_async16(sQ + row * AROWB + c * 16, Qh + qg + (size_t)row * HD + c * 8);
        }
        cp_commit();
    }
    const __half* kvsrc[2] = {Kh, Vh};
    auto load_kv = [&](int kt, int st) {
        uint32_t sb = sKV0 + st * AKVST;
        const size_t base = kg + (size_t)kt * 128 * HD;
        #pragma unroll
        for (int i = 0; i < 16; i++) {
            int idx = i * 256 + tid;
            int mat = idx >> 11;
            int rem = idx & 2047;
            int row = rem >> 4, c = rem & 15;
            cp_async16(sb + mat * AKVMAT + row * AROWB + c * 16,
                       kvsrc[mat] + base + (size_t)row * HD + c * 8);
        }
        cp_commit();
    };

    const int nkt = qt + 1;          // 128-row kv tiles, causal
    load_kv(0, 0);
    if (nkt > 1) load_kv(1, 1); else cp_commit();

    // Extract Q fragments once (32 regs), then release the Q smem region.
    uint32_t qf[8][4];
    cp_wait<2>();                    // Q group complete (2 newest = kv groups)
    __syncthreads();
    {
        const int arow = wid * 16 + (lid & 15);
        #pragma unroll
        for (int kk = 0; kk < 8; kk++) {
            const int akcol = kk * 16 + ((lid & 16) ? 8 : 0);
            ldsm4(qf[kk], sQ + arow * AROWB + akcol * 2);
        }
    }
    __syncthreads();                 // all warps done with Q smem

    float oacc[16][4];
    #pragma unroll
    for (int jn = 0; jn < 16; jn++)
        #pragma unroll
        for (int e = 0; e < 4; e++) oacc[jn][e] = 0.f;
    float mrow[2] = {-1e30f, -1e30f};
    float lrow[2] = {0.f, 0.f};

    for (int kt = 0; kt < nkt; kt++) {
        if (kt + 2 < nkt) load_kv(kt + 2, (kt + 2) % 3);
        else              cp_commit();
        cp_wait<2>();
        __syncthreads();

        const uint32_t sb = sKV0 + (kt % 3) * AKVST;
        const uint32_t sK = sb, sV = sb + AKVMAT;

        // ---- S = Q K^T over 128 kv rows
        float sacc[16][4];
        #pragma unroll
        for (int j = 0; j < 16; j++)
            #pragma unroll
            for (int e = 0; e < 4; e++) sacc[j][e] = 0.f;

        #pragma unroll
        for (int kk = 0; kk < 8; kk++) {
            #pragma unroll
            for (int np = 0; np < 8; np++) {
                uint32_t bh4[4];
                const int brow  = np * 16 + (lid & 7) + ((lid & 16) ? 8 : 0);
                const int bkcol = kk * 16 + ((lid & 8) ? 8 : 0);
                ldsm4(bh4, sK + brow * AROWB + bkcol * 2);
                #pragma unroll
                for (int jj = 0; jj < 2; jj++) {
                    const int j = 2 * np + jj, q = jj * 2;
                    mma_f16(sacc[j], qf[kk], bh4[q], bh4[q + 1]);
                }
            }
        }

        // ---- causal mask (diagonal tile only)
        if (kt == qt) {
            const int kv0 = kt * 128;
            const int rbase = qt * 128 + wid * 16 + (lid >> 2);
            #pragma unroll
            for (int j = 0; j < 16; j++)
                #pragma unroll
                for (int e = 0; e < 4; e++) {
                    int col = kv0 + j * 8 + 2 * (lid & 3) + (e & 1);
                    int row = rbase + (e >> 1) * 8;
                    if (col > row) sacc[j][e] = -1e30f;
                }
        }

        // ---- online softmax: row max, f16x2 exp -> P fragments, l via mma
        float mnew[2];
        #pragma unroll
        for (int h2 = 0; h2 < 2; h2++) {
            float tm = -1e30f;
            #pragma unroll
            for (int j = 0; j < 16; j++)
                tm = fmaxf(tm, fmaxf(sacc[j][h2 * 2], sacc[j][h2 * 2 + 1]));
            tm = fmaxf(tm, __shfl_xor_sync(0xffffffffu, tm, 1));
            tm = fmaxf(tm, __shfl_xor_sync(0xffffffffu, tm, 2));
            mnew[h2] = fmaxf(mrow[h2], tm);
        }

        uint32_t pfrag[16][2];
        #pragma unroll
        for (int j = 0; j < 16; j++) {
            pfrag[j][0] = ex2p(sacc[j][0] - mnew[0], sacc[j][1] - mnew[0]);
            pfrag[j][1] = ex2p(sacc[j][2] - mnew[1], sacc[j][3] - mnew[1]);
        }

        float lacc[4] = {0.f, 0.f, 0.f, 0.f};
        #pragma unroll
        for (int ks = 0; ks < 8; ks++) {
            uint32_t pf[4];
            pf[0] = pfrag[2 * ks][0];
            pf[1] = pfrag[2 * ks][1];
            pf[2] = pfrag[2 * ks + 1][0];
            pf[3] = pfrag[2 * ks + 1][1];
            mma_f16(lacc, pf, ONES2, ONES2);
        }

        #pragma unroll
        for (int h2 = 0; h2 < 2; h2++) {
            float corr = ex2f(mrow[h2] - mnew[h2]);
            lrow[h2] = lrow[h2] * corr + (h2 ? lacc[2] : lacc[0]);
            mrow[h2] = mnew[h2];
            #pragma unroll
            for (int jn = 0; jn < 16; jn++) {
                oacc[jn][h2 * 2]     *= corr;
                oacc[jn][h2 * 2 + 1] *= corr;
            }
        }

        // ---- O += P V
        #pragma unroll
        for (int ks = 0; ks < 8; ks++) {
            uint32_t pf[4];
            pf[0] = pfrag[2 * ks][0];
            pf[1] = pfrag[2 * ks][1];
            pf[2] = pfrag[2 * ks + 1][0];
            pf[3] = pfrag[2 * ks + 1][1];
            #pragma unroll
            for (int np = 0; np < 8; np++) {
                uint32_t vh4[4];
                const int vrow = ks * 16 + (lid & 7) + 8 * ((lid >> 3) & 1);
                const int vcol = np * 16 + 8 * (lid >> 4);
                ldsm4t(vh4, sV + vrow * AROWB + vcol * 2);
                #pragma unroll
                for (int jj = 0; jj < 2; jj++) {
                    const int jn = 2 * np + jj, q = jj * 2;
                    mma_f16(oacc[jn], pf, vh4[q], vh4[q + 1]);
                }
            }
        }
        __syncthreads();
    }

    // ---- epilogue: normalize, write f16 y[b, t, h*128 + d]
    #pragma unroll
    for (int h2 = 0; h2 < 2; h2++) {
        float inv = 1.f / lrow[h2];
        int row_t = qt * 128 + wid * 16 + (lid >> 2) + 8 * h2;
        size_t base = ((size_t)b * T_ + row_t) * C_ + h * HD;
        #pragma unroll
        for (int jn = 0; jn < 16; jn++) {
            int col = jn * 8 + 2 * (lid & 3);
            *(__half2*)(Yh + base + col) =
                __floats2half2_rn(oacc[jn][h2 * 2] * inv, oacc[jn][h2 * 2 + 1] * inv);
        }
    }
}

// ---------------------------------------------------------------------------
extern "C" void kernel_launch(void* const* d_in, const int* in_sizes, int n_in,
                              void* d_out, int out_size)
{
    const float* x    = (const float*)d_in[0];
    const float* fcos = (const float*)d_in[1];
    const float* fsin = (const float*)d_in[2];
    const float* wq   = (const float*)d_in[3];
    const float* wk   = (const float*)d_in[4];
    const float* wv   = (const float*)d_in[5];
    const float* wo   = (const float*)d_in[6];
    float* out = (float*)d_out;

    __half *xs, *wh, *qh, *kh, *vh, *yh, *woh;
    cudaGetSymbolAddress((void**)&xs,  g_xs);
    cudaGetSymbolAddress((void**)&wh,  g_wh);
    cudaGetSymbolAddress((void**)&qh,  g_qh);
    cudaGetSymbolAddress((void**)&kh,  g_kh);
    cudaGetSymbolAddress((void**)&vh,  g_vh);
    cudaGetSymbolAddress((void**)&yh,  g_yh);
    cudaGetSymbolAddress((void**)&woh, g_woh);

    const int M  = B_ * T_;    // 4096
    const int NW_ = NKV * HD;  // 512
    const int NQKV = C_ + 2 * NW_;  // 3072

    // Single merged convert launch: x, wq, wo, wk, wv -> f16
    cvt_all<<<(N4_TOT + 255) / 256, 256>>>(
        (const float4*)x, (const float4*)wq, (const float4*)wk,
        (const float4*)wv, (const float4*)wo,
        (__half2*)xs, (__half2*)wh, (__half2*)woh);

    cudaFuncSetAttribute(gemm_f16, cudaFuncAttributeMaxDynamicSharedMemorySize, GSM_TOTAL);
    cudaFuncSetAttribute(attn_mma, cudaFuncAttributeMaxDynamicSharedMemorySize, ASM_TOTAL);

    // Merged QKV projection with fused RoPE epilogue
    gemm_f16<<<dim3(NQKV / 128, M / 128), 256, GSM_TOTAL>>>(
        xs, wh, nullptr, qh, kh, vh, fcos, fsin, C_, NQKV, 1);

    // Flash attention -> f16 y (BN=128 kv tiles, Q in registers, 3-stage KV)
    attn_mma<<<dim3(T_ / 128, B_ * NH), 256, ASM_TOTAL>>>(qh, kh, vh, yh);

    // Output projection (fp32 out)
    gemm_f16<<<dim3(C_ / 128, M / 128), 256, GSM_TOTAL>>>(
        yh, woh, out, nullptr, nullptr, nullptr, nullptr, nullptr, C_, C_, 0);
}

// round 17
// speedup vs baseline: 3.1136x; 1.0142x over previous
#include <cuda_runtime.h>
#include <cuda_bf16.h>
#include <cuda_fp16.h>
#include <math.h>
#include <stdint.h>

#define B_   2
#define T_   2048
#define C_   2048
#define NH   16
#define NKV  4
#define HD   128
#define QSCL  0.1275495818259719f            // (1/sqrt(128)) * log2(e)

// ---------------------------------------------------------------------------
// Scratch (device globals; no allocation allowed)
// ---------------------------------------------------------------------------
__device__ __half g_xs [(size_t)B_ * T_ * C_];                // f16 x
__device__ __half g_wh [(size_t)3 * C_ / 2 * C_];             // [wq;wk;wv] f16
__device__ __half g_qh [(size_t)B_ * NH  * T_ * HD];          // Q f16 (QSCL, roped)
__device__ __half g_kh [(size_t)B_ * NKV * T_ * HD];          // K f16 (roped)
__device__ __half g_vh [(size_t)B_ * NKV * T_ * HD];          // V f16
__device__ __half g_yh [(size_t)B_ * T_ * C_];                // attn out f16
__device__ __half g_woh[(size_t)C_ * C_];                     // wo f16

// ---------------------------------------------------------------------------
// PTX helpers — arch-agnostic (sm_80+)
// ---------------------------------------------------------------------------
__device__ __forceinline__ uint32_t smem_u32(const void* p) {
    uint32_t a;
    asm("{ .reg .u64 t; cvta.to.shared.u64 t, %1; cvt.u32.u64 %0, t; }"
        : "=r"(a) : "l"(p));
    return a;
}
__device__ __forceinline__ void cp_async16(uint32_t saddr, const void* gaddr) {
    asm volatile("cp.async.cg.shared.global [%0], [%1], 16;"
                 :: "r"(saddr), "l"(gaddr));
}
__device__ __forceinline__ void cp_commit() { asm volatile("cp.async.commit_group;"); }
template <int N> __device__ __forceinline__ void cp_wait() {
    asm volatile("cp.async.wait_group %0;" :: "n"(N));
}
__device__ __forceinline__ void ldsm4(uint32_t* r, uint32_t addr) {
    asm volatile("ldmatrix.sync.aligned.m8n8.x4.shared.b16 {%0,%1,%2,%3}, [%4];"
                 : "=r"(r[0]), "=r"(r[1]), "=r"(r[2]), "=r"(r[3]) : "r"(addr));
}
__device__ __forceinline__ void ldsm4t(uint32_t* r, uint32_t addr) {
    asm volatile("ldmatrix.sync.aligned.m8n8.x4.trans.shared.b16 {%0,%1,%2,%3}, [%4];"
                 : "=r"(r[0]), "=r"(r[1]), "=r"(r[2]), "=r"(r[3]) : "r"(addr));
}
__device__ __forceinline__ void mma_f16(float* c, const uint32_t* a,
                                        uint32_t b0, uint32_t b1) {
    asm volatile(
        "mma.sync.aligned.m16n8k16.row.col.f32.f16.f16.f32 "
        "{%0,%1,%2,%3}, {%4,%5,%6,%7}, {%8,%9}, {%0,%1,%2,%3};"
        : "+f"(c[0]), "+f"(c[1]), "+f"(c[2]), "+f"(c[3])
        : "r"(a[0]), "r"(a[1]), "r"(a[2]), "r"(a[3]), "r"(b0), "r"(b1));
}
__device__ __forceinline__ float ex2f(float x) {
    float y; asm("ex2.approx.f32 %0, %1;" : "=f"(y) : "f"(x)); return y;
}
__device__ __forceinline__ uint32_t ex2p(float s0, float s1) {
    uint32_t t;
    asm("{\n\tcvt.rn.f16x2.f32 %0, %2, %1;\n\t"
        "ex2.approx.f16x2 %0, %0;\n\t}"
        : "=r"(t) : "f"(s0), "f"(s1));
    return t;
}

// ---------------------------------------------------------------------------
// Merged fp32 -> f16 convert, 4 float4 per thread (MLP=4 hides DRAM latency)
// ---------------------------------------------------------------------------
#define N4_X   (B_ * T_ * C_ / 4)
#define N4_WQ  (C_ * C_ / 4)
#define N4_WKV (NKV * HD * C_ / 4)
#define N4_TOT (N4_X + 2 * N4_WQ + 2 * N4_WKV)

__global__ void cvt_all(const float4* __restrict__ x, const float4* __restrict__ wq,
                        const float4* __restrict__ wk, const float4* __restrict__ wv,
                        const float4* __restrict__ wo,
                        __half2* __restrict__ xs, __half2* __restrict__ wh,
                        __half2* __restrict__ woh)
{
    const int base = blockIdx.x * 1024 + threadIdx.x;

    const float4* src[4]; __half2* dst[4]; int off[4];
    float4 v[4]; bool ok[4];
    #pragma unroll
    for (int j = 0; j < 4; j++) {
        int i = base + j * 256;
        ok[j] = (i < N4_TOT);
        if (!ok[j]) continue;
        if (i < N4_X)                  { src[j] = x;  dst[j] = xs;  off[j] = i; }
        else if (i < N4_X + N4_WQ)     { src[j] = wq; dst[j] = wh;  off[j] = i - N4_X; }
        else if (i < N4_X + 2 * N4_WQ) { src[j] = wo; dst[j] = woh; off[j] = i - N4_X - N4_WQ; }
        else if (i < N4_X + 2 * N4_WQ + N4_WKV) {
            src[j] = wk; dst[j] = wh + (size_t)C_ * C_ / 2;
            off[j] = i - N4_X - 2 * N4_WQ;
        } else {
            src[j] = wv; dst[j] = wh + (size_t)(C_ + NKV * HD) * C_ / 2;
            off[j] = i - N4_X - 2 * N4_WQ - N4_WKV;
        }
        v[j] = src[j][off[j]];           // 4 independent loads in flight
    }
    #pragma unroll
    for (int j = 0; j < 4; j++) {
        if (!ok[j]) continue;
        dst[j][2 * off[j] + 0] = __floats2half2_rn(v[j].x, v[j].y);
        dst[j][2 * off[j] + 1] = __floats2half2_rn(v[j].z, v[j].w);
    }
}

// ---------------------------------------------------------------------------
// f16 1-term GEMM (NT) — frozen (tensor≈50% = f32-acc mma.sync ceiling).
// 128x128 CTA tile, BK=64/stage, 2-stage cp.async, 256 threads.
// ---------------------------------------------------------------------------
#define GROW   144
#define GMAT   (128 * GROW)          // 18432
#define GSTG   (2 * GMAT)            // 36864
#define GSM_TOTAL (2 * GSTG)         // 73728

__global__ __launch_bounds__(256) void gemm_f16(
    const __half* __restrict__ A, const __half* __restrict__ W,
    float* __restrict__ Cout,
    __half* __restrict__ Qh, __half* __restrict__ Kh, __half* __restrict__ Vh,
    const float* __restrict__ fcos, const float* __restrict__ fsin,
    int K, int N, int mode)
{
    extern __shared__ char smem[];
    const int tid = threadIdx.x;
    const int lid = tid & 31, wid = tid >> 5;
    const int wm = wid & 1, wn = wid >> 1;
    const int bm = blockIdx.y, bn = blockIdx.x;

    const __half* Asrc = A + (size_t)bm * 128 * K;
    const __half* Wsrc = W + (size_t)bn * 128 * K;

    float acc[4][4][4];
    #pragma unroll
    for (int mi = 0; mi < 4; mi++)
        #pragma unroll
        for (int ni = 0; ni < 4; ni++)
            #pragma unroll
            for (int e = 0; e < 4; e++) acc[mi][ni][e] = 0.f;

    const int nst = K >> 6;

    auto load_stage = [&](int s) {
        char* base = smem + (s & 1) * GSTG;
        const int k0 = s << 6;
        #pragma unroll
        for (int m = 0; m < 2; m++) {
            const __half* src = (m ? Wsrc : Asrc) + k0;
            char* dst = base + m * GMAT;
            #pragma unroll
            for (int j = 0; j < 4; j++) {
                int idx = j * 256 + tid;
                int row = idx >> 3;
                int c   = idx & 7;
                cp_async16(smem_u32(dst + row * GROW + c * 16),
                           src + (size_t)row * K + c * 8);
            }
        }
        cp_commit();
    };

    load_stage(0);

    for (int s = 0; s < nst; s++) {
        if (s + 1 < nst) { load_stage(s + 1); cp_wait<1>(); }
        else             { cp_wait<0>(); }
        __syncthreads();

        const uint32_t sb = smem_u32(smem + (s & 1) * GSTG);
        #pragma unroll
        for (int kk = 0; kk < 4; kk++) {
            uint32_t ah[4][4], bh[2][4];
            const int arow  = wm * 64 + (lid & 15);
            const int akcol = kk * 16 + ((lid & 16) ? 8 : 0);
            #pragma unroll
            for (int mi = 0; mi < 4; mi++)
                ldsm4(ah[mi], sb + (arow + mi * 16) * GROW + akcol * 2);
            const int brow  = wn * 32 + (lid & 7) + ((lid & 16) ? 8 : 0);
            const int bkcol = kk * 16 + ((lid & 8) ? 8 : 0);
            #pragma unroll
            for (int p = 0; p < 2; p++)
                ldsm4(bh[p], sb + GMAT + (brow + p * 16) * GROW + bkcol * 2);
            #pragma unroll
            for (int mi = 0; mi < 4; mi++)
                #pragma unroll
                for (int ni = 0; ni < 4; ni++) {
                    const int p = ni >> 1, q = (ni & 1) * 2;
                    mma_f16(acc[mi][ni], ah[mi], bh[p][q], bh[p][q + 1]);
                }
        }
        __syncthreads();
    }

    const int r0c = lid >> 2, cc = (lid & 3) * 2;
    #pragma unroll
    for (int mi = 0; mi < 4; mi++) {
        #pragma unroll
        for (int ni = 0; ni < 4; ni++) {
            int row = bm * 128 + wm * 64 + mi * 16 + r0c;
            int col = bn * 128 + wn * 32 + ni * 8 + cc;
            #pragma unroll
            for (int half = 0; half < 2; half++) {
                int rr = row + half * 8;
                float v0 = acc[mi][ni][half * 2], v1 = acc[mi][ni][half * 2 + 1];
                if (mode == 0) {
                    *(float2*)(Cout + (size_t)rr * N + col) = make_float2(v0, v1);
                } else {
                    const int b = rr >> 11, t = rr & (T_ - 1);
                    const int ht = col >> 7, d = col & (HD - 1);
                    if (ht < NH) {
                        float c = fcos[t * 64 + (d >> 1)];
                        float sn = fsin[t * 64 + (d >> 1)];
                        float r0 = (v0 * c - v1 * sn) * QSCL;
                        float r1 = (v0 * sn + v1 * c) * QSCL;
                        *(__half2*)(Qh + ((((size_t)b * NH + ht) * T_ + t) * HD + d)) =
                            __floats2half2_rn(r0, r1);
                    } else if (ht < NH + NKV) {
                        int h = ht - NH;
                        float c = fcos[t * 64 + (d >> 1)];
                        float sn = fsin[t * 64 + (d >> 1)];
                        float r0 = v0 * c - v1 * sn;
                        float r1 = v0 * sn + v1 * c;
                        size_t off = (((size_t)b * NKV + h) * T_ + t) * HD + d;
                        *(__half2*)(Kh + off) = __floats2half2_rn(r0, r1);
                    } else {
                        int h = ht - NH - NKV;
                        size_t off = (((size_t)b * NKV + h) * T_ + t) * HD + d;
                        *(__half2*)(Vh + off) = __floats2half2_rn(v0, v1);
                    }
                }
            }
        }
    }
}

// ---------------------------------------------------------------------------
// Tensor-core causal flash attention — BN=128 KV tiles, Q fragments hoisted,
// 3-stage KV ring with depth-2 prefetch. (R16 core, frozen.)
// ---------------------------------------------------------------------------
#define AROWB  272
#define AKVMAT 34816                 // 128 * 272
#define AKVST  (2 * AKVMAT)          // 69632
#define ASM_TOTAL (3 * AKVST)        // 208896
#define ONES2  0x3C003C00u

__global__ __launch_bounds__(256, 1) void attn_mma(
    const __half* __restrict__ Qh,
    const __half* __restrict__ Kh, const __half* __restrict__ Vh,
    __half* __restrict__ Yh)
{
    extern __shared__ char smem[];
    const int tid = threadIdx.x;
    const int lid = tid & 31, wid = tid >> 5;
    const int qt = (T_ / 128 - 1) - blockIdx.x;   // heavy tiles first
    const int bh = blockIdx.y;
    const int b  = bh >> 4, h = bh & 15;
    const int kvh = h >> 2;

    const size_t qg = ((size_t)(b * NH + h) * T_ + qt * 128) * HD;
    const size_t kg = (size_t)(b * NKV + kvh) * T_ * HD;

    const uint32_t sKV0 = smem_u32(smem);
    const uint32_t sQ   = sKV0 + 2 * AKVST;      // ring slot 2 (temp for Q)

    // Q -> smem (own cp.async group)
    {
        #pragma unroll
        for (int i = 0; i < 8; i++) {
            int idx = i * 256 + tid;
            int row = idx >> 4, c = idx & 15;
            cp_async16(sQ + row * AROWB + c * 16, Qh + qg + (size_t)row * HD + c * 8);
        }
        cp_commit();
    }
    const __half* kvsrc[2] = {Kh, Vh};
    auto load_kv = [&](int kt, int st) {
        uint32_t sb = sKV0 + st * AKVST;
        const size_t base = kg + (size_t)kt * 128 * HD;
        #pragma unroll
        for (int i = 0; i < 16; i++) {
            int idx = i * 256 + tid;
            int mat = idx >> 11;
            int rem = idx & 2047;
            int row = rem >> 4, c = rem & 15;
            cp_async16(sb + mat * AKVMAT + row * AROWB + c * 16,
                       kvsrc[mat] + base + (size_t)row * HD + c * 8);
        }
        cp_commit();
    };

    const int nkt = qt + 1;
    load_kv(0, 0);
    if (nkt > 1) load_kv(1, 1); else cp_commit();

    // Extract Q fragments once (32 regs), then release the Q smem region.
    uint32_t qf[8][4];
    cp_wait<2>();
    __syncthreads();
    {
        const int arow = wid * 16 + (lid & 15);
        #pragma unroll
        for (int kk = 0; kk < 8; kk++) {
            const int akcol = kk * 16 + ((lid & 16) ? 8 : 0);
            ldsm4(qf[kk], sQ + arow * AROWB + akcol * 2);
        }
    }
    __syncthreads();

    float oacc[16][4];
    #pragma unroll
    for (int jn = 0; jn < 16; jn++)
        #pragma unroll
        for (int e = 0; e < 4; e++) oacc[jn][e] = 0.f;
    float mrow[2] = {-1e30f, -1e30f};
    float lrow[2] = {0.f, 0.f};

    for (int kt = 0; kt < nkt; kt++) {
        if (kt + 2 < nkt) load_kv(kt + 2, (kt + 2) % 3);
        else              cp_commit();
        cp_wait<2>();
        __syncthreads();

        const uint32_t sb = sKV0 + (kt % 3) * AKVST;
        const uint32_t sK = sb, sV = sb + AKVMAT;

        // ---- S = Q K^T over 128 kv rows
        float sacc[16][4];
        #pragma unroll
        for (int j = 0; j < 16; j++)
            #pragma unroll
            for (int e = 0; e < 4; e++) sacc[j][e] = 0.f;

        #pragma unroll
        for (int kk = 0; kk < 8; kk++) {
            #pragma unroll
            for (int np = 0; np < 8; np++) {
                uint32_t bh4[4];
                const int brow  = np * 16 + (lid & 7) + ((lid & 16) ? 8 : 0);
                const int bkcol = kk * 16 + ((lid & 8) ? 8 : 0);
                ldsm4(bh4, sK + brow * AROWB + bkcol * 2);
                #pragma unroll
                for (int jj = 0; jj < 2; jj++) {
                    const int j = 2 * np + jj, q = jj * 2;
                    mma_f16(sacc[j], qf[kk], bh4[q], bh4[q + 1]);
                }
            }
        }

        // ---- causal mask (diagonal tile only)
        if (kt == qt) {
            const int kv0 = kt * 128;
            const int rbase = qt * 128 + wid * 16 + (lid >> 2);
            #pragma unroll
            for (int j = 0; j < 16; j++)
                #pragma unroll
                for (int e = 0; e < 4; e++) {
                    int col = kv0 + j * 8 + 2 * (lid & 3) + (e & 1);
                    int row = rbase + (e >> 1) * 8;
                    if (col > row) sacc[j][e] = -1e30f;
                }
        }

        // ---- online softmax: row max, f16x2 exp -> P fragments, l via mma
        float mnew[2];
        #pragma unroll
        for (int h2 = 0; h2 < 2; h2++) {
            float tm = -1e30f;
            #pragma unroll
            for (int j = 0; j < 16; j++)
                tm = fmaxf(tm, fmaxf(sacc[j][h2 * 2], sacc[j][h2 * 2 + 1]));
            tm = fmaxf(tm, __shfl_xor_sync(0xffffffffu, tm, 1));
            tm = fmaxf(tm, __shfl_xor_sync(0xffffffffu, tm, 2));
            mnew[h2] = fmaxf(mrow[h2], tm);
        }

        uint32_t pfrag[16][2];
        #pragma unroll
        for (int j = 0; j < 16; j++) {
            pfrag[j][0] = ex2p(sacc[j][0] - mnew[0], sacc[j][1] - mnew[0]);
            pfrag[j][1] = ex2p(sacc[j][2] - mnew[1], sacc[j][3] - mnew[1]);
        }

        float lacc[4] = {0.f, 0.f, 0.f, 0.f};
        #pragma unroll
        for (int ks = 0; ks < 8; ks++) {
            uint32_t pf[4];
            pf[0] = pfrag[2 * ks][0];
            pf[1] = pfrag[2 * ks][1];
            pf[2] = pfrag[2 * ks + 1][0];
            pf[3] = pfrag[2 * ks + 1][1];
            mma_f16(lacc, pf, ONES2, ONES2);
        }

        #pragma unroll
        for (int h2 = 0; h2 < 2; h2++) {
            float corr = ex2f(mrow[h2] - mnew[h2]);
            lrow[h2] = lrow[h2] * corr + (h2 ? lacc[2] : lacc[0]);
            mrow[h2] = mnew[h2];
            #pragma unroll
            for (int jn = 0; jn < 16; jn++) {
                oacc[jn][h2 * 2]     *= corr;
                oacc[jn][h2 * 2 + 1] *= corr;
            }
        }

        // ---- O += P V
        #pragma unroll
        for (int ks = 0; ks < 8; ks++) {
            uint32_t pf[4];
            pf[0] = pfrag[2 * ks][0];
            pf[1] = pfrag[2 * ks][1];
            pf[2] = pfrag[2 * ks + 1][0];
            pf[3] = pfrag[2 * ks + 1][1];
            #pragma unroll
            for (int np = 0; np < 8; np++) {
                uint32_t vh4[4];
                const int vrow = ks * 16 + (lid & 7) + 8 * ((lid >> 3) & 1);
                const int vcol = np * 16 + 8 * (lid >> 4);
                ldsm4t(vh4, sV + vrow * AROWB + vcol * 2);
                #pragma unroll
                for (int jj = 0; jj < 2; jj++) {
                    const int jn = 2 * np + jj, q = jj * 2;
                    mma_f16(oacc[jn], pf, vh4[q], vh4[q + 1]);
                }
            }
        }
        __syncthreads();
    }

    // ---- epilogue: normalize, write f16 y[b, t, h*128 + d]
    #pragma unroll
    for (int h2 = 0; h2 < 2; h2++) {
        float inv = 1.f / lrow[h2];
        int row_t = qt * 128 + wid * 16 + (lid >> 2) + 8 * h2;
        size_t base = ((size_t)b * T_ + row_t) * C_ + h * HD;
        #pragma unroll
        for (int jn = 0; jn < 16; jn++) {
            int col = jn * 8 + 2 * (lid & 3);
            *(__half2*)(Yh + base + col) =
                __floats2half2_rn(oacc[jn][h2 * 2] * inv, oacc[jn][h2 * 2 + 1] * inv);
        }
    }
}

// ---------------------------------------------------------------------------
extern "C" void kernel_launch(void* const* d_in, const int* in_sizes, int n_in,
                              void* d_out, int out_size)
{
    const float* x    = (const float*)d_in[0];
    const float* fcos = (const float*)d_in[1];
    const float* fsin = (const float*)d_in[2];
    const float* wq   = (const float*)d_in[3];
    const float* wk   = (const float*)d_in[4];
    const float* wv   = (const float*)d_in[5];
    const float* wo   = (const float*)d_in[6];
    float* out = (float*)d_out;

    __half *xs, *wh, *qh, *kh, *vh, *yh, *woh;
    cudaGetSymbolAddress((void**)&xs,  g_xs);
    cudaGetSymbolAddress((void**)&wh,  g_wh);
    cudaGetSymbolAddress((void**)&qh,  g_qh);
    cudaGetSymbolAddress((void**)&kh,  g_kh);
    cudaGetSymbolAddress((void**)&vh,  g_vh);
    cudaGetSymbolAddress((void**)&yh,  g_yh);
    cudaGetSymbolAddress((void**)&woh, g_woh);

    const int M  = B_ * T_;    // 4096
    const int NW_ = NKV * HD;  // 512
    const int NQKV = C_ + 2 * NW_;  // 3072

    // Single merged convert launch (4 float4/thread ILP)
    cvt_all<<<(N4_TOT + 1023) / 1024, 256>>>(
        (const float4*)x, (const float4*)wq, (const float4*)wk,
        (const float4*)wv, (const float4*)wo,
        (__half2*)xs, (__half2*)wh, (__half2*)woh);

    cudaFuncSetAttribute(gemm_f16, cudaFuncAttributeMaxDynamicSharedMemorySize, GSM_TOTAL);
    cudaFuncSetAttribute(attn_mma, cudaFuncAttributeMaxDynamicSharedMemorySize, ASM_TOTAL);

    // Merged QKV projection with fused RoPE epilogue
    gemm_f16<<<dim3(NQKV / 128, M / 128), 256, GSM_TOTAL>>>(
        xs, wh, nullptr, qh, kh, vh, fcos, fsin, C_, NQKV, 1);

    // Flash attention -> f16 y
    attn_mma<<<dim3(T_ / 128, B_ * NH), 256, ASM_TOTAL>>>(qh, kh, vh, yh);

    // Output projection (fp32 out)
    gemm_f16<<<dim3(C_ / 128, M / 128), 256, GSM_TOTAL>>>(
        yh, woh, out, nullptr, nullptr, nullptr, nullptr, nullptr, C_, C_, 0);
}